// round 3
// baseline (speedup 1.0000x reference)
#include <cuda_runtime.h>
#include <cstddef>

// Problem constants
#define BB    2
#define NN    2048
#define DIMM  512
#define HH    8
#define DHH   64
#define NQ    513          // distinct effective query rows per head (q[i] = q[i % 513])
#define G     16           // B*H
#define ROWS  4096         // B*N
#define QC    2048         // qkvt columns (4*inner)

// r = exp(-1/e)
#define RDEC 0.69220062755534637f

// ---------------- scratch (static device arrays; no allocation) ----------------
__device__ __align__(256) float g_qkvt[(size_t)ROWS * QC];       // 32 MB  [4096][2048]
__device__ __align__(256) float g_S[(size_t)G * NQ * NN];        // 67 MB  [g][513][2048]
__device__ __align__(256) float g_out1[(size_t)G * NQ * DHH];    // 2.1 MB [g][513][64]
__device__ __align__(256) float g_cat[(size_t)ROWS * 1024];      // 16 MB  [4096][1024]
__device__ __align__(256) float g_sinv[NN];

// =====================================================================
// Generic SGEMM: C[M,N] = A[M,K] @ B[K,N] (+bias).  BM=BN=128, BK=16,
// 256 threads, 8x8 microtile.  Requires M%128==0, N%128==0, K%16==0.
// =====================================================================
__global__ __launch_bounds__(256) void sgemm128(
    const float* __restrict__ A, int lda,
    const float* __restrict__ B, int ldb,
    float* __restrict__ C, int ldc,
    int K, const float* __restrict__ bias)
{
    __shared__ float As[16][132];   // [k][m] (transposed)
    __shared__ float Bs[16][132];   // [k][n]
    int tid  = threadIdx.x;
    int row0 = blockIdx.y * 128, col0 = blockIdx.x * 128;
    int ar = tid >> 1, ak = (tid & 1) * 8;          // A loader: row ar, k-cols ak..ak+7
    int bk = tid >> 4, bn = (tid & 15) * 8;         // B loader: k-row bk, cols bn..bn+7
    int tx = tid & 15, ty = tid >> 4;

    const float* Ap = A + (size_t)(row0 + ar) * lda + ak;
    const float* Bp = B + (size_t)bk * ldb + col0 + bn;

    float acc[8][8];
#pragma unroll
    for (int i = 0; i < 8; i++)
#pragma unroll
        for (int j = 0; j < 8; j++) acc[i][j] = 0.f;

    for (int k0 = 0; k0 < K; k0 += 16) {
        float4 a0 = *(const float4*)(Ap);
        float4 a1 = *(const float4*)(Ap + 4);
        float4 b0 = *(const float4*)(Bp);
        float4 b1 = *(const float4*)(Bp + 4);
        __syncthreads();
        As[ak + 0][ar] = a0.x; As[ak + 1][ar] = a0.y;
        As[ak + 2][ar] = a0.z; As[ak + 3][ar] = a0.w;
        As[ak + 4][ar] = a1.x; As[ak + 5][ar] = a1.y;
        As[ak + 6][ar] = a1.z; As[ak + 7][ar] = a1.w;
        *(float4*)&Bs[bk][bn]     = b0;
        *(float4*)&Bs[bk][bn + 4] = b1;
        __syncthreads();
#pragma unroll
        for (int kk = 0; kk < 16; kk++) {
            float a[8], b[8];
            *(float4*)&a[0] = *(const float4*)&As[kk][ty * 8];
            *(float4*)&a[4] = *(const float4*)&As[kk][ty * 8 + 4];
            *(float4*)&b[0] = *(const float4*)&Bs[kk][tx * 8];
            *(float4*)&b[4] = *(const float4*)&Bs[kk][tx * 8 + 4];
#pragma unroll
            for (int i = 0; i < 8; i++)
#pragma unroll
                for (int j = 0; j < 8; j++) acc[i][j] += a[i] * b[j];
        }
        Ap += 16;
        Bp += (size_t)16 * ldb;
    }

    float bv[8];
#pragma unroll
    for (int j = 0; j < 8; j++) bv[j] = bias ? bias[col0 + tx * 8 + j] : 0.f;
#pragma unroll
    for (int i = 0; i < 8; i++) {
        float* Cp = C + (size_t)(row0 + ty * 8 + i) * ldc + col0 + tx * 8;
        float4 o0 = make_float4(acc[i][0] + bv[0], acc[i][1] + bv[1],
                                acc[i][2] + bv[2], acc[i][3] + bv[3]);
        float4 o1 = make_float4(acc[i][4] + bv[4], acc[i][5] + bv[5],
                                acc[i][6] + bv[6], acc[i][7] + bv[7]);
        *(float4*)Cp       = o0;
        *(float4*)(Cp + 4) = o1;
    }
}

// =====================================================================
// S[g][i][j] = 0.125 * sum_c Q[i][c] * K[j][c]   (i < 513, full K tile)
// grid (32 j-tiles, 9 i-tiles, 16 g), 256 threads, 4x4 microtile.
// =====================================================================
__global__ __launch_bounds__(256) void qk_kernel()
{
    int g = blockIdx.z, b = g >> 3, h = g & 7;
    int i0 = blockIdx.y * 64, j0 = blockIdx.x * 64;
    const float* Q  = g_qkvt + (size_t)b * NN * QC + h * DHH;        // [i][c], ld QC
    const float* Kp = Q + 512;                                       // [j][c], ld QC

    __shared__ float Qt[64][68];    // [c][i]
    __shared__ float Kt[64][68];    // [c][j]
    int tid = threadIdx.x;
    int lr  = tid >> 2;             // 0..63
    int lc0 = (tid & 3) * 16;       // 0,16,32,48
#pragma unroll
    for (int q = 0; q < 4; q++) {
        int c = lc0 + q * 4;
        float4 v = make_float4(0.f, 0.f, 0.f, 0.f);
        if (i0 + lr < NQ) v = *(const float4*)(Q + (size_t)(i0 + lr) * QC + c);
        Qt[c + 0][lr] = v.x; Qt[c + 1][lr] = v.y; Qt[c + 2][lr] = v.z; Qt[c + 3][lr] = v.w;
        float4 w = *(const float4*)(Kp + (size_t)(j0 + lr) * QC + c);
        Kt[c + 0][lr] = w.x; Kt[c + 1][lr] = w.y; Kt[c + 2][lr] = w.z; Kt[c + 3][lr] = w.w;
    }
    __syncthreads();

    int tx = tid & 15, ty = tid >> 4;
    float acc[4][4] = {};
#pragma unroll 16
    for (int c = 0; c < 64; c++) {
        float4 a  = *(const float4*)&Qt[c][ty * 4];
        float4 bb = *(const float4*)&Kt[c][tx * 4];
        float av[4] = {a.x, a.y, a.z, a.w};
        float bv[4] = {bb.x, bb.y, bb.z, bb.w};
#pragma unroll
        for (int i = 0; i < 4; i++)
#pragma unroll
            for (int j = 0; j < 4; j++) acc[i][j] += av[i] * bv[j];
    }
#pragma unroll
    for (int i = 0; i < 4; i++) {
        int r = i0 + ty * 4 + i;
        if (r < NQ) {
            float4 o = make_float4(acc[i][0] * 0.125f, acc[i][1] * 0.125f,
                                   acc[i][2] * 0.125f, acc[i][3] * 0.125f);
            *(float4*)(g_S + ((size_t)g * NQ + r) * NN + j0 + tx * 4) = o;
        }
    }
}

// =====================================================================
// Row softmax over g_S rows (16*513 rows of length 2048), in place.
// =====================================================================
__global__ __launch_bounds__(256) void softmax_kernel()
{
    size_t row = blockIdx.x;
    float* p = g_S + row * NN;
    int tid = threadIdx.x;
    float4 v0 = ((const float4*)p)[tid];
    float4 v1 = ((const float4*)p)[tid + 256];

    float m = fmaxf(fmaxf(fmaxf(v0.x, v0.y), fmaxf(v0.z, v0.w)),
                    fmaxf(fmaxf(v1.x, v1.y), fmaxf(v1.z, v1.w)));
    __shared__ float red[256];
    red[tid] = m; __syncthreads();
    for (int s = 128; s > 0; s >>= 1) {
        if (tid < s) red[tid] = fmaxf(red[tid], red[tid + s]);
        __syncthreads();
    }
    float bm = red[0];
    __syncthreads();

    v0.x = __expf(v0.x - bm); v0.y = __expf(v0.y - bm);
    v0.z = __expf(v0.z - bm); v0.w = __expf(v0.w - bm);
    v1.x = __expf(v1.x - bm); v1.y = __expf(v1.y - bm);
    v1.z = __expf(v1.z - bm); v1.w = __expf(v1.w - bm);
    float s8 = v0.x + v0.y + v0.z + v0.w + v1.x + v1.y + v1.z + v1.w;
    red[tid] = s8; __syncthreads();
    for (int s = 128; s > 0; s >>= 1) {
        if (tid < s) red[tid] += red[tid + s];
        __syncthreads();
    }
    float inv = 1.0f / red[0];

    v0.x *= inv; v0.y *= inv; v0.z *= inv; v0.w *= inv;
    v1.x *= inv; v1.y *= inv; v1.z *= inv; v1.w *= inv;
    ((float4*)p)[tid]       = v0;
    ((float4*)p)[tid + 256] = v1;
}

// =====================================================================
// out1[g][i][:] = P[g][i][:] @ V[g]   (M=513, N=64, K=2048)
// grid (1, 9, 16), 256 threads, 64x64x16 tiles, 4x4 microtile.
// =====================================================================
__global__ __launch_bounds__(256) void pv_kernel()
{
    int g = blockIdx.z, b = g >> 3, h = g & 7;
    int row0 = blockIdx.y * 64;
    const float* A  = g_S + (size_t)g * NQ * NN;                       // [513][2048]
    const float* Bp = g_qkvt + (size_t)b * NN * QC + 1024 + h * DHH;   // [2048][64], ld QC
    float* C = g_out1 + (size_t)g * NQ * DHH;

    __shared__ float As[16][68];    // [k][m]
    __shared__ float Bs[16][68];    // [k][n]
    int tid = threadIdx.x;
    int ar = tid >> 2, ak = (tid & 3) * 4;
    int bk = tid >> 4, bn = (tid & 15) * 4;
    int tx = tid & 15, ty = tid >> 4;

    float acc[4][4] = {};
    for (int k0 = 0; k0 < NN; k0 += 16) {
        float4 av = (row0 + ar < NQ)
            ? *(const float4*)(A + (size_t)(row0 + ar) * NN + k0 + ak)
            : make_float4(0.f, 0.f, 0.f, 0.f);
        float4 bv = *(const float4*)(Bp + (size_t)(k0 + bk) * QC + bn);
        __syncthreads();
        As[ak + 0][ar] = av.x; As[ak + 1][ar] = av.y;
        As[ak + 2][ar] = av.z; As[ak + 3][ar] = av.w;
        *(float4*)&Bs[bk][bn] = bv;
        __syncthreads();
#pragma unroll
        for (int kk = 0; kk < 16; kk++) {
            float4 a  = *(const float4*)&As[kk][ty * 4];
            float4 bb = *(const float4*)&Bs[kk][tx * 4];
            float aa[4] = {a.x, a.y, a.z, a.w};
            float bbv[4] = {bb.x, bb.y, bb.z, bb.w};
#pragma unroll
            for (int i = 0; i < 4; i++)
#pragma unroll
                for (int j = 0; j < 4; j++) acc[i][j] += aa[i] * bbv[j];
        }
    }
#pragma unroll
    for (int i = 0; i < 4; i++) {
        int r = row0 + ty * 4 + i;
        if (r < NQ)
            *(float4*)(C + (size_t)r * DHH + tx * 4) =
                make_float4(acc[i][0], acc[i][1], acc[i][2], acc[i][3]);
    }
}

// =====================================================================
// Expand out1 (513 distinct rows) into cat[:, h*128 + 0..63] via i%513.
// =====================================================================
__global__ void expand_kernel()
{
    int idx = blockIdx.x * 256 + threadIdx.x;        // 0 .. ROWS*512-1
    int row = idx >> 9;                              // b*2048 + i
    int col = idx & 511;                             // h*64 + c
    int b = row >> 11, i = row & 2047;
    int h = col >> 6,  c = col & 63;
    g_cat[(size_t)row * 1024 + h * 128 + c] =
        g_out1[(((size_t)(b * 8 + h)) * NQ + (i % 513)) * DHH + c];
}

// =====================================================================
// sinv[j] = 1 / sum_i r^{|i-j|}  (closed form)
// =====================================================================
__global__ void sinv_kernel()
{
    int j = blockIdx.x * 256 + threadIdx.x;
    if (j < NN) {
        const float r = RDEC;
        float s = (1.0f - powf(r, (float)(j + 1)) + r - powf(r, (float)(NN - j)))
                  / (1.0f - r);
        g_sinv[j] = 1.0f / s;
    }
}

// =====================================================================
// out2 via decay scan: out2[i] = f[i] + g[i] - u[i],  u = t * sinv.
// Chunked with 96-halo warm-up (r^96 ~ 5e-16).  Writes cat half 2.
// grid (16 g, 8 chunks), 64 threads (c).
// =====================================================================
__global__ __launch_bounds__(64) void scan_kernel()
{
    int g = blockIdx.x, chunk = blockIdx.y;
    int b = g >> 3, h = g & 7;
    int c = threadIdx.x;
    const float r = RDEC;
    const float* T = g_qkvt + (size_t)b * NN * QC + 1536 + h * DHH + c;   // t[j][c] at T[j*QC]
    float* Cc = g_cat + (size_t)b * NN * 1024 + h * 128 + 64 + c;         // cat[j] at Cc[j*1024]
    int i0 = chunk * 256;

    int js = i0 - 96; if (js < 0) js = 0;
    float f = 0.f;
    for (int j = js; j < i0 + 256; j++) {
        float u = T[(size_t)j * QC] * g_sinv[j];
        f = f * r + u;
        if (j >= i0) Cc[(size_t)j * 1024] = f - u;
    }
    int je = i0 + 255 + 96; if (je > NN - 1) je = NN - 1;
    float gg = 0.f;
    for (int j = je; j >= i0; j--) {
        float u = T[(size_t)j * QC] * g_sinv[j];
        gg = gg * r + u;
        if (j < i0 + 256) Cc[(size_t)j * 1024] += gg;
    }
}

// =====================================================================
extern "C" void kernel_launch(void* const* d_in, const int* in_sizes, int n_in,
                              void* d_out, int out_size)
{
    const float* x     = (const float*)d_in[0];   // [2,2048,512]
    const float* W_qkv = (const float*)d_in[1];   // [512,2048]
    const float* W_out = (const float*)d_in[2];   // [1024,512]
    const float* b_out = (const float*)d_in[3];   // [512]
    float* out = (float*)d_out;                   // [2,2048,512]

    float *p_qkvt, *p_cat;
    cudaGetSymbolAddress((void**)&p_qkvt, g_qkvt);
    cudaGetSymbolAddress((void**)&p_cat,  g_cat);

    // 1) qkvt = x @ W_qkv : [4096,512] @ [512,2048]
    sgemm128<<<dim3(QC / 128, ROWS / 128), 256>>>(x, DIMM, W_qkv, QC,
                                                  p_qkvt, QC, DIMM, nullptr);

    // sinv (independent of qkvt)
    sinv_kernel<<<8, 256>>>();

    // 2) S = scale * Q_eff K^T  (513 distinct query rows per head)
    qk_kernel<<<dim3(NN / 64, (NQ + 63) / 64, G), 256>>>();

    // 3) softmax rows
    softmax_kernel<<<G * NQ, 256>>>();

    // 4) out1 = P @ V
    pv_kernel<<<dim3(1, (NQ + 63) / 64, G), 256>>>();

    // 5) assemble cat: broadcast out1 + decay-scan out2
    expand_kernel<<<(ROWS * 512) / 256, 256>>>();
    scan_kernel<<<dim3(G, NN / 256), 64>>>();

    // 6) out = cat @ W_out + b_out : [4096,1024] @ [1024,512]
    sgemm128<<<dim3(DIMM / 128, ROWS / 128), 256>>>(p_cat, 1024, W_out, DIMM,
                                                    out, DIMM, 1024, b_out);
}

// round 5
// speedup vs baseline: 1.2833x; 1.2833x over previous
#include <cuda_runtime.h>
#include <cstdint>
#include <cstddef>

// Problem constants
#define BB    2
#define NN    2048
#define DIMM  512
#define HH    8
#define DHH   64
#define NQ    513          // distinct effective query rows per head (q[i] = q[i % 513])
#define G     16           // B*H
#define ROWS  4096         // B*N
#define QC    2048         // qkvt columns (4*inner)

// r = exp(-1/e)
#define RDEC 0.69220062755534637f

// ---------------- scratch (static device arrays; no allocation) ----------------
__device__ __align__(256) float g_qkvt[(size_t)ROWS * QC];       // 32 MB  [4096][2048]
__device__ __align__(256) float g_S[(size_t)G * NQ * NN];        // 67 MB  [g][513][2048]
__device__ __align__(256) float g_out1[(size_t)G * NQ * DHH];    // 2.1 MB [g][513][64]
__device__ __align__(256) float g_cat[(size_t)ROWS * 1024];      // 16 MB  [4096][1024]
__device__ __align__(256) float g_sinv[NN];
__device__ __align__(256) float g_Wqt[(size_t)QC * DIMM];        // W_qkv^T [2048][512]
__device__ __align__(256) float g_Wot[(size_t)DIMM * 1024];      // W_out^T [512][1024]
__device__ __align__(256) float g_Vt[(size_t)G * DHH * NN];      // 8 MB  [g][64][2048]

// ======================= portable PTX helpers =======================
__device__ __forceinline__ uint32_t smem_u32(const void* p) {
    uint32_t a;
    asm("{ .reg .u64 t; cvta.to.shared.u64 t, %1; cvt.u32.u64 %0, t; }" : "=r"(a) : "l"(p));
    return a;
}
__device__ __forceinline__ void ldsm_x4(uint32_t* f, uint32_t addr) {
    asm volatile("ldmatrix.sync.aligned.m8n8.x4.shared.b16 {%0,%1,%2,%3}, [%4];"
                 : "=r"(f[0]), "=r"(f[1]), "=r"(f[2]), "=r"(f[3]) : "r"(addr));
}
__device__ __forceinline__ void sp32(uint32_t v, uint32_t& hi, uint32_t& lo) {
    float f = __uint_as_float(v);
    asm("cvt.rna.tf32.f32 %0, %1;" : "=r"(hi) : "f"(f));
    float d = f - __uint_as_float(hi);
    asm("cvt.rna.tf32.f32 %0, %1;" : "=r"(lo) : "f"(d));
}
__device__ __forceinline__ void mma8(float* c, const uint32_t* a, const uint32_t* b) {
    asm volatile("mma.sync.aligned.m16n8k8.row.col.f32.tf32.tf32.f32 "
                 "{%0,%1,%2,%3}, {%4,%5,%6,%7}, {%8,%9}, {%0,%1,%2,%3};"
                 : "+f"(c[0]), "+f"(c[1]), "+f"(c[2]), "+f"(c[3])
                 : "r"(a[0]), "r"(a[1]), "r"(a[2]), "r"(a[3]), "r"(b[0]), "r"(b[1]));
}
#define CP_ASYNC_COMMIT() asm volatile("cp.async.commit_group;")
#define CP_ASYNC_WAIT(n)  asm volatile("cp.async.wait_group %0;" :: "n"(n))

#define STAGES 3

// =====================================================================
// tf32 mma.sync GEMM: C[M,N] = scale * A[M,K] @ B[N,K]^T (+bias)
// CTA tile 128 x BN, 8 warps (4m x 2n), warp tile 32 x BN/2.
// 2-term tf32 split (3 mma per k8).  K%32==0, N tiles full.
// MODE 0: plain.  MODE 1: QK (per-z head offsets).  MODE 2: PV.
// =====================================================================
template<int BN, int MODE>
__global__ __launch_bounds__(256) void mma_gemm(
    const float* __restrict__ A0, int lda,
    const float* __restrict__ B0, int ldb,
    float* __restrict__ C0, int ldc,
    int M, int K, float scale, const float* __restrict__ bias)
{
    constexpr int BM = 128;
    constexpr int NTILES = BN / 16;          // n-tiles per warp (8 or 4)
    constexpr int ABYTES = BM * 32 * 4;      // 16 KB per stage
    constexpr int BBYTES = BN * 32 * 4;

    extern __shared__ __align__(1024) char smem[];
    uint32_t sAb = smem_u32(smem);
    uint32_t sBb = sAb + STAGES * ABYTES;

    int tid = threadIdx.x, wid = tid >> 5, lane = tid & 31;
    int row0 = blockIdx.y * BM, col0 = blockIdx.x * BN;

    const float* A = A0; const float* B = B0; float* C = C0;
    if (MODE == 1) {
        int z = blockIdx.z, b = z >> 3, h = z & 7;
        A += (size_t)b * NN * QC + h * DHH;
        B += (size_t)b * NN * QC + 512 + h * DHH;
        C += (size_t)z * NQ * NN;
    }
    if (MODE == 2) {
        int z = blockIdx.z;
        A += (size_t)z * NQ * NN;
        B += (size_t)z * DHH * NN;
        C += (size_t)z * NQ * DHH;
    }

    auto load_stage = [&](int stage, int k0) {
        uint32_t da = sAb + stage * ABYTES;
#pragma unroll
        for (int i = 0; i < BM * 8 / 256; ++i) {
            int chunk = tid + i * 256;
            int r = chunk >> 3, kc = chunk & 7;
            uint32_t dst = da + r * 128 + ((kc * 16) ^ ((r & 7) << 4));
            const float* src = A + (size_t)(row0 + r) * lda + k0 + kc * 4;
            uint32_t sz = (row0 + r < M) ? 16u : 0u;
            asm volatile("cp.async.cg.shared.global [%0], [%1], 16, %2;"
                         :: "r"(dst), "l"(src), "r"(sz));
        }
        uint32_t db = sBb + stage * BBYTES;
#pragma unroll
        for (int i = 0; i < BN * 8 / 256; ++i) {
            int chunk = tid + i * 256;
            int r = chunk >> 3, kc = chunk & 7;
            uint32_t dst = db + r * 128 + ((kc * 16) ^ ((r & 7) << 4));
            const float* src = B + (size_t)(col0 + r) * ldb + k0 + kc * 4;
            asm volatile("cp.async.cg.shared.global [%0], [%1], 16;"
                         :: "r"(dst), "l"(src));
        }
    };

    int NT = K >> 5;
#pragma unroll
    for (int s = 0; s < STAGES - 1; ++s) {
        if (s < NT) load_stage(s, s * 32);
        CP_ASYNC_COMMIT();
    }

    int wm = wid & 3, wn = wid >> 2;
    int mbase = wm * 32;
    int nbase = wn * (BN / 2);
    int lrow  = lane & 15;
    int lhalf = (lane >> 4) & 1;

    float acc[2][NTILES][4];
#pragma unroll
    for (int mt = 0; mt < 2; ++mt)
#pragma unroll
        for (int nt = 0; nt < NTILES; ++nt)
#pragma unroll
            for (int j = 0; j < 4; ++j) acc[mt][nt][j] = 0.f;

    for (int t = 0; t < NT; ++t) {
        CP_ASYNC_WAIT(STAGES - 2);
        __syncthreads();
        if (t + STAGES - 1 < NT)
            load_stage((t + STAGES - 1) % STAGES, (t + STAGES - 1) * 32);
        CP_ASYNC_COMMIT();

        int st = t % STAGES;
        uint32_t aBase = sAb + st * ABYTES;
        uint32_t bBase = sBb + st * BBYTES;
#pragma unroll
        for (int kk = 0; kk < 4; ++kk) {
            uint32_t ahi[2][4], alo[2][4];
#pragma unroll
            for (int mt = 0; mt < 2; ++mt) {
                int r = mbase + mt * 16 + lrow;
                uint32_t addr = aBase + r * 128 +
                                (((uint32_t)(kk * 32 + lhalf * 16)) ^ ((r & 7) << 4));
                uint32_t f[4];
                ldsm_x4(f, addr);
#pragma unroll
                for (int j = 0; j < 4; ++j) sp32(f[j], ahi[mt][j], alo[mt][j]);
            }
            uint32_t bhi[NTILES][2], blo[NTILES][2];
#pragma unroll
            for (int p = 0; p < NTILES / 2; ++p) {
                int r = nbase + p * 16 + lrow;
                uint32_t addr = bBase + r * 128 +
                                (((uint32_t)(kk * 32 + lhalf * 16)) ^ ((r & 7) << 4));
                uint32_t f[4];
                ldsm_x4(f, addr);
                sp32(f[0], bhi[2 * p][0],     blo[2 * p][0]);
                sp32(f[1], bhi[2 * p + 1][0], blo[2 * p + 1][0]);
                sp32(f[2], bhi[2 * p][1],     blo[2 * p][1]);
                sp32(f[3], bhi[2 * p + 1][1], blo[2 * p + 1][1]);
            }
#pragma unroll
            for (int mt = 0; mt < 2; ++mt)
#pragma unroll
                for (int nt = 0; nt < NTILES; ++nt) {
                    mma8(acc[mt][nt], ahi[mt], bhi[nt]);
                    mma8(acc[mt][nt], ahi[mt], blo[nt]);
                    mma8(acc[mt][nt], alo[mt], bhi[nt]);
                }
        }
    }
    CP_ASYNC_WAIT(0);

    // epilogue: c0,c1 -> (row=lane/4, col=(lane%4)*2); c2,c3 -> row+8
    int cr = lane >> 2, cc = (lane & 3) * 2;
#pragma unroll
    for (int mt = 0; mt < 2; ++mt) {
        int rg = row0 + mbase + mt * 16 + cr;
#pragma unroll
        for (int nt = 0; nt < NTILES; ++nt) {
            int cg = col0 + nbase + nt * 8 + cc;
            float2 b2 = make_float2(0.f, 0.f);
            if (bias) b2 = *(const float2*)(bias + cg);
            if (rg < M) {
                float2 v = make_float2(acc[mt][nt][0] * scale + b2.x,
                                       acc[mt][nt][1] * scale + b2.y);
                *(float2*)(C + (size_t)rg * ldc + cg) = v;
            }
            if (rg + 8 < M) {
                float2 v = make_float2(acc[mt][nt][2] * scale + b2.x,
                                       acc[mt][nt][3] * scale + b2.y);
                *(float2*)(C + (size_t)(rg + 8) * ldc + cg) = v;
            }
        }
    }
}

// =====================================================================
// Transpose: D[c][r] = S[r][c].  S is [R][Cc].  block (32,8), tile 32x32.
// =====================================================================
__global__ void transpose_k(const float* __restrict__ S, float* __restrict__ D,
                            int R, int Cc)
{
    __shared__ float t[32][33];
    int bx = blockIdx.x * 32, by = blockIdx.y * 32;
    int x = bx + threadIdx.x, y = by + threadIdx.y;
#pragma unroll
    for (int i = 0; i < 32; i += 8)
        if (x < Cc && y + i < R) t[threadIdx.y + i][threadIdx.x] = S[(size_t)(y + i) * Cc + x];
    __syncthreads();
    x = by + threadIdx.x; y = bx + threadIdx.y;
#pragma unroll
    for (int i = 0; i < 32; i += 8)
        if (x < R && y + i < Cc) D[(size_t)(y + i) * R + x] = t[threadIdx.x][threadIdx.y + i];
}

// =====================================================================
// Vt[g][c][j] = V[g][j][c]  (V = qkvt quarter 3).  block (32,8).
// =====================================================================
__global__ void vtrans()
{
    int g = blockIdx.z, b = g >> 3, h = g & 7;
    int j0 = blockIdx.x * 32, c0 = blockIdx.y * 32;
    __shared__ float t[32][33];
    const float* src = g_qkvt + (size_t)b * NN * QC + 1024 + h * DHH;
#pragma unroll
    for (int i = 0; i < 32; i += 8)
        t[threadIdx.y + i][threadIdx.x] =
            src[(size_t)(j0 + threadIdx.y + i) * QC + c0 + threadIdx.x];
    __syncthreads();
    float* dst = g_Vt + (size_t)g * DHH * NN;
#pragma unroll
    for (int i = 0; i < 32; i += 8)
        dst[(size_t)(c0 + threadIdx.y + i) * NN + j0 + threadIdx.x] =
            t[threadIdx.x][threadIdx.y + i];
}

// =====================================================================
// Row softmax over g_S rows (16*513 rows of length 2048), in place.
// =====================================================================
__global__ __launch_bounds__(256) void softmax_kernel()
{
    size_t row = blockIdx.x;
    float* p = g_S + row * NN;
    int tid = threadIdx.x;
    float4 v0 = ((const float4*)p)[tid];
    float4 v1 = ((const float4*)p)[tid + 256];

    float m = fmaxf(fmaxf(fmaxf(v0.x, v0.y), fmaxf(v0.z, v0.w)),
                    fmaxf(fmaxf(v1.x, v1.y), fmaxf(v1.z, v1.w)));
    __shared__ float red[256];
    red[tid] = m; __syncthreads();
    for (int s = 128; s > 0; s >>= 1) {
        if (tid < s) red[tid] = fmaxf(red[tid], red[tid + s]);
        __syncthreads();
    }
    float bm = red[0];
    __syncthreads();

    v0.x = __expf(v0.x - bm); v0.y = __expf(v0.y - bm);
    v0.z = __expf(v0.z - bm); v0.w = __expf(v0.w - bm);
    v1.x = __expf(v1.x - bm); v1.y = __expf(v1.y - bm);
    v1.z = __expf(v1.z - bm); v1.w = __expf(v1.w - bm);
    float s8 = v0.x + v0.y + v0.z + v0.w + v1.x + v1.y + v1.z + v1.w;
    red[tid] = s8; __syncthreads();
    for (int s = 128; s > 0; s >>= 1) {
        if (tid < s) red[tid] += red[tid + s];
        __syncthreads();
    }
    float inv = 1.0f / red[0];

    v0.x *= inv; v0.y *= inv; v0.z *= inv; v0.w *= inv;
    v1.x *= inv; v1.y *= inv; v1.z *= inv; v1.w *= inv;
    ((float4*)p)[tid]       = v0;
    ((float4*)p)[tid + 256] = v1;
}

// =====================================================================
// Expand out1 (513 distinct rows) into cat[:, h*128 + 0..63] via i%513.
// =====================================================================
__global__ void expand_kernel()
{
    int idx = blockIdx.x * 256 + threadIdx.x;
    int row = idx >> 9;
    int col = idx & 511;
    int b = row >> 11, i = row & 2047;
    int h = col >> 6,  c = col & 63;
    g_cat[(size_t)row * 1024 + h * 128 + c] =
        g_out1[(((size_t)(b * 8 + h)) * NQ + (i % 513)) * DHH + c];
}

// =====================================================================
__global__ void sinv_kernel()
{
    int j = blockIdx.x * 256 + threadIdx.x;
    if (j < NN) {
        const float r = RDEC;
        float s = (1.0f - powf(r, (float)(j + 1)) + r - powf(r, (float)(NN - j)))
                  / (1.0f - r);
        g_sinv[j] = 1.0f / s;
    }
}

// =====================================================================
// out2 via decay scan, 96-halo chunks. grid (16 g, 8 chunks), 64 threads.
// =====================================================================
__global__ __launch_bounds__(64) void scan_kernel()
{
    int g = blockIdx.x, chunk = blockIdx.y;
    int b = g >> 3, h = g & 7;
    int c = threadIdx.x;
    const float r = RDEC;
    const float* T = g_qkvt + (size_t)b * NN * QC + 1536 + h * DHH + c;
    float* Cc = g_cat + (size_t)b * NN * 1024 + h * 128 + 64 + c;
    int i0 = chunk * 256;

    int js = i0 - 96; if (js < 0) js = 0;
    float f = 0.f;
    for (int j = js; j < i0 + 256; j++) {
        float u = T[(size_t)j * QC] * g_sinv[j];
        f = f * r + u;
        if (j >= i0) Cc[(size_t)j * 1024] = f - u;
    }
    int je = i0 + 255 + 96; if (je > NN - 1) je = NN - 1;
    float gg = 0.f;
    for (int j = je; j >= i0; j--) {
        float u = T[(size_t)j * QC] * g_sinv[j];
        gg = gg * r + u;
        if (j < i0 + 256) Cc[(size_t)j * 1024] += gg;
    }
}

// =====================================================================
#define SMA128 (STAGES * (128 + 128) * 32 * 4)
#define SMA64  (STAGES * (128 + 64)  * 32 * 4)

extern "C" void kernel_launch(void* const* d_in, const int* in_sizes, int n_in,
                              void* d_out, int out_size)
{
    const float* x     = (const float*)d_in[0];   // [2,2048,512]
    const float* W_qkv = (const float*)d_in[1];   // [512,2048]
    const float* W_out = (const float*)d_in[2];   // [1024,512]
    const float* b_out = (const float*)d_in[3];   // [512]
    float* out = (float*)d_out;                   // [2,2048,512]

    float *p_qkvt, *p_cat, *p_Wqt, *p_Wot, *p_S, *p_Vt, *p_out1;
    cudaGetSymbolAddress((void**)&p_qkvt, g_qkvt);
    cudaGetSymbolAddress((void**)&p_cat,  g_cat);
    cudaGetSymbolAddress((void**)&p_Wqt,  g_Wqt);
    cudaGetSymbolAddress((void**)&p_Wot,  g_Wot);
    cudaGetSymbolAddress((void**)&p_S,    g_S);
    cudaGetSymbolAddress((void**)&p_Vt,   g_Vt);
    cudaGetSymbolAddress((void**)&p_out1, g_out1);

    static bool attr_done = false;
    if (!attr_done) {
        cudaFuncSetAttribute(mma_gemm<128, 0>,
                             cudaFuncAttributeMaxDynamicSharedMemorySize, SMA128);
        cudaFuncSetAttribute(mma_gemm<128, 1>,
                             cudaFuncAttributeMaxDynamicSharedMemorySize, SMA128);
        cudaFuncSetAttribute(mma_gemm<64, 2>,
                             cudaFuncAttributeMaxDynamicSharedMemorySize, SMA64);
        attr_done = true;
    }

    // 0) weight transposes to [N,K] K-major; sinv
    transpose_k<<<dim3(64, 16), dim3(32, 8)>>>(W_qkv, p_Wqt, 512, 2048);
    transpose_k<<<dim3(16, 32), dim3(32, 8)>>>(W_out, p_Wot, 1024, 512);
    sinv_kernel<<<8, 256>>>();

    // 1) qkvt = x @ W_qkv : M=4096, N=2048, K=512
    mma_gemm<128, 0><<<dim3(16, 32, 1), 256, SMA128>>>(
        x, DIMM, p_Wqt, DIMM, p_qkvt, QC, ROWS, DIMM, 1.0f, nullptr);

    // 1b) V transpose for PV (K-major B operand)
    vtrans<<<dim3(64, 2, G), dim3(32, 8)>>>();

    // 2) S = 0.125 * Q_eff @ K^T : per g, M=513, N=2048, K=64
    mma_gemm<128, 1><<<dim3(16, 5, G), 256, SMA128>>>(
        p_qkvt, QC, p_qkvt, QC, p_S, NN, NQ, DHH, 0.125f, nullptr);

    // 3) softmax rows
    softmax_kernel<<<G * NQ, 256>>>();

    // 4) out1 = P @ Vt^T : per g, M=513, N=64, K=2048
    mma_gemm<64, 2><<<dim3(1, 5, G), 256, SMA64>>>(
        p_S, NN, p_Vt, NN, p_out1, DHH, NQ, NN, 1.0f, nullptr);

    // 5) assemble cat
    expand_kernel<<<(ROWS * 512) / 256, 256>>>();
    scan_kernel<<<dim3(G, NN / 256), 64>>>();

    // 6) out = cat @ W_out + b_out : M=4096, N=512, K=1024
    mma_gemm<128, 0><<<dim3(4, 32, 1), 256, SMA128>>>(
        p_cat, 1024, p_Wot, 1024, out, DIMM, ROWS, 1024, 1.0f, b_out);
}

// round 6
// speedup vs baseline: 1.8754x; 1.4614x over previous
#include <cuda_runtime.h>
#include <cuda_bf16.h>
#include <cstdint>
#include <cstddef>

// Problem constants
#define BB    2
#define NN    2048
#define DIMM  512
#define HH    8
#define DHH   64
#define NQ    513          // distinct effective query rows per head (q[i] = q[i % 513])
#define G     16           // B*H
#define ROWS  4096         // B*N
#define QC    2048         // qkvt columns (4*inner)

// r = exp(-1/e)
#define RDEC 0.69220062755534637f

typedef __nv_bfloat16  bf16;
typedef __nv_bfloat162 bf162;

// ---------------- scratch (static device arrays; no allocation) ----------------
__device__ __align__(256) float g_qkvt[(size_t)ROWS * QC];        // 32 MB fp32 (V, t, scan)
__device__ __align__(256) float g_S[(size_t)G * NQ * NN];         // 67 MB fp32 logits
__device__ __align__(256) float g_out1[(size_t)G * NQ * DHH];     // 2.1 MB fp32
__device__ __align__(256) float g_o2[(size_t)G * NN * DHH];       // 8 MB fp32 (out2)
__device__ __align__(256) float g_sinv[NN];

__device__ __align__(256) bf16 g_xh[(size_t)ROWS * DIMM];         // x planes
__device__ __align__(256) bf16 g_xl[(size_t)ROWS * DIMM];
__device__ __align__(256) bf16 g_Wqth[(size_t)QC * DIMM];         // W_qkv^T planes [2048][512]
__device__ __align__(256) bf16 g_Wqtl[(size_t)QC * DIMM];
__device__ __align__(256) bf16 g_Woth[(size_t)DIMM * 1024];       // W_out^T planes [512][1024]
__device__ __align__(256) bf16 g_Wotl[(size_t)DIMM * 1024];
__device__ __align__(256) bf16 g_qkh[(size_t)ROWS * 1024];        // qkvt cols<1024 planes
__device__ __align__(256) bf16 g_qkl[(size_t)ROWS * 1024];
__device__ __align__(256) bf16 g_Vth[(size_t)G * DHH * NN];       // V^T planes [g][64][2048]
__device__ __align__(256) bf16 g_Vtl[(size_t)G * DHH * NN];
__device__ __align__(256) bf16 g_Sh[(size_t)G * NQ * NN];         // softmax planes
__device__ __align__(256) bf16 g_Sl[(size_t)G * NQ * NN];
__device__ __align__(256) bf16 g_cath[(size_t)ROWS * 1024];       // cat planes
__device__ __align__(256) bf16 g_catl[(size_t)ROWS * 1024];

// ======================= portable PTX helpers =======================
__device__ __forceinline__ uint32_t smem_u32(const void* p) {
    uint32_t a;
    asm("{ .reg .u64 t; cvta.to.shared.u64 t, %1; cvt.u32.u64 %0, t; }" : "=r"(a) : "l"(p));
    return a;
}
__device__ __forceinline__ void ldsm_x4(uint32_t* f, uint32_t addr) {
    asm volatile("ldmatrix.sync.aligned.m8n8.x4.shared.b16 {%0,%1,%2,%3}, [%4];"
                 : "=r"(f[0]), "=r"(f[1]), "=r"(f[2]), "=r"(f[3]) : "r"(addr));
}
__device__ __forceinline__ void mma16(float* c, const uint32_t* a, const uint32_t* b) {
    asm volatile("mma.sync.aligned.m16n8k16.row.col.f32.bf16.bf16.f32 "
                 "{%0,%1,%2,%3}, {%4,%5,%6,%7}, {%8,%9}, {%0,%1,%2,%3};"
                 : "+f"(c[0]), "+f"(c[1]), "+f"(c[2]), "+f"(c[3])
                 : "r"(a[0]), "r"(a[1]), "r"(a[2]), "r"(a[3]), "r"(b[0]), "r"(b[1]));
}
#define CP_ASYNC_COMMIT() asm volatile("cp.async.commit_group;")
#define CP_ASYNC_WAIT(n)  asm volatile("cp.async.wait_group %0;" :: "n"(n))

__device__ __forceinline__ void bsplit(float v, bf16& h, bf16& l) {
    h = __float2bfloat16(v);
    l = __float2bfloat16(v - __bfloat162float(h));
}

// interleaved-line SMEM layout: 2 rows per 128B line, 8x 16B chunks, XOR(line&7)
__device__ __forceinline__ uint32_t tpos(int r, int ch) {
    return ((uint32_t)(r >> 1) << 7) |
           ((uint32_t)((((r & 1) << 2) | ch) ^ ((r >> 1) & 7)) << 4);
}

#define STAGES 3

// =====================================================================
// bf16x3 mma.sync GEMM: C[M,N] = scale * A[M,K] @ B[N,K]^T (+bias)
// A/B given as precomputed (hi, lo) bf16 planes, K-major, ld in elems.
// CTA tile BM x BN, 8 warps (4m x 2n).  BK=32 per stage, 2 k16 steps.
// MODE 0: plain (+bias).  MODE 1: qkvt (also writes Q/K planes for col<1024).
// MODE 2: QK per-z offsets.  MODE 3: PV per-z offsets.
// =====================================================================
template<int BM, int BN, int MODE>
__global__ __launch_bounds__(256) void bmma_gemm(
    const bf16* __restrict__ Ah0, const bf16* __restrict__ Al0, int lda,
    const bf16* __restrict__ Bh0, const bf16* __restrict__ Bl0, int ldb,
    float* __restrict__ C0, int ldc,
    int M, int K, float scale, const float* __restrict__ bias)
{
    constexpr int MT     = BM / 64;      // m16 tiles per warp
    constexpr int NTILES = BN / 16;      // n8 tiles per warp
    constexpr int APL = BM * 64;         // bytes per A plane per stage
    constexpr int BPL = BN * 64;
    constexpr int STAGE = 2 * (APL + BPL);

    extern __shared__ __align__(1024) char smem[];
    uint32_t sbase = smem_u32(smem);

    int tid = threadIdx.x, wid = tid >> 5, lane = tid & 31;
    int row0 = blockIdx.y * BM, col0 = blockIdx.x * BN;

    const bf16* Ah = Ah0; const bf16* Al = Al0;
    const bf16* Bh = Bh0; const bf16* Bl = Bl0;
    float* C = C0;
    if (MODE == 2) {
        int z = blockIdx.z, b = z >> 3, h = z & 7;
        size_t ao = (size_t)b * 2048 * 1024 + h * 64;
        Ah += ao; Al += ao;
        Bh += ao + 512; Bl += ao + 512;
        C  += (size_t)z * NQ * NN;
    }
    if (MODE == 3) {
        int z = blockIdx.z;
        size_t ao = (size_t)z * NQ * 2048;
        Ah += ao; Al += ao;
        size_t bo = (size_t)z * 64 * 2048;
        Bh += bo; Bl += bo;
        C += (size_t)z * NQ * 64;
    }

    auto load_stage = [&](int stage, int k0) {
        uint32_t sb = sbase + stage * STAGE;
#pragma unroll
        for (int i = 0; i < BM * 4 / 256; ++i) {
            int id = tid + i * 256;
            int r = id >> 2, ch = id & 3;
            uint32_t pos = tpos(r, ch);
            const bf16* sh = Ah + (size_t)(row0 + r) * lda + k0 + ch * 8;
            const bf16* sl = Al + (size_t)(row0 + r) * lda + k0 + ch * 8;
            uint32_t gz = (row0 + r < M) ? 16u : 0u;
            asm volatile("cp.async.cg.shared.global [%0], [%1], 16, %2;"
                         :: "r"(sb + pos), "l"(sh), "r"(gz));
            asm volatile("cp.async.cg.shared.global [%0], [%1], 16, %2;"
                         :: "r"(sb + APL + pos), "l"(sl), "r"(gz));
        }
#pragma unroll
        for (int i = 0; i < BN * 4 / 256; ++i) {
            int id = tid + i * 256;
            int r = id >> 2, ch = id & 3;
            uint32_t pos = tpos(r, ch);
            const bf16* sh = Bh + (size_t)(col0 + r) * ldb + k0 + ch * 8;
            const bf16* sl = Bl + (size_t)(col0 + r) * ldb + k0 + ch * 8;
            asm volatile("cp.async.cg.shared.global [%0], [%1], 16;"
                         :: "r"(sb + 2 * APL + pos), "l"(sh));
            asm volatile("cp.async.cg.shared.global [%0], [%1], 16;"
                         :: "r"(sb + 2 * APL + BPL + pos), "l"(sl));
        }
    };

    int NT = K >> 5;
#pragma unroll
    for (int s = 0; s < STAGES - 1; ++s) {
        if (s < NT) load_stage(s, s * 32);
        CP_ASYNC_COMMIT();
    }

    int wm = wid & 3, wn = wid >> 2;
    int mbase = wm * (BM / 4);
    int nbase = wn * (BN / 2);

    float acc[MT][NTILES][4];
#pragma unroll
    for (int mt = 0; mt < MT; ++mt)
#pragma unroll
        for (int nt = 0; nt < NTILES; ++nt)
#pragma unroll
            for (int j = 0; j < 4; ++j) acc[mt][nt][j] = 0.f;

    for (int t = 0; t < NT; ++t) {
        CP_ASYNC_WAIT(STAGES - 2);
        __syncthreads();
        if (t + STAGES - 1 < NT)
            load_stage((t + STAGES - 1) % STAGES, (t + STAGES - 1) * 32);
        CP_ASYNC_COMMIT();

        uint32_t sb = sbase + (t % STAGES) * STAGE;
#pragma unroll
        for (int kk = 0; kk < 2; ++kk) {
            uint32_t ah[MT][4], al[MT][4];
#pragma unroll
            for (int mt = 0; mt < MT; ++mt) {
                int r = mbase + mt * 16 + (lane & 15);
                int ch = kk * 2 + (lane >> 4);
                uint32_t pos = tpos(r, ch);
                ldsm_x4(ah[mt], sb + pos);
                ldsm_x4(al[mt], sb + APL + pos);
            }
            uint32_t bh[NTILES][2], bl[NTILES][2];
#pragma unroll
            for (int p = 0; p < NTILES / 2; ++p) {
                int r = nbase + p * 16 + ((lane >> 4) << 3) + (lane & 7);
                int ch = kk * 2 + ((lane >> 3) & 1);
                uint32_t pos = tpos(r, ch);
                uint32_t f[4];
                ldsm_x4(f, sb + 2 * APL + pos);
                bh[2 * p][0] = f[0]; bh[2 * p][1] = f[1];
                bh[2 * p + 1][0] = f[2]; bh[2 * p + 1][1] = f[3];
                ldsm_x4(f, sb + 2 * APL + BPL + pos);
                bl[2 * p][0] = f[0]; bl[2 * p][1] = f[1];
                bl[2 * p + 1][0] = f[2]; bl[2 * p + 1][1] = f[3];
            }
#pragma unroll
            for (int mt = 0; mt < MT; ++mt)
#pragma unroll
                for (int nt = 0; nt < NTILES; ++nt) {
                    mma16(acc[mt][nt], ah[mt], bh[nt]);
                    mma16(acc[mt][nt], ah[mt], bl[nt]);
                    mma16(acc[mt][nt], al[mt], bh[nt]);
                }
        }
    }
    CP_ASYNC_WAIT(0);

    // epilogue: c0,c1 -> (row=lane/4, col=(lane%4)*2); c2,c3 -> row+8
    int cr = lane >> 2, cc = (lane & 3) * 2;
#pragma unroll
    for (int mt = 0; mt < MT; ++mt) {
        int rgb = row0 + mbase + mt * 16 + cr;
#pragma unroll
        for (int nt = 0; nt < NTILES; ++nt) {
            int cg = col0 + nbase + nt * 8 + cc;
            float2 b2 = make_float2(0.f, 0.f);
            if (MODE == 0 && bias) b2 = *(const float2*)(bias + cg);
#pragma unroll
            for (int half = 0; half < 2; ++half) {
                int rg = rgb + half * 8;
                if (rg < M) {
                    float2 v = make_float2(acc[mt][nt][half * 2] * scale + b2.x,
                                           acc[mt][nt][half * 2 + 1] * scale + b2.y);
                    *(float2*)(C + (size_t)rg * ldc + cg) = v;
                    if (MODE == 1 && cg < 1024) {
                        bf16 hx, lx, hy, ly;
                        bsplit(v.x, hx, lx); bsplit(v.y, hy, ly);
                        bf162 hh; hh.x = hx; hh.y = hy;
                        bf162 ll; ll.x = lx; ll.y = ly;
                        *(bf162*)&g_qkh[(size_t)rg * 1024 + cg] = hh;
                        *(bf162*)&g_qkl[(size_t)rg * 1024 + cg] = ll;
                    }
                }
            }
        }
    }
}

// =====================================================================
// x splitter: fp32 -> (hi, lo) bf16 planes
// =====================================================================
__global__ void split_x_kernel(const float* __restrict__ X)
{
    int i = blockIdx.x * 256 + threadIdx.x;        // < ROWS*DIMM/4
    float4 v = ((const float4*)X)[i];
    bf16 h0, l0, h1, l1, h2, l2, h3, l3;
    bsplit(v.x, h0, l0); bsplit(v.y, h1, l1);
    bsplit(v.z, h2, l2); bsplit(v.w, h3, l3);
    bf162 a, b;
    a.x = h0; a.y = h1; b.x = h2; b.y = h3;
    ((bf162*)g_xh)[i * 2] = a; ((bf162*)g_xh)[i * 2 + 1] = b;
    a.x = l0; a.y = l1; b.x = l2; b.y = l3;
    ((bf162*)g_xl)[i * 2] = a; ((bf162*)g_xl)[i * 2 + 1] = b;
}

// =====================================================================
// Transpose + split: D[c][r] planes = split(S[r][c]).  R,C % 32 == 0.
// =====================================================================
__global__ void transpose_split(const float* __restrict__ S,
                                bf16* __restrict__ Dh, bf16* __restrict__ Dl,
                                int R, int C)
{
    __shared__ float t[32][33];
    int bx = blockIdx.x * 32, by = blockIdx.y * 32;
#pragma unroll
    for (int i = 0; i < 32; i += 8)
        t[threadIdx.y + i][threadIdx.x] =
            S[(size_t)(by + threadIdx.y + i) * C + bx + threadIdx.x];
    __syncthreads();
#pragma unroll
    for (int i = 0; i < 32; i += 8) {
        float v = t[threadIdx.x][threadIdx.y + i];
        bf16 h, l; bsplit(v, h, l);
        size_t o = (size_t)(bx + threadIdx.y + i) * R + by + threadIdx.x;
        Dh[o] = h; Dl[o] = l;
    }
}

// =====================================================================
// V^T planes: Vt[g][c][j] = split(qkvt V quarter).  grid (64, 2, 16).
// =====================================================================
__global__ void vtrans_split()
{
    int g = blockIdx.z, b = g >> 3, h = g & 7;
    int j0 = blockIdx.x * 32, c0 = blockIdx.y * 32;
    __shared__ float t[32][33];
    const float* src = g_qkvt + (size_t)b * NN * QC + 1024 + h * DHH;
#pragma unroll
    for (int i = 0; i < 32; i += 8)
        t[threadIdx.y + i][threadIdx.x] =
            src[(size_t)(j0 + threadIdx.y + i) * QC + c0 + threadIdx.x];
    __syncthreads();
#pragma unroll
    for (int i = 0; i < 32; i += 8) {
        float v = t[threadIdx.x][threadIdx.y + i];
        bf16 hh, ll; bsplit(v, hh, ll);
        size_t o = (size_t)g * DHH * NN + (size_t)(c0 + threadIdx.y + i) * NN + j0 + threadIdx.x;
        g_Vth[o] = hh; g_Vtl[o] = ll;
    }
}

// =====================================================================
// Row softmax over g_S rows (16*513 rows of 2048); writes bf16 planes.
// =====================================================================
__global__ __launch_bounds__(256) void softmax_kernel()
{
    size_t row = blockIdx.x;
    const float* p = g_S + row * NN;
    int tid = threadIdx.x;
    float4 v0 = ((const float4*)p)[tid];
    float4 v1 = ((const float4*)p)[tid + 256];

    float m = fmaxf(fmaxf(fmaxf(v0.x, v0.y), fmaxf(v0.z, v0.w)),
                    fmaxf(fmaxf(v1.x, v1.y), fmaxf(v1.z, v1.w)));
    __shared__ float red[256];
    red[tid] = m; __syncthreads();
    for (int s = 128; s > 0; s >>= 1) {
        if (tid < s) red[tid] = fmaxf(red[tid], red[tid + s]);
        __syncthreads();
    }
    float bm = red[0];
    __syncthreads();

    v0.x = __expf(v0.x - bm); v0.y = __expf(v0.y - bm);
    v0.z = __expf(v0.z - bm); v0.w = __expf(v0.w - bm);
    v1.x = __expf(v1.x - bm); v1.y = __expf(v1.y - bm);
    v1.z = __expf(v1.z - bm); v1.w = __expf(v1.w - bm);
    float s8 = v0.x + v0.y + v0.z + v0.w + v1.x + v1.y + v1.z + v1.w;
    red[tid] = s8; __syncthreads();
    for (int s = 128; s > 0; s >>= 1) {
        if (tid < s) red[tid] += red[tid + s];
        __syncthreads();
    }
    float inv = 1.0f / red[0];

    bf162* ph = (bf162*)(g_Sh + row * NN);
    bf162* pl = (bf162*)(g_Sl + row * NN);
    float vals[8] = {v0.x * inv, v0.y * inv, v0.z * inv, v0.w * inv,
                     v1.x * inv, v1.y * inv, v1.z * inv, v1.w * inv};
#pragma unroll
    for (int q = 0; q < 2; ++q) {
        int base = (q == 0) ? tid * 2 : tid * 2 + 512;
#pragma unroll
        for (int j = 0; j < 2; ++j) {
            bf16 h0, l0, h1, l1;
            bsplit(vals[q * 4 + j * 2],     h0, l0);
            bsplit(vals[q * 4 + j * 2 + 1], h1, l1);
            bf162 hh; hh.x = h0; hh.y = h1;
            bf162 ll; ll.x = l0; ll.y = l1;
            ph[base + j] = hh; pl[base + j] = ll;
        }
    }
}

// =====================================================================
__global__ void sinv_kernel()
{
    int j = blockIdx.x * 256 + threadIdx.x;
    if (j < NN) {
        const float r = RDEC;
        float s = (1.0f - powf(r, (float)(j + 1)) + r - powf(r, (float)(NN - j)))
                  / (1.0f - r);
        g_sinv[j] = 1.0f / s;
    }
}

// =====================================================================
// out2 via decay scan, 96-halo chunks -> g_o2[g][j][c] fp32.
// grid (16 g, 8 chunks), 64 threads (c).
// =====================================================================
__global__ __launch_bounds__(64) void scan_kernel()
{
    int g = blockIdx.x, chunk = blockIdx.y;
    int b = g >> 3, h = g & 7;
    int c = threadIdx.x;
    const float r = RDEC;
    const float* T = g_qkvt + (size_t)b * NN * QC + 1536 + h * DHH + c;
    float* O = g_o2 + (size_t)g * NN * DHH + c;
    int i0 = chunk * 256;

    int js = i0 - 96; if (js < 0) js = 0;
    float f = 0.f;
    for (int j = js; j < i0 + 256; j++) {
        float u = T[(size_t)j * QC] * g_sinv[j];
        f = f * r + u;
        if (j >= i0) O[(size_t)j * DHH] = f - u;
    }
    int je = i0 + 255 + 96; if (je > NN - 1) je = NN - 1;
    float gg = 0.f;
    for (int j = je; j >= i0; j--) {
        float u = T[(size_t)j * QC] * g_sinv[j];
        gg = gg * r + u;
        if (j < i0 + 256) O[(size_t)j * DHH] += gg;
    }
}

// =====================================================================
// Assemble cat planes: cols h*128+[0,64) from out1 (i%513), +[64,128) from o2.
// =====================================================================
__global__ void expand2_kernel()
{
    int idx = blockIdx.x * 256 + threadIdx.x;      // < 4096*1024
    int row = idx >> 10, q = idx & 1023;
    int b = row >> 11, i = row & 2047;
    int h = q >> 7, c = q & 127;
    int g = b * 8 + h;
    float v;
    if (c < 64)
        v = g_out1[((size_t)g * NQ + (i % 513)) * DHH + c];
    else
        v = g_o2[((size_t)g * NN + i) * DHH + (c - 64)];
    bf16 hh, ll; bsplit(v, hh, ll);
    g_cath[idx] = hh; g_catl[idx] = ll;
}

// =====================================================================
#define SM_QKV (STAGES * 2 * (128 * 64 + 128 * 64))   // 98304
#define SM_PV  (STAGES * 2 * (64 * 64 + 64 * 64))     // 49152
#define SM_OUT (STAGES * 2 * (128 * 64 + 64 * 64))    // 73728

extern "C" void kernel_launch(void* const* d_in, const int* in_sizes, int n_in,
                              void* d_out, int out_size)
{
    const float* x     = (const float*)d_in[0];   // [2,2048,512]
    const float* W_qkv = (const float*)d_in[1];   // [512,2048]
    const float* W_out = (const float*)d_in[2];   // [1024,512]
    const float* b_out = (const float*)d_in[3];   // [512]
    float* out = (float*)d_out;                   // [2,2048,512]

    float *p_qkvt, *p_S, *p_out1;
    bf16 *p_xh, *p_xl, *p_Wqth, *p_Wqtl, *p_Woth, *p_Wotl;
    bf16 *p_qkh, *p_qkl, *p_Vth, *p_Vtl, *p_Sh, *p_Sl, *p_cath, *p_catl;
    cudaGetSymbolAddress((void**)&p_qkvt, g_qkvt);
    cudaGetSymbolAddress((void**)&p_S,    g_S);
    cudaGetSymbolAddress((void**)&p_out1, g_out1);
    cudaGetSymbolAddress((void**)&p_xh,   g_xh);
    cudaGetSymbolAddress((void**)&p_xl,   g_xl);
    cudaGetSymbolAddress((void**)&p_Wqth, g_Wqth);
    cudaGetSymbolAddress((void**)&p_Wqtl, g_Wqtl);
    cudaGetSymbolAddress((void**)&p_Woth, g_Woth);
    cudaGetSymbolAddress((void**)&p_Wotl, g_Wotl);
    cudaGetSymbolAddress((void**)&p_qkh,  g_qkh);
    cudaGetSymbolAddress((void**)&p_qkl,  g_qkl);
    cudaGetSymbolAddress((void**)&p_Vth,  g_Vth);
    cudaGetSymbolAddress((void**)&p_Vtl,  g_Vtl);
    cudaGetSymbolAddress((void**)&p_Sh,   g_Sh);
    cudaGetSymbolAddress((void**)&p_Sl,   g_Sl);
    cudaGetSymbolAddress((void**)&p_cath, g_cath);
    cudaGetSymbolAddress((void**)&p_catl, g_catl);

    static bool attr_done = false;
    if (!attr_done) {
        cudaFuncSetAttribute(bmma_gemm<128, 128, 1>,
                             cudaFuncAttributeMaxDynamicSharedMemorySize, SM_QKV);
        cudaFuncSetAttribute(bmma_gemm<128, 128, 2>,
                             cudaFuncAttributeMaxDynamicSharedMemorySize, SM_QKV);
        cudaFuncSetAttribute(bmma_gemm<64, 64, 3>,
                             cudaFuncAttributeMaxDynamicSharedMemorySize, SM_PV);
        cudaFuncSetAttribute(bmma_gemm<128, 64, 0>,
                             cudaFuncAttributeMaxDynamicSharedMemorySize, SM_OUT);
        attr_done = true;
    }

    // 0) input/weight plane production (independent)
    split_x_kernel<<<(ROWS * DIMM / 4) / 256, 256>>>(x);
    transpose_split<<<dim3(64, 16), dim3(32, 8)>>>(W_qkv, p_Wqth, p_Wqtl, 512, 2048);
    transpose_split<<<dim3(16, 32), dim3(32, 8)>>>(W_out, p_Woth, p_Wotl, 1024, 512);
    sinv_kernel<<<8, 256>>>();

    // 1) qkvt = x @ W_qkv : M=4096, N=2048, K=512.  Writes fp32 + Q/K planes.
    bmma_gemm<128, 128, 1><<<dim3(16, 32, 1), 256, SM_QKV>>>(
        p_xh, p_xl, DIMM, p_Wqth, p_Wqtl, DIMM, p_qkvt, QC, ROWS, DIMM, 1.0f, nullptr);

    // 1b) V^T planes
    vtrans_split<<<dim3(64, 2, G), dim3(32, 8)>>>();

    // 2) S = 0.125 * Q_eff @ K^T : per g, M=513, N=2048, K=64
    bmma_gemm<128, 128, 2><<<dim3(16, 5, G), 256, SM_QKV>>>(
        p_qkh, p_qkl, 1024, p_qkh, p_qkl, 1024, p_S, NN, NQ, DHH, 0.125f, nullptr);

    // 3) softmax rows -> P planes
    softmax_kernel<<<G * NQ, 256>>>();

    // 4) out1 = P @ Vt^T : per g, M=513, N=64, K=2048  (144 CTAs = 1 wave)
    bmma_gemm<64, 64, 3><<<dim3(1, 9, G), 256, SM_PV>>>(
        p_Sh, p_Sl, NN, p_Vth, p_Vtl, NN, p_out1, DHH, NQ, NN, 1.0f, nullptr);

    // 5) out2 scan + cat plane assembly
    scan_kernel<<<dim3(G, NN / 256), 64>>>();
    expand2_kernel<<<(ROWS * 1024) / 256, 256>>>();

    // 6) out = cat @ W_out + b_out : M=4096, N=512, K=1024
    bmma_gemm<128, 64, 0><<<dim3(8, 32, 1), 256, SM_OUT>>>(
        p_cath, p_catl, 1024, p_Woth, p_Wotl, 1024, out, DIMM, ROWS, 1024, 1.0f, b_out);
}

// round 7
// speedup vs baseline: 1.8769x; 1.0008x over previous
#include <cuda_runtime.h>
#include <cuda_bf16.h>
#include <cstdint>
#include <cstddef>

// Problem constants
#define BB    2
#define NN    2048
#define DIMM  512
#define HH    8
#define DHH   64
#define NQ    513          // distinct effective query rows per head (q[i] = q[i % 513])
#define G     16           // B*H
#define ROWS  4096         // B*N
#define QC    2048         // qkvt columns (4*inner)

// r = exp(-1/e)
#define RDEC 0.69220062755534637f

typedef __nv_bfloat16  bf16;
typedef __nv_bfloat162 bf162;

// ---------------- scratch (static device arrays; no allocation) ----------------
__device__ __align__(256) float g_qkvt[(size_t)ROWS * QC];        // 32 MB fp32 (V, t, scan)
__device__ __align__(256) float g_S[(size_t)G * NQ * NN];         // 67 MB fp32 logits
__device__ __align__(256) float g_out1[(size_t)G * NQ * DHH];     // 2.1 MB fp32
__device__ __align__(256) float g_o2[(size_t)G * NN * DHH];       // 8 MB fp32 (out2)
__device__ __align__(256) float g_sinv[NN];

__device__ __align__(256) bf16 g_xh[(size_t)ROWS * DIMM];         // x planes
__device__ __align__(256) bf16 g_xl[(size_t)ROWS * DIMM];
__device__ __align__(256) bf16 g_Wqth[(size_t)QC * DIMM];         // W_qkv^T planes [2048][512]
__device__ __align__(256) bf16 g_Wqtl[(size_t)QC * DIMM];
__device__ __align__(256) bf16 g_Woth[(size_t)DIMM * 1024];       // W_out^T planes [512][1024]
__device__ __align__(256) bf16 g_Wotl[(size_t)DIMM * 1024];
__device__ __align__(256) bf16 g_qkh[(size_t)ROWS * 1024];        // qkvt cols<1024 planes
__device__ __align__(256) bf16 g_qkl[(size_t)ROWS * 1024];
__device__ __align__(256) bf16 g_Vth[(size_t)G * DHH * NN];       // V^T planes [g][64][2048]
__device__ __align__(256) bf16 g_Vtl[(size_t)G * DHH * NN];
__device__ __align__(256) bf16 g_Sh[(size_t)G * NQ * NN];         // softmax planes
__device__ __align__(256) bf16 g_Sl[(size_t)G * NQ * NN];
__device__ __align__(256) bf16 g_cath[(size_t)ROWS * 1024];       // cat planes
__device__ __align__(256) bf16 g_catl[(size_t)ROWS * 1024];

// ======================= portable PTX helpers =======================
__device__ __forceinline__ uint32_t smem_u32(const void* p) {
    uint32_t a;
    asm("{ .reg .u64 t; cvta.to.shared.u64 t, %1; cvt.u32.u64 %0, t; }" : "=r"(a) : "l"(p));
    return a;
}
__device__ __forceinline__ void ldsm_x4(uint32_t* f, uint32_t addr) {
    asm volatile("ldmatrix.sync.aligned.m8n8.x4.shared.b16 {%0,%1,%2,%3}, [%4];"
                 : "=r"(f[0]), "=r"(f[1]), "=r"(f[2]), "=r"(f[3]) : "r"(addr));
}
__device__ __forceinline__ void mma16(float* c, const uint32_t* a, const uint32_t* b) {
    asm volatile("mma.sync.aligned.m16n8k16.row.col.f32.bf16.bf16.f32 "
                 "{%0,%1,%2,%3}, {%4,%5,%6,%7}, {%8,%9}, {%0,%1,%2,%3};"
                 : "+f"(c[0]), "+f"(c[1]), "+f"(c[2]), "+f"(c[3])
                 : "r"(a[0]), "r"(a[1]), "r"(a[2]), "r"(a[3]), "r"(b[0]), "r"(b[1]));
}
#define CP_ASYNC_COMMIT() asm volatile("cp.async.commit_group;")
#define CP_ASYNC_WAIT(n)  asm volatile("cp.async.wait_group %0;" :: "n"(n))

__device__ __forceinline__ void bsplit(float v, bf16& h, bf16& l) {
    h = __float2bfloat16(v);
    l = __float2bfloat16(v - __bfloat162float(h));
}

// interleaved-line SMEM layout: 2 rows per 128B line, 8x 16B chunks, XOR(line&7)
__device__ __forceinline__ uint32_t tpos(int r, int ch) {
    return ((uint32_t)(r >> 1) << 7) |
           ((uint32_t)((((r & 1) << 2) | ch) ^ ((r >> 1) & 7)) << 4);
}

#define STAGES 3

// =====================================================================
// bf16x3 mma.sync GEMM: C[M,N] = scale * A[M,K] @ B[N,K]^T (+bias)
// A/B given as precomputed (hi, lo) bf16 planes, K-major, ld in elems.
// CTA tile BM x BN, 8 warps (4m x 2n).  BK=32 per stage, 2 k16 steps.
// MODE 0: plain (+bias).  MODE 1: qkvt (also writes Q/K planes for col<1024).
// MODE 2: QK per-z offsets.  MODE 3: PV per-z offsets.
// =====================================================================
template<int BM, int BN, int MODE>
__global__ __launch_bounds__(256) void bmma_gemm(
    const bf16* __restrict__ Ah0, const bf16* __restrict__ Al0, int lda,
    const bf16* __restrict__ Bh0, const bf16* __restrict__ Bl0, int ldb,
    float* __restrict__ C0, int ldc,
    int M, int K, float scale, const float* __restrict__ bias)
{
    constexpr int MT     = BM / 64;      // m16 tiles per warp
    constexpr int NTILES = BN / 16;      // n8 tiles per warp
    constexpr int APL = BM * 64;         // bytes per A plane per stage
    constexpr int BPL = BN * 64;
    constexpr int STAGE = 2 * (APL + BPL);

    extern __shared__ __align__(1024) char smem[];
    uint32_t sbase = smem_u32(smem);

    int tid = threadIdx.x, wid = tid >> 5, lane = tid & 31;
    int row0 = blockIdx.y * BM, col0 = blockIdx.x * BN;

    const bf16* Ah = Ah0; const bf16* Al = Al0;
    const bf16* Bh = Bh0; const bf16* Bl = Bl0;
    float* C = C0;
    if (MODE == 2) {
        int z = blockIdx.z, b = z >> 3, h = z & 7;
        size_t ao = (size_t)b * 2048 * 1024 + h * 64;
        Ah += ao; Al += ao;
        Bh += ao + 512; Bl += ao + 512;
        C  += (size_t)z * NQ * NN;
    }
    if (MODE == 3) {
        int z = blockIdx.z;
        size_t ao = (size_t)z * NQ * 2048;
        Ah += ao; Al += ao;
        size_t bo = (size_t)z * 64 * 2048;
        Bh += bo; Bl += bo;
        C += (size_t)z * NQ * 64;
    }

    auto load_stage = [&](int stage, int k0) {
        uint32_t sb = sbase + stage * STAGE;
#pragma unroll
        for (int i = 0; i < BM * 4 / 256; ++i) {
            int id = tid + i * 256;
            int r = id >> 2, ch = id & 3;
            uint32_t pos = tpos(r, ch);
            const bf16* sh = Ah + (size_t)(row0 + r) * lda + k0 + ch * 8;
            const bf16* sl = Al + (size_t)(row0 + r) * lda + k0 + ch * 8;
            uint32_t gz = (row0 + r < M) ? 16u : 0u;
            asm volatile("cp.async.cg.shared.global [%0], [%1], 16, %2;"
                         :: "r"(sb + pos), "l"(sh), "r"(gz));
            asm volatile("cp.async.cg.shared.global [%0], [%1], 16, %2;"
                         :: "r"(sb + APL + pos), "l"(sl), "r"(gz));
        }
#pragma unroll
        for (int i = 0; i < BN * 4 / 256; ++i) {
            int id = tid + i * 256;
            int r = id >> 2, ch = id & 3;
            uint32_t pos = tpos(r, ch);
            const bf16* sh = Bh + (size_t)(col0 + r) * ldb + k0 + ch * 8;
            const bf16* sl = Bl + (size_t)(col0 + r) * ldb + k0 + ch * 8;
            asm volatile("cp.async.cg.shared.global [%0], [%1], 16;"
                         :: "r"(sb + 2 * APL + pos), "l"(sh));
            asm volatile("cp.async.cg.shared.global [%0], [%1], 16;"
                         :: "r"(sb + 2 * APL + BPL + pos), "l"(sl));
        }
    };

    int NT = K >> 5;
#pragma unroll
    for (int s = 0; s < STAGES - 1; ++s) {
        if (s < NT) load_stage(s, s * 32);
        CP_ASYNC_COMMIT();
    }

    int wm = wid & 3, wn = wid >> 2;
    int mbase = wm * (BM / 4);
    int nbase = wn * (BN / 2);

    float acc[MT][NTILES][4];
#pragma unroll
    for (int mt = 0; mt < MT; ++mt)
#pragma unroll
        for (int nt = 0; nt < NTILES; ++nt)
#pragma unroll
            for (int j = 0; j < 4; ++j) acc[mt][nt][j] = 0.f;

    for (int t = 0; t < NT; ++t) {
        CP_ASYNC_WAIT(STAGES - 2);
        __syncthreads();
        if (t + STAGES - 1 < NT)
            load_stage((t + STAGES - 1) % STAGES, (t + STAGES - 1) * 32);
        CP_ASYNC_COMMIT();

        uint32_t sb = sbase + (t % STAGES) * STAGE;
#pragma unroll
        for (int kk = 0; kk < 2; ++kk) {
            uint32_t ah[MT][4], al[MT][4];
#pragma unroll
            for (int mt = 0; mt < MT; ++mt) {
                int r = mbase + mt * 16 + (lane & 15);
                int ch = kk * 2 + (lane >> 4);
                uint32_t pos = tpos(r, ch);
                ldsm_x4(ah[mt], sb + pos);
                ldsm_x4(al[mt], sb + APL + pos);
            }
            uint32_t bh[NTILES][2], bl[NTILES][2];
#pragma unroll
            for (int p = 0; p < NTILES / 2; ++p) {
                int r = nbase + p * 16 + ((lane >> 4) << 3) + (lane & 7);
                int ch = kk * 2 + ((lane >> 3) & 1);
                uint32_t pos = tpos(r, ch);
                uint32_t f[4];
                ldsm_x4(f, sb + 2 * APL + pos);
                bh[2 * p][0] = f[0]; bh[2 * p][1] = f[1];
                bh[2 * p + 1][0] = f[2]; bh[2 * p + 1][1] = f[3];
                ldsm_x4(f, sb + 2 * APL + BPL + pos);
                bl[2 * p][0] = f[0]; bl[2 * p][1] = f[1];
                bl[2 * p + 1][0] = f[2]; bl[2 * p + 1][1] = f[3];
            }
#pragma unroll
            for (int mt = 0; mt < MT; ++mt)
#pragma unroll
                for (int nt = 0; nt < NTILES; ++nt) {
                    mma16(acc[mt][nt], ah[mt], bh[nt]);
                    mma16(acc[mt][nt], ah[mt], bl[nt]);
                    mma16(acc[mt][nt], al[mt], bh[nt]);
                }
        }
    }
    CP_ASYNC_WAIT(0);

    // epilogue: c0,c1 -> (row=lane/4, col=(lane%4)*2); c2,c3 -> row+8
    int cr = lane >> 2, cc = (lane & 3) * 2;
#pragma unroll
    for (int mt = 0; mt < MT; ++mt) {
        int rgb = row0 + mbase + mt * 16 + cr;
#pragma unroll
        for (int nt = 0; nt < NTILES; ++nt) {
            int cg = col0 + nbase + nt * 8 + cc;
            float2 b2 = make_float2(0.f, 0.f);
            if (MODE == 0 && bias) b2 = *(const float2*)(bias + cg);
#pragma unroll
            for (int half = 0; half < 2; ++half) {
                int rg = rgb + half * 8;
                if (rg < M) {
                    float2 v = make_float2(acc[mt][nt][half * 2] * scale + b2.x,
                                           acc[mt][nt][half * 2 + 1] * scale + b2.y);
                    *(float2*)(C + (size_t)rg * ldc + cg) = v;
                    if (MODE == 1 && cg < 1024) {
                        bf16 hx, lx, hy, ly;
                        bsplit(v.x, hx, lx); bsplit(v.y, hy, ly);
                        bf162 hh; hh.x = hx; hh.y = hy;
                        bf162 ll; ll.x = lx; ll.y = ly;
                        *(bf162*)&g_qkh[(size_t)rg * 1024 + cg] = hh;
                        *(bf162*)&g_qkl[(size_t)rg * 1024 + cg] = ll;
                    }
                }
            }
        }
    }
}

// =====================================================================
// x splitter: fp32 -> (hi, lo) bf16 planes
// =====================================================================
__global__ void split_x_kernel(const float* __restrict__ X)
{
    int i = blockIdx.x * 256 + threadIdx.x;        // < ROWS*DIMM/4
    float4 v = ((const float4*)X)[i];
    bf16 h0, l0, h1, l1, h2, l2, h3, l3;
    bsplit(v.x, h0, l0); bsplit(v.y, h1, l1);
    bsplit(v.z, h2, l2); bsplit(v.w, h3, l3);
    bf162 a, b;
    a.x = h0; a.y = h1; b.x = h2; b.y = h3;
    ((bf162*)g_xh)[i * 2] = a; ((bf162*)g_xh)[i * 2 + 1] = b;
    a.x = l0; a.y = l1; b.x = l2; b.y = l3;
    ((bf162*)g_xl)[i * 2] = a; ((bf162*)g_xl)[i * 2 + 1] = b;
}

// =====================================================================
// Transpose + split: D[c][r] planes = split(S[r][c]).  R,C % 32 == 0.
// =====================================================================
__global__ void transpose_split(const float* __restrict__ S,
                                bf16* __restrict__ Dh, bf16* __restrict__ Dl,
                                int R, int C)
{
    __shared__ float t[32][33];
    int bx = blockIdx.x * 32, by = blockIdx.y * 32;
#pragma unroll
    for (int i = 0; i < 32; i += 8)
        t[threadIdx.y + i][threadIdx.x] =
            S[(size_t)(by + threadIdx.y + i) * C + bx + threadIdx.x];
    __syncthreads();
#pragma unroll
    for (int i = 0; i < 32; i += 8) {
        float v = t[threadIdx.x][threadIdx.y + i];
        bf16 h, l; bsplit(v, h, l);
        size_t o = (size_t)(bx + threadIdx.y + i) * R + by + threadIdx.x;
        Dh[o] = h; Dl[o] = l;
    }
}

// =====================================================================
// V^T planes: Vt[g][c][j] = split(qkvt V quarter).  grid (64, 2, 16).
// =====================================================================
__global__ void vtrans_split()
{
    int g = blockIdx.z, b = g >> 3, h = g & 7;
    int j0 = blockIdx.x * 32, c0 = blockIdx.y * 32;
    __shared__ float t[32][33];
    const float* src = g_qkvt + (size_t)b * NN * QC + 1024 + h * DHH;
#pragma unroll
    for (int i = 0; i < 32; i += 8)
        t[threadIdx.y + i][threadIdx.x] =
            src[(size_t)(j0 + threadIdx.y + i) * QC + c0 + threadIdx.x];
    __syncthreads();
#pragma unroll
    for (int i = 0; i < 32; i += 8) {
        float v = t[threadIdx.x][threadIdx.y + i];
        bf16 hh, ll; bsplit(v, hh, ll);
        size_t o = (size_t)g * DHH * NN + (size_t)(c0 + threadIdx.y + i) * NN + j0 + threadIdx.x;
        g_Vth[o] = hh; g_Vtl[o] = ll;
    }
}

// =====================================================================
// Row softmax over g_S rows (16*513 rows of 2048); writes bf16 planes.
// =====================================================================
__global__ __launch_bounds__(256) void softmax_kernel()
{
    size_t row = blockIdx.x;
    const float* p = g_S + row * NN;
    int tid = threadIdx.x;
    float4 v0 = ((const float4*)p)[tid];
    float4 v1 = ((const float4*)p)[tid + 256];

    float m = fmaxf(fmaxf(fmaxf(v0.x, v0.y), fmaxf(v0.z, v0.w)),
                    fmaxf(fmaxf(v1.x, v1.y), fmaxf(v1.z, v1.w)));
    __shared__ float red[256];
    red[tid] = m; __syncthreads();
    for (int s = 128; s > 0; s >>= 1) {
        if (tid < s) red[tid] = fmaxf(red[tid], red[tid + s]);
        __syncthreads();
    }
    float bm = red[0];
    __syncthreads();

    v0.x = __expf(v0.x - bm); v0.y = __expf(v0.y - bm);
    v0.z = __expf(v0.z - bm); v0.w = __expf(v0.w - bm);
    v1.x = __expf(v1.x - bm); v1.y = __expf(v1.y - bm);
    v1.z = __expf(v1.z - bm); v1.w = __expf(v1.w - bm);
    float s8 = v0.x + v0.y + v0.z + v0.w + v1.x + v1.y + v1.z + v1.w;
    red[tid] = s8; __syncthreads();
    for (int s = 128; s > 0; s >>= 1) {
        if (tid < s) red[tid] += red[tid + s];
        __syncthreads();
    }
    float inv = 1.0f / red[0];

    bf162* ph = (bf162*)(g_Sh + row * NN);
    bf162* pl = (bf162*)(g_Sl + row * NN);
    float vals[8] = {v0.x * inv, v0.y * inv, v0.z * inv, v0.w * inv,
                     v1.x * inv, v1.y * inv, v1.z * inv, v1.w * inv};
#pragma unroll
    for (int q = 0; q < 2; ++q) {
        int base = (q == 0) ? tid * 2 : tid * 2 + 512;
#pragma unroll
        for (int j = 0; j < 2; ++j) {
            bf16 h0, l0, h1, l1;
            bsplit(vals[q * 4 + j * 2],     h0, l0);
            bsplit(vals[q * 4 + j * 2 + 1], h1, l1);
            bf162 hh; hh.x = h0; hh.y = h1;
            bf162 ll; ll.x = l0; ll.y = l1;
            ph[base + j] = hh; pl[base + j] = ll;
        }
    }
}

// =====================================================================
__global__ void sinv_kernel()
{
    int j = blockIdx.x * 256 + threadIdx.x;
    if (j < NN) {
        const float r = RDEC;
        float s = (1.0f - powf(r, (float)(j + 1)) + r - powf(r, (float)(NN - j)))
                  / (1.0f - r);
        g_sinv[j] = 1.0f / s;
    }
}

// =====================================================================
// out2 via decay scan, 96-halo chunks -> g_o2[g][j][c] fp32.
// grid (16 g, 8 chunks), 64 threads (c).
// =====================================================================
__global__ __launch_bounds__(64) void scan_kernel()
{
    int g = blockIdx.x, chunk = blockIdx.y;
    int b = g >> 3, h = g & 7;
    int c = threadIdx.x;
    const float r = RDEC;
    const float* T = g_qkvt + (size_t)b * NN * QC + 1536 + h * DHH + c;
    float* O = g_o2 + (size_t)g * NN * DHH + c;
    int i0 = chunk * 256;

    int js = i0 - 96; if (js < 0) js = 0;
    float f = 0.f;
    for (int j = js; j < i0 + 256; j++) {
        float u = T[(size_t)j * QC] * g_sinv[j];
        f = f * r + u;
        if (j >= i0) O[(size_t)j * DHH] = f - u;
    }
    int je = i0 + 255 + 96; if (je > NN - 1) je = NN - 1;
    float gg = 0.f;
    for (int j = je; j >= i0; j--) {
        float u = T[(size_t)j * QC] * g_sinv[j];
        gg = gg * r + u;
        if (j < i0 + 256) O[(size_t)j * DHH] += gg;
    }
}

// =====================================================================
// Assemble cat planes: cols h*128+[0,64) from out1 (i%513), +[64,128) from o2.
// =====================================================================
__global__ void expand2_kernel()
{
    int idx = blockIdx.x * 256 + threadIdx.x;      // < 4096*1024
    int row = idx >> 10, q = idx & 1023;
    int b = row >> 11, i = row & 2047;
    int h = q >> 7, c = q & 127;
    int g = b * 8 + h;
    float v;
    if (c < 64)
        v = g_out1[((size_t)g * NQ + (i % 513)) * DHH + c];
    else
        v = g_o2[((size_t)g * NN + i) * DHH + (c - 64)];
    bf16 hh, ll; bsplit(v, hh, ll);
    g_cath[idx] = hh; g_catl[idx] = ll;
}

// =====================================================================
#define SM_QKV (STAGES * 2 * (128 * 64 + 128 * 64))   // 98304
#define SM_PV  (STAGES * 2 * (64 * 64 + 64 * 64))     // 49152
#define SM_OUT (STAGES * 2 * (128 * 64 + 64 * 64))    // 73728

extern "C" void kernel_launch(void* const* d_in, const int* in_sizes, int n_in,
                              void* d_out, int out_size)
{
    const float* x     = (const float*)d_in[0];   // [2,2048,512]
    const float* W_qkv = (const float*)d_in[1];   // [512,2048]
    const float* W_out = (const float*)d_in[2];   // [1024,512]
    const float* b_out = (const float*)d_in[3];   // [512]
    float* out = (float*)d_out;                   // [2,2048,512]

    float *p_qkvt, *p_S, *p_out1;
    bf16 *p_xh, *p_xl, *p_Wqth, *p_Wqtl, *p_Woth, *p_Wotl;
    bf16 *p_qkh, *p_qkl, *p_Vth, *p_Vtl, *p_Sh, *p_Sl, *p_cath, *p_catl;
    cudaGetSymbolAddress((void**)&p_qkvt, g_qkvt);
    cudaGetSymbolAddress((void**)&p_S,    g_S);
    cudaGetSymbolAddress((void**)&p_out1, g_out1);
    cudaGetSymbolAddress((void**)&p_xh,   g_xh);
    cudaGetSymbolAddress((void**)&p_xl,   g_xl);
    cudaGetSymbolAddress((void**)&p_Wqth, g_Wqth);
    cudaGetSymbolAddress((void**)&p_Wqtl, g_Wqtl);
    cudaGetSymbolAddress((void**)&p_Woth, g_Woth);
    cudaGetSymbolAddress((void**)&p_Wotl, g_Wotl);
    cudaGetSymbolAddress((void**)&p_qkh,  g_qkh);
    cudaGetSymbolAddress((void**)&p_qkl,  g_qkl);
    cudaGetSymbolAddress((void**)&p_Vth,  g_Vth);
    cudaGetSymbolAddress((void**)&p_Vtl,  g_Vtl);
    cudaGetSymbolAddress((void**)&p_Sh,   g_Sh);
    cudaGetSymbolAddress((void**)&p_Sl,   g_Sl);
    cudaGetSymbolAddress((void**)&p_cath, g_cath);
    cudaGetSymbolAddress((void**)&p_catl, g_catl);

    static bool attr_done = false;
    if (!attr_done) {
        cudaFuncSetAttribute(bmma_gemm<128, 128, 1>,
                             cudaFuncAttributeMaxDynamicSharedMemorySize, SM_QKV);
        cudaFuncSetAttribute(bmma_gemm<128, 128, 2>,
                             cudaFuncAttributeMaxDynamicSharedMemorySize, SM_QKV);
        cudaFuncSetAttribute(bmma_gemm<64, 64, 3>,
                             cudaFuncAttributeMaxDynamicSharedMemorySize, SM_PV);
        cudaFuncSetAttribute(bmma_gemm<128, 64, 0>,
                             cudaFuncAttributeMaxDynamicSharedMemorySize, SM_OUT);
        attr_done = true;
    }

    // 0) input/weight plane production (independent)
    split_x_kernel<<<(ROWS * DIMM / 4) / 256, 256>>>(x);
    transpose_split<<<dim3(64, 16), dim3(32, 8)>>>(W_qkv, p_Wqth, p_Wqtl, 512, 2048);
    transpose_split<<<dim3(16, 32), dim3(32, 8)>>>(W_out, p_Woth, p_Wotl, 1024, 512);
    sinv_kernel<<<8, 256>>>();

    // 1) qkvt = x @ W_qkv : M=4096, N=2048, K=512.  Writes fp32 + Q/K planes.
    bmma_gemm<128, 128, 1><<<dim3(16, 32, 1), 256, SM_QKV>>>(
        p_xh, p_xl, DIMM, p_Wqth, p_Wqtl, DIMM, p_qkvt, QC, ROWS, DIMM, 1.0f, nullptr);

    // 1b) V^T planes
    vtrans_split<<<dim3(64, 2, G), dim3(32, 8)>>>();

    // 2) S = 0.125 * Q_eff @ K^T : per g, M=513, N=2048, K=64
    bmma_gemm<128, 128, 2><<<dim3(16, 5, G), 256, SM_QKV>>>(
        p_qkh, p_qkl, 1024, p_qkh, p_qkl, 1024, p_S, NN, NQ, DHH, 0.125f, nullptr);

    // 3) softmax rows -> P planes
    softmax_kernel<<<G * NQ, 256>>>();

    // 4) out1 = P @ Vt^T : per g, M=513, N=64, K=2048  (144 CTAs = 1 wave)
    bmma_gemm<64, 64, 3><<<dim3(1, 9, G), 256, SM_PV>>>(
        p_Sh, p_Sl, NN, p_Vth, p_Vtl, NN, p_out1, DHH, NQ, NN, 1.0f, nullptr);

    // 5) out2 scan + cat plane assembly
    scan_kernel<<<dim3(G, NN / 256), 64>>>();
    expand2_kernel<<<(ROWS * 1024) / 256, 256>>>();

    // 6) out = cat @ W_out + b_out : M=4096, N=512, K=1024
    bmma_gemm<128, 64, 0><<<dim3(8, 32, 1), 256, SM_OUT>>>(
        p_cath, p_catl, 1024, p_Woth, p_Wotl, 1024, out, DIMM, ROWS, 1024, 1.0f, b_out);
}

// round 10
// speedup vs baseline: 2.0919x; 1.1146x over previous
#include <cuda_runtime.h>
#include <cuda_bf16.h>
#include <cstdint>
#include <cstddef>

// Problem constants
#define BB    2
#define NN    2048
#define DIMM  512
#define HH    8
#define DHH   64
#define NQ    513          // distinct effective query rows per head (q[i] = q[i % 513])
#define G     16           // B*H
#define ROWS  4096         // B*N
#define QC    2048         // qkvt columns (4*inner)
#define FROWS 640          // padded NQ for flash partials (5 * 128)

// r = exp(-1/e)
#define RDEC 0.69220062755534637f

typedef __nv_bfloat16  bf16;
typedef __nv_bfloat162 bf162;

// ---------------- scratch (static device arrays; no allocation) ----------------
__device__ __align__(256) float g_qkvt[(size_t)ROWS * QC];        // 32 MB fp32 (V, t, scan)
__device__ __align__(256) float g_out1[(size_t)G * NQ * DHH];     // 2.1 MB fp32
__device__ __align__(256) float g_o2[(size_t)G * NN * DHH];       // 8 MB fp32 (out2)
__device__ __align__(256) float g_sinv[NN];

__device__ __align__(256) bf16 g_xh[(size_t)ROWS * DIMM];         // x planes
__device__ __align__(256) bf16 g_xl[(size_t)ROWS * DIMM];
__device__ __align__(256) bf16 g_Wqth[(size_t)QC * DIMM];         // W_qkv^T planes [2048][512]
__device__ __align__(256) bf16 g_Wqtl[(size_t)QC * DIMM];
__device__ __align__(256) bf16 g_Woth[(size_t)DIMM * 1024];       // W_out^T planes [512][1024]
__device__ __align__(256) bf16 g_Wotl[(size_t)DIMM * 1024];
__device__ __align__(256) bf16 g_qkh[(size_t)ROWS * 1024];        // Q/K planes (cols 0..1023)
__device__ __align__(256) bf16 g_qkl[(size_t)ROWS * 1024];
__device__ __align__(256) bf16 g_Vth[(size_t)G * DHH * NN];       // V^T planes [g][64][2048]
__device__ __align__(256) bf16 g_Vtl[(size_t)G * DHH * NN];
__device__ __align__(256) bf16 g_cath[(size_t)ROWS * 1024];       // cat planes
__device__ __align__(256) bf16 g_catl[(size_t)ROWS * 1024];

// flash split-j partials
__device__ __align__(256) float g_pO[(size_t)2 * G * FROWS * DHH];  // 5.2 MB
__device__ __align__(256) float g_pM[2 * G * FROWS];
__device__ __align__(256) float g_pL[2 * G * FROWS];

// ======================= portable PTX helpers =======================
__device__ __forceinline__ uint32_t smem_u32(const void* p) {
    uint32_t a;
    asm("{ .reg .u64 t; cvta.to.shared.u64 t, %1; cvt.u32.u64 %0, t; }" : "=r"(a) : "l"(p));
    return a;
}
__device__ __forceinline__ void ldsm_x4(uint32_t* f, uint32_t addr) {
    asm volatile("ldmatrix.sync.aligned.m8n8.x4.shared.b16 {%0,%1,%2,%3}, [%4];"
                 : "=r"(f[0]), "=r"(f[1]), "=r"(f[2]), "=r"(f[3]) : "r"(addr));
}
__device__ __forceinline__ void mma16(float* c, const uint32_t* a, const uint32_t* b) {
    asm volatile("mma.sync.aligned.m16n8k16.row.col.f32.bf16.bf16.f32 "
                 "{%0,%1,%2,%3}, {%4,%5,%6,%7}, {%8,%9}, {%0,%1,%2,%3};"
                 : "+f"(c[0]), "+f"(c[1]), "+f"(c[2]), "+f"(c[3])
                 : "r"(a[0]), "r"(a[1]), "r"(a[2]), "r"(a[3]), "r"(b[0]), "r"(b[1]));
}
#define CP_ASYNC_COMMIT() asm volatile("cp.async.commit_group;")
#define CP_ASYNC_WAIT(n)  asm volatile("cp.async.wait_group %0;" :: "n"(n))
#define CP_ASYNC16(dst, src) \
    asm volatile("cp.async.cg.shared.global [%0], [%1], 16;" :: "r"(dst), "l"(src))
#define CP_ASYNC16Z(dst, src, gz) \
    asm volatile("cp.async.cg.shared.global [%0], [%1], 16, %2;" :: "r"(dst), "l"(src), "r"(gz))

__device__ __forceinline__ void bsplit(float v, bf16& h, bf16& l) {
    h = __float2bfloat16(v);
    l = __float2bfloat16(v - __bfloat162float(h));
}
__device__ __forceinline__ uint32_t pack_bf(float lo, float hi) {
    bf162 t; t.x = __float2bfloat16(lo); t.y = __float2bfloat16(hi);
    return *(uint32_t*)&t;
}

// interleaved-line SMEM layout for BK=32 (64B rows): 2 rows per 128B line
__device__ __forceinline__ uint32_t tpos(int r, int ch) {
    return ((uint32_t)(r >> 1) << 7) |
           ((uint32_t)((((r & 1) << 2) | ch) ^ ((r >> 1) & 7)) << 4);
}
// full-line layout for 128B rows (64 bf16): chunk ch in 0..7
__device__ __forceinline__ uint32_t fpos(int r, int ch) {
    return ((uint32_t)r << 7) | ((uint32_t)(ch ^ (r & 7)) << 4);
}

#define STAGES 3

// =====================================================================
// bf16x3 mma.sync GEMM: C[M,N] = scale * A[M,K] @ B[N,K]^T (+bias)
// A/B as (hi, lo) bf16 planes, K-major.  CTA BM x BN, 8 warps (4m x 2n).
// MODE 0: plain (+bias, fp32 C).
// MODE 1: qkvt cols 512..2047 (col0 offset +512; planes for cg<1024, fp32 else)
// MODE 4: qkvt Q-part cols 0..511 for rows <640 per batch (planes only)
// =====================================================================
template<int BM, int BN, int MODE>
__global__ __launch_bounds__(256) void bmma_gemm(
    const bf16* __restrict__ Ah0, const bf16* __restrict__ Al0, int lda,
    const bf16* __restrict__ Bh0, const bf16* __restrict__ Bl0, int ldb,
    float* __restrict__ C0, int ldc,
    int M, int K, float scale, const float* __restrict__ bias)
{
    constexpr int MT     = BM / 64;
    constexpr int NTILES = BN / 16;
    constexpr int APL = BM * 64;
    constexpr int BPL = BN * 64;
    constexpr int STAGE = 2 * (APL + BPL);

    extern __shared__ __align__(1024) char smem[];
    uint32_t sbase = smem_u32(smem);

    int tid = threadIdx.x, wid = tid >> 5, lane = tid & 31;
    int row0, col0;
    if (MODE == 4) {
        row0 = (blockIdx.y / 5) * 2048 + (blockIdx.y % 5) * 128;
        col0 = blockIdx.x * BN;
    } else if (MODE == 1) {
        row0 = blockIdx.y * BM;
        col0 = 512 + blockIdx.x * BN;
    } else {
        row0 = blockIdx.y * BM;
        col0 = blockIdx.x * BN;
    }

    const bf16* Ah = Ah0; const bf16* Al = Al0;
    const bf16* Bh = Bh0; const bf16* Bl = Bl0;
    float* C = C0;

    auto load_stage = [&](int stage, int k0) {
        uint32_t sb = sbase + stage * STAGE;
#pragma unroll
        for (int i = 0; i < BM * 4 / 256; ++i) {
            int id = tid + i * 256;
            int r = id >> 2, ch = id & 3;
            uint32_t pos = tpos(r, ch);
            const bf16* sh = Ah + (size_t)(row0 + r) * lda + k0 + ch * 8;
            const bf16* sl = Al + (size_t)(row0 + r) * lda + k0 + ch * 8;
            uint32_t gz = (row0 + r < M) ? 16u : 0u;
            CP_ASYNC16Z(sb + pos, sh, gz);
            CP_ASYNC16Z(sb + APL + pos, sl, gz);
        }
#pragma unroll
        for (int i = 0; i < BN * 4 / 256; ++i) {
            int id = tid + i * 256;
            int r = id >> 2, ch = id & 3;
            uint32_t pos = tpos(r, ch);
            const bf16* sh = Bh + (size_t)(col0 + r) * ldb + k0 + ch * 8;
            const bf16* sl = Bl + (size_t)(col0 + r) * ldb + k0 + ch * 8;
            CP_ASYNC16(sb + 2 * APL + pos, sh);
            CP_ASYNC16(sb + 2 * APL + BPL + pos, sl);
        }
    };

    int NT = K >> 5;
#pragma unroll
    for (int s = 0; s < STAGES - 1; ++s) {
        if (s < NT) load_stage(s, s * 32);
        CP_ASYNC_COMMIT();
    }

    int wm = wid & 3, wn = wid >> 2;
    int mbase = wm * (BM / 4);
    int nbase = wn * (BN / 2);

    float acc[MT][NTILES][4];
#pragma unroll
    for (int mt = 0; mt < MT; ++mt)
#pragma unroll
        for (int nt = 0; nt < NTILES; ++nt)
#pragma unroll
            for (int j = 0; j < 4; ++j) acc[mt][nt][j] = 0.f;

    for (int t = 0; t < NT; ++t) {
        CP_ASYNC_WAIT(STAGES - 2);
        __syncthreads();
        if (t + STAGES - 1 < NT)
            load_stage((t + STAGES - 1) % STAGES, (t + STAGES - 1) * 32);
        CP_ASYNC_COMMIT();

        uint32_t sb = sbase + (t % STAGES) * STAGE;
#pragma unroll
        for (int kk = 0; kk < 2; ++kk) {
            uint32_t ah[MT][4], al[MT][4];
#pragma unroll
            for (int mt = 0; mt < MT; ++mt) {
                int r = mbase + mt * 16 + (lane & 15);
                int ch = kk * 2 + (lane >> 4);
                uint32_t pos = tpos(r, ch);
                ldsm_x4(ah[mt], sb + pos);
                ldsm_x4(al[mt], sb + APL + pos);
            }
            uint32_t bh[NTILES][2], bl[NTILES][2];
#pragma unroll
            for (int p = 0; p < NTILES / 2; ++p) {
                int r = nbase + p * 16 + ((lane >> 4) << 3) + (lane & 7);
                int ch = kk * 2 + ((lane >> 3) & 1);
                uint32_t pos = tpos(r, ch);
                uint32_t f[4];
                ldsm_x4(f, sb + 2 * APL + pos);
                bh[2 * p][0] = f[0]; bh[2 * p][1] = f[1];
                bh[2 * p + 1][0] = f[2]; bh[2 * p + 1][1] = f[3];
                ldsm_x4(f, sb + 2 * APL + BPL + pos);
                bl[2 * p][0] = f[0]; bl[2 * p][1] = f[1];
                bl[2 * p + 1][0] = f[2]; bl[2 * p + 1][1] = f[3];
            }
#pragma unroll
            for (int mt = 0; mt < MT; ++mt)
#pragma unroll
                for (int nt = 0; nt < NTILES; ++nt) {
                    mma16(acc[mt][nt], ah[mt], bh[nt]);
                    mma16(acc[mt][nt], ah[mt], bl[nt]);
                    mma16(acc[mt][nt], al[mt], bh[nt]);
                }
        }
    }
    CP_ASYNC_WAIT(0);

    int cr = lane >> 2, cc = (lane & 3) * 2;
#pragma unroll
    for (int mt = 0; mt < MT; ++mt) {
        int rgb = row0 + mbase + mt * 16 + cr;
#pragma unroll
        for (int nt = 0; nt < NTILES; ++nt) {
            int cg = col0 + nbase + nt * 8 + cc;
            float2 b2 = make_float2(0.f, 0.f);
            if (MODE == 0 && bias) b2 = *(const float2*)(bias + cg);
#pragma unroll
            for (int half = 0; half < 2; ++half) {
                int rg = rgb + half * 8;
                if (rg < M) {
                    float vx = acc[mt][nt][half * 2] * scale + b2.x;
                    float vy = acc[mt][nt][half * 2 + 1] * scale + b2.y;
                    bool wplane = (MODE == 1 || MODE == 4) && cg < 1024;
                    bool wf32   = (MODE == 0) || (MODE == 1 && cg >= 1024);
                    if (wf32)
                        *(float2*)(C + (size_t)rg * ldc + cg) = make_float2(vx, vy);
                    if (wplane) {
                        bf16 hx, lx, hy, ly;
                        bsplit(vx, hx, lx); bsplit(vy, hy, ly);
                        bf162 hh; hh.x = hx; hh.y = hy;
                        bf162 ll; ll.x = lx; ll.y = ly;
                        *(bf162*)&g_qkh[(size_t)rg * 1024 + cg] = hh;
                        *(bf162*)&g_qkl[(size_t)rg * 1024 + cg] = ll;
                    }
                }
            }
        }
    }
}

// =====================================================================
// Fused flash attention: S = 0.125 * Q K^T, online softmax, O = P V.
// grid (2 splits, 5 mtiles, 16 g), 8 warps.  BM=128 rows, j-tiles of 64.
// Each warp owns 16 rows x full 64-col j-tile (no cross-warp softmax).
// Writes unnormalized O + (m, l) partials per split.
// =====================================================================
__global__ __launch_bounds__(256) void flash_kernel()
{
    constexpr int JT = 16;                 // j-tiles per split (16*64 = 1024)
    extern __shared__ __align__(1024) char smem[];
    uint32_t sb = smem_u32(smem);
    const uint32_t sQh = sb, sQl = sb + 16384;   // 128 x 64 bf16 planes

    int split = blockIdx.x, mtile = blockIdx.y, g = blockIdx.z;
    int b = g >> 3, h = g & 7;
    int row0 = mtile * 128;
    int tid = threadIdx.x, wid = tid >> 5, lane = tid & 31;

    const bf16* Qh = g_qkh + (size_t)b * 2048 * 1024 + h * 64;
    const bf16* Ql = g_qkl + (size_t)b * 2048 * 1024 + h * 64;
    const bf16* Kh = Qh + 512;
    const bf16* Kl = Ql + 512;
    const bf16* Vh = g_Vth + (size_t)g * DHH * NN;
    const bf16* Vl = g_Vtl + (size_t)g * DHH * NN;

    // ---- Q tile load (guarded at 513 rows) ----
#pragma unroll
    for (int i = 0; i < 4; ++i) {
        int id = tid + i * 256;            // 0..1023: 128 rows x 8 chunks
        int r = id >> 3, ch = id & 7;
        uint32_t pos = fpos(r, ch);
        uint32_t gz = (row0 + r < NQ) ? 16u : 0u;
        CP_ASYNC16Z(sQh + pos, Qh + (size_t)(row0 + r) * 1024 + ch * 8, gz);
        CP_ASYNC16Z(sQl + pos, Ql + (size_t)(row0 + r) * 1024 + ch * 8, gz);
    }
    CP_ASYNC_COMMIT();

    int j0 = split * 1024;
    auto load_kv = [&](int stage, int jt) {
        uint32_t kb = sb + 32768 + stage * 32768;
        int jb = j0 + jt * 64;
#pragma unroll
        for (int i = 0; i < 2; ++i) {
            int id = tid + i * 256;        // 0..511: 64 rows x 8 chunks
            int r = id >> 3, ch = id & 7;
            uint32_t pos = fpos(r, ch);
            CP_ASYNC16(kb + pos,         Kh + (size_t)(jb + r) * 1024 + ch * 8);
            CP_ASYNC16(kb + 8192 + pos,  Kl + (size_t)(jb + r) * 1024 + ch * 8);
            CP_ASYNC16(kb + 16384 + pos, Vh + (size_t)r * NN + jb + ch * 8);
            CP_ASYNC16(kb + 24576 + pos, Vl + (size_t)r * NN + jb + ch * 8);
        }
    };
    load_kv(0, 0);
    CP_ASYNC_COMMIT();
    CP_ASYNC_WAIT(0);
    __syncthreads();

    // ---- Q fragments (held for whole loop) ----
    uint32_t qh[4][4], ql[4][4];
#pragma unroll
    for (int kk = 0; kk < 4; ++kk) {
        int r = wid * 16 + (lane & 15);
        uint32_t pos = fpos(r, 2 * kk + (lane >> 4));
        ldsm_x4(qh[kk], sQh + pos);
        ldsm_x4(ql[kk], sQl + pos);
    }

    float mr[2] = {-1e30f, -1e30f};
    float lr[2] = {0.f, 0.f};
    float oacc[8][4];
#pragma unroll
    for (int nt = 0; nt < 8; ++nt)
#pragma unroll
        for (int j = 0; j < 4; ++j) oacc[nt][j] = 0.f;

    for (int t = 0; t < JT; ++t) {
        if (t + 1 < JT) load_kv((t + 1) & 1, t + 1);
        CP_ASYNC_COMMIT();

        uint32_t kb = sb + 32768 + (t & 1) * 32768;

        // ---- S = Q K^T (bf16x3) ----
        float sacc[8][4];
#pragma unroll
        for (int nt = 0; nt < 8; ++nt)
#pragma unroll
            for (int j = 0; j < 4; ++j) sacc[nt][j] = 0.f;
#pragma unroll
        for (int kk = 0; kk < 4; ++kk) {
            uint32_t bh[8][2], bl[8][2];
#pragma unroll
            for (int p = 0; p < 4; ++p) {
                int r = p * 16 + ((lane >> 4) << 3) + (lane & 7);
                uint32_t pos = fpos(r, 2 * kk + ((lane >> 3) & 1));
                uint32_t f[4];
                ldsm_x4(f, kb + pos);
                bh[2 * p][0] = f[0]; bh[2 * p][1] = f[1];
                bh[2 * p + 1][0] = f[2]; bh[2 * p + 1][1] = f[3];
                ldsm_x4(f, kb + 8192 + pos);
                bl[2 * p][0] = f[0]; bl[2 * p][1] = f[1];
                bl[2 * p + 1][0] = f[2]; bl[2 * p + 1][1] = f[3];
            }
#pragma unroll
            for (int nt = 0; nt < 8; ++nt) {
                mma16(sacc[nt], qh[kk], bh[nt]);
                mma16(sacc[nt], qh[kk], bl[nt]);
                mma16(sacc[nt], ql[kk], bh[nt]);
            }
        }

        // ---- scale + online softmax (rows spread over quads) ----
#pragma unroll
        for (int nt = 0; nt < 8; ++nt)
#pragma unroll
            for (int j = 0; j < 4; ++j) sacc[nt][j] *= 0.125f;

#pragma unroll
        for (int hr = 0; hr < 2; ++hr) {
            float mx = -1e30f;
#pragma unroll
            for (int nt = 0; nt < 8; ++nt)
                mx = fmaxf(mx, fmaxf(sacc[nt][hr * 2], sacc[nt][hr * 2 + 1]));
            mx = fmaxf(mx, __shfl_xor_sync(0xffffffffu, mx, 1));
            mx = fmaxf(mx, __shfl_xor_sync(0xffffffffu, mx, 2));
            float mnew = fmaxf(mr[hr], mx);
            float alpha = __expf(mr[hr] - mnew);
            mr[hr] = mnew;
            float rs = 0.f;
#pragma unroll
            for (int nt = 0; nt < 8; ++nt) {
                float p0 = __expf(sacc[nt][hr * 2] - mnew);
                float p1 = __expf(sacc[nt][hr * 2 + 1] - mnew);
                sacc[nt][hr * 2] = p0; sacc[nt][hr * 2 + 1] = p1;
                rs += p0 + p1;
            }
            rs += __shfl_xor_sync(0xffffffffu, rs, 1);
            rs += __shfl_xor_sync(0xffffffffu, rs, 2);
            lr[hr] = lr[hr] * alpha + rs;
#pragma unroll
            for (int nt = 0; nt < 8; ++nt) {
                oacc[nt][hr * 2]     *= alpha;
                oacc[nt][hr * 2 + 1] *= alpha;
            }
        }

        // ---- O += P V (bf16x3; P acc-frags -> A-frags in-register) ----
#pragma unroll
        for (int kk = 0; kk < 4; ++kk) {
            uint32_t pa_h[4], pa_l[4];
            {
                float x0 = sacc[2 * kk][0],     x1 = sacc[2 * kk][1];
                float x2 = sacc[2 * kk][2],     x3 = sacc[2 * kk][3];
                float y0 = sacc[2 * kk + 1][0], y1 = sacc[2 * kk + 1][1];
                float y2 = sacc[2 * kk + 1][2], y3 = sacc[2 * kk + 1][3];
                pa_h[0] = pack_bf(x0, x1);
                pa_h[1] = pack_bf(x2, x3);
                pa_h[2] = pack_bf(y0, y1);
                pa_h[3] = pack_bf(y2, y3);
                bf162* ph = (bf162*)pa_h;
                pa_l[0] = pack_bf(x0 - __bfloat162float(ph[0].x), x1 - __bfloat162float(ph[0].y));
                pa_l[1] = pack_bf(x2 - __bfloat162float(ph[1].x), x3 - __bfloat162float(ph[1].y));
                pa_l[2] = pack_bf(y0 - __bfloat162float(ph[2].x), y1 - __bfloat162float(ph[2].y));
                pa_l[3] = pack_bf(y2 - __bfloat162float(ph[3].x), y3 - __bfloat162float(ph[3].y));
            }
            uint32_t vh[8][2], vl[8][2];
#pragma unroll
            for (int p = 0; p < 4; ++p) {
                int r = p * 16 + ((lane >> 4) << 3) + (lane & 7);
                uint32_t pos = fpos(r, 2 * kk + ((lane >> 3) & 1));
                uint32_t f[4];
                ldsm_x4(f, kb + 16384 + pos);
                vh[2 * p][0] = f[0]; vh[2 * p][1] = f[1];
                vh[2 * p + 1][0] = f[2]; vh[2 * p + 1][1] = f[3];
                ldsm_x4(f, kb + 24576 + pos);
                vl[2 * p][0] = f[0]; vl[2 * p][1] = f[1];
                vl[2 * p + 1][0] = f[2]; vl[2 * p + 1][1] = f[3];
            }
#pragma unroll
            for (int nt = 0; nt < 8; ++nt) {
                mma16(oacc[nt], pa_h, vh[nt]);
                mma16(oacc[nt], pa_h, vl[nt]);
                mma16(oacc[nt], pa_l, vh[nt]);
            }
        }

        CP_ASYNC_WAIT(0);
        __syncthreads();
    }

    // ---- store partials (unnormalized O, m, l) ----
    int cr = lane >> 2, cc = (lane & 3) * 2;
#pragma unroll
    for (int hr = 0; hr < 2; ++hr) {
        int row = row0 + wid * 16 + cr + hr * 8;
        size_t base = (((size_t)split * G + g) * FROWS + row) * DHH;
#pragma unroll
        for (int nt = 0; nt < 8; ++nt) {
            *(float2*)&g_pO[base + nt * 8 + cc] =
                make_float2(oacc[nt][hr * 2], oacc[nt][hr * 2 + 1]);
        }
        if ((lane & 3) == 0) {
            size_t mi = ((size_t)split * G + g) * FROWS + row;
            g_pM[mi] = mr[hr];
            g_pL[mi] = lr[hr];
        }
    }
}

// =====================================================================
// Combine split-j partials -> g_out1 (normalized).
// =====================================================================
__global__ void combine_kernel()
{
    int idx = blockIdx.x * 256 + threadIdx.x;     // over G*NQ*32 col-pairs
    if (idx >= G * NQ * 32) return;
    int c = (idx & 31) * 2;
    int rem = idx >> 5;
    int row = rem % NQ, g = rem / NQ;
    size_t m0i = ((size_t)0 * G + g) * FROWS + row;
    size_t m1i = ((size_t)1 * G + g) * FROWS + row;
    float m0 = g_pM[m0i], l0 = g_pL[m0i];
    float m1 = g_pM[m1i], l1 = g_pL[m1i];
    float M = fmaxf(m0, m1);
    float w0 = __expf(m0 - M), w1 = __expf(m1 - M);
    float inv = 1.f / (w0 * l0 + w1 * l1);
    float2 o0 = *(const float2*)&g_pO[(m0i) * DHH + c];
    float2 o1 = *(const float2*)&g_pO[(m1i) * DHH + c];
    float2 o = make_float2((w0 * o0.x + w1 * o1.x) * inv,
                           (w0 * o0.y + w1 * o1.y) * inv);
    *(float2*)&g_out1[((size_t)g * NQ + row) * DHH + c] = o;
}

// =====================================================================
// x splitter: fp32 -> (hi, lo) bf16 planes
// =====================================================================
__global__ void split_x_kernel(const float* __restrict__ X)
{
    int i = blockIdx.x * 256 + threadIdx.x;
    float4 v = ((const float4*)X)[i];
    bf16 h0, l0, h1, l1, h2, l2, h3, l3;
    bsplit(v.x, h0, l0); bsplit(v.y, h1, l1);
    bsplit(v.z, h2, l2); bsplit(v.w, h3, l3);
    bf162 a, b;
    a.x = h0; a.y = h1; b.x = h2; b.y = h3;
    ((bf162*)g_xh)[i * 2] = a; ((bf162*)g_xh)[i * 2 + 1] = b;
    a.x = l0; a.y = l1; b.x = l2; b.y = l3;
    ((bf162*)g_xl)[i * 2] = a; ((bf162*)g_xl)[i * 2 + 1] = b;
}

// =====================================================================
// Transpose + split: D[c][r] planes = split(S[r][c]).
// =====================================================================
__global__ void transpose_split(const float* __restrict__ S,
                                bf16* __restrict__ Dh, bf16* __restrict__ Dl,
                                int R, int C)
{
    __shared__ float t[32][33];
    int bx = blockIdx.x * 32, by = blockIdx.y * 32;
#pragma unroll
    for (int i = 0; i < 32; i += 8)
        t[threadIdx.y + i][threadIdx.x] =
            S[(size_t)(by + threadIdx.y + i) * C + bx + threadIdx.x];
    __syncthreads();
#pragma unroll
    for (int i = 0; i < 32; i += 8) {
        float v = t[threadIdx.x][threadIdx.y + i];
        bf16 h, l; bsplit(v, h, l);
        size_t o = (size_t)(bx + threadIdx.y + i) * R + by + threadIdx.x;
        Dh[o] = h; Dl[o] = l;
    }
}

// =====================================================================
// V^T planes: Vt[g][c][j] = split(qkvt V quarter).  grid (64, 2, 16).
// =====================================================================
__global__ void vtrans_split()
{
    int g = blockIdx.z, b = g >> 3, h = g & 7;
    int j0 = blockIdx.x * 32, c0 = blockIdx.y * 32;
    __shared__ float t[32][33];
    const float* src = g_qkvt + (size_t)b * NN * QC + 1024 + h * DHH;
#pragma unroll
    for (int i = 0; i < 32; i += 8)
        t[threadIdx.y + i][threadIdx.x] =
            src[(size_t)(j0 + threadIdx.y + i) * QC + c0 + threadIdx.x];
    __syncthreads();
#pragma unroll
    for (int i = 0; i < 32; i += 8) {
        float v = t[threadIdx.x][threadIdx.y + i];
        bf16 hh, ll; bsplit(v, hh, ll);
        size_t o = (size_t)g * DHH * NN + (size_t)(c0 + threadIdx.y + i) * NN + j0 + threadIdx.x;
        g_Vth[o] = hh; g_Vtl[o] = ll;
    }
}

// =====================================================================
__global__ void sinv_kernel()
{
    int j = blockIdx.x * 256 + threadIdx.x;
    if (j < NN) {
        const float r = RDEC;
        float s = (1.0f - powf(r, (float)(j + 1)) + r - powf(r, (float)(NN - j)))
                  / (1.0f - r);
        g_sinv[j] = 1.0f / s;
    }
}

// =====================================================================
// out2 via decay scan, 96-halo chunks -> g_o2[g][j][c] fp32.
// =====================================================================
__global__ __launch_bounds__(64) void scan_kernel()
{
    int g = blockIdx.x, chunk = blockIdx.y;
    int b = g >> 3, h = g & 7;
    int c = threadIdx.x;
    const float r = RDEC;
    const float* T = g_qkvt + (size_t)b * NN * QC + 1536 + h * DHH + c;
    float* O = g_o2 + (size_t)g * NN * DHH + c;
    int i0 = chunk * 256;

    int js = i0 - 96; if (js < 0) js = 0;
    float f = 0.f;
    for (int j = js; j < i0 + 256; j++) {
        float u = T[(size_t)j * QC] * g_sinv[j];
        f = f * r + u;
        if (j >= i0) O[(size_t)j * DHH] = f - u;
    }
    int je = i0 + 255 + 96; if (je > NN - 1) je = NN - 1;
    float gg = 0.f;
    for (int j = je; j >= i0; j--) {
        float u = T[(size_t)j * QC] * g_sinv[j];
        gg = gg * r + u;
        if (j < i0 + 256) O[(size_t)j * DHH] += gg;
    }
}

// =====================================================================
// Assemble cat planes: cols h*128+[0,64) from out1 (i%513), +[64,128) from o2.
// =====================================================================
__global__ void expand2_kernel()
{
    int idx = blockIdx.x * 256 + threadIdx.x;      // < 4096*1024
    int row = idx >> 10, q = idx & 1023;
    int b = row >> 11, i = row & 2047;
    int h = q >> 7, c = q & 127;
    int g = b * 8 + h;
    float v;
    if (c < 64)
        v = g_out1[((size_t)g * NQ + (i % 513)) * DHH + c];
    else
        v = g_o2[((size_t)g * NN + i) * DHH + (c - 64)];
    bf16 hh, ll; bsplit(v, hh, ll);
    g_cath[idx] = hh; g_catl[idx] = ll;
}

// =====================================================================
#define SM_QKV (STAGES * 2 * (128 * 64 + 128 * 64))   // 98304
#define SM_OUT (STAGES * 2 * (128 * 64 + 64 * 64))    // 73728
#define SM_FLASH (32768 + 2 * 32768)                  // 98304

extern "C" void kernel_launch(void* const* d_in, const int* in_sizes, int n_in,
                              void* d_out, int out_size)
{
    const float* x     = (const float*)d_in[0];   // [2,2048,512]
    const float* W_qkv = (const float*)d_in[1];   // [512,2048]
    const float* W_out = (const float*)d_in[2];   // [1024,512]
    const float* b_out = (const float*)d_in[3];   // [512]
    float* out = (float*)d_out;                   // [2,2048,512]

    float *p_qkvt;
    bf16 *p_xh, *p_xl, *p_Wqth, *p_Wqtl, *p_Woth, *p_Wotl, *p_cath, *p_catl;
    cudaGetSymbolAddress((void**)&p_qkvt, g_qkvt);
    cudaGetSymbolAddress((void**)&p_xh,   g_xh);
    cudaGetSymbolAddress((void**)&p_xl,   g_xl);
    cudaGetSymbolAddress((void**)&p_Wqth, g_Wqth);
    cudaGetSymbolAddress((void**)&p_Wqtl, g_Wqtl);
    cudaGetSymbolAddress((void**)&p_Woth, g_Woth);
    cudaGetSymbolAddress((void**)&p_Wotl, g_Wotl);
    cudaGetSymbolAddress((void**)&p_cath, g_cath);
    cudaGetSymbolAddress((void**)&p_catl, g_catl);

    static bool attr_done = false;
    if (!attr_done) {
        cudaFuncSetAttribute(bmma_gemm<128, 128, 1>,
                             cudaFuncAttributeMaxDynamicSharedMemorySize, SM_QKV);
        cudaFuncSetAttribute(bmma_gemm<128, 128, 4>,
                             cudaFuncAttributeMaxDynamicSharedMemorySize, SM_QKV);
        cudaFuncSetAttribute(bmma_gemm<128, 64, 0>,
                             cudaFuncAttributeMaxDynamicSharedMemorySize, SM_OUT);
        cudaFuncSetAttribute(flash_kernel,
                             cudaFuncAttributeMaxDynamicSharedMemorySize, SM_FLASH);
        attr_done = true;
    }

    // 0) input/weight plane production
    split_x_kernel<<<(ROWS * DIMM / 4) / 256, 256>>>(x);
    transpose_split<<<dim3(64, 16), dim3(32, 8)>>>(W_qkv, p_Wqth, p_Wqtl, 512, 2048);
    transpose_split<<<dim3(16, 32), dim3(32, 8)>>>(W_out, p_Woth, p_Wotl, 1024, 512);
    sinv_kernel<<<8, 256>>>();

    // 1a) Q quarter (cols 0..511) for rows < 640 per batch: planes only
    bmma_gemm<128, 128, 4><<<dim3(4, 10, 1), 256, SM_QKV>>>(
        p_xh, p_xl, DIMM, p_Wqth, p_Wqtl, DIMM, p_qkvt, QC, ROWS, DIMM, 1.0f, nullptr);

    // 1b) K/V/t quarters (cols 512..2047), all rows: K planes + V/t fp32
    bmma_gemm<128, 128, 1><<<dim3(12, 32, 1), 256, SM_QKV>>>(
        p_xh, p_xl, DIMM, p_Wqth, p_Wqtl, DIMM, p_qkvt, QC, ROWS, DIMM, 1.0f, nullptr);

    // 1c) V^T planes
    vtrans_split<<<dim3(64, 2, G), dim3(32, 8)>>>();

    // 2) fused QK + softmax + PV (split-j x2), then combine
    flash_kernel<<<dim3(2, 5, G), 256, SM_FLASH>>>();
    combine_kernel<<<(G * NQ * 32 + 255) / 256, 256>>>();

    // 3) out2 scan + cat plane assembly
    scan_kernel<<<dim3(G, NN / 256), 64>>>();
    expand2_kernel<<<(ROWS * 1024) / 256, 256>>>();

    // 4) out = cat @ W_out + b_out : M=4096, N=512, K=1024
    bmma_gemm<128, 64, 0><<<dim3(8, 32, 1), 256, SM_OUT>>>(
        p_cath, p_catl, 1024, p_Woth, p_Wotl, 1024, out, DIMM, ROWS, 1024, 1.0f, b_out);
}

// round 11
// speedup vs baseline: 2.4790x; 1.1850x over previous
#include <cuda_runtime.h>
#include <cuda_bf16.h>
#include <cstdint>
#include <cstddef>

// Problem constants
#define BB    2
#define NN    2048
#define DIMM  512
#define HH    8
#define DHH   64
#define NQ    513          // distinct effective query rows per head (q[i] = q[i % 513])
#define G     16           // B*H
#define ROWS  4096         // B*N
#define FROWS 640          // padded NQ for flash partials (5 * 128)

// r = exp(-1/e)
#define RDEC 0.69220062755534637f

typedef __nv_bfloat16  bf16;
typedef __nv_bfloat162 bf162;

// ---------------- scratch (static device arrays; no allocation) ----------------
__device__ __align__(256) float g_t[(size_t)ROWS * 512];          // t quarter fp32
__device__ __align__(256) float g_O1[(size_t)1152 * 512];         // O1proj fp32

__device__ __align__(256) bf16 g_xh[(size_t)ROWS * DIMM];         // x planes
__device__ __align__(256) bf16 g_xl[(size_t)ROWS * DIMM];
__device__ __align__(256) bf16 g_Wqth[(size_t)2048 * DIMM];       // W_qkv^T planes
__device__ __align__(256) bf16 g_Wqtl[(size_t)2048 * DIMM];
__device__ __align__(256) bf16 g_Wo1th[(size_t)512 * 512];        // W_out^T (out1 rows) planes
__device__ __align__(256) bf16 g_Wo1tl[(size_t)512 * 512];
__device__ __align__(256) bf16 g_Wo2th[(size_t)512 * 512];        // W_out^T (out2 rows) planes
__device__ __align__(256) bf16 g_Wo2tl[(size_t)512 * 512];
__device__ __align__(256) bf16 g_qkh[(size_t)ROWS * 1024];        // Q/K planes (cols 0..1023)
__device__ __align__(256) bf16 g_qkl[(size_t)ROWS * 1024];
__device__ __align__(256) bf16 g_vh[(size_t)ROWS * 512];          // V planes [row][h*64+c]
__device__ __align__(256) bf16 g_vl[(size_t)ROWS * 512];
__device__ __align__(256) bf16 g_o1h[(size_t)1152 * 512];         // combine out planes [b*513+i][h*64+c]
__device__ __align__(256) bf16 g_o1l[(size_t)1152 * 512];
__device__ __align__(256) bf16 g_o2h[(size_t)ROWS * 512];         // scan out planes
__device__ __align__(256) bf16 g_o2l[(size_t)ROWS * 512];

// flash split-j partials
__device__ __align__(256) float g_pO[(size_t)2 * G * FROWS * DHH];
__device__ __align__(256) float g_pM[2 * G * FROWS];
__device__ __align__(256) float g_pL[2 * G * FROWS];

// ======================= portable PTX helpers =======================
__device__ __forceinline__ uint32_t smem_u32(const void* p) {
    uint32_t a;
    asm("{ .reg .u64 t; cvta.to.shared.u64 t, %1; cvt.u32.u64 %0, t; }" : "=r"(a) : "l"(p));
    return a;
}
__device__ __forceinline__ void ldsm_x4(uint32_t* f, uint32_t addr) {
    asm volatile("ldmatrix.sync.aligned.m8n8.x4.shared.b16 {%0,%1,%2,%3}, [%4];"
                 : "=r"(f[0]), "=r"(f[1]), "=r"(f[2]), "=r"(f[3]) : "r"(addr));
}
__device__ __forceinline__ void ldsm_x4_t(uint32_t* f, uint32_t addr) {
    asm volatile("ldmatrix.sync.aligned.m8n8.x4.trans.shared.b16 {%0,%1,%2,%3}, [%4];"
                 : "=r"(f[0]), "=r"(f[1]), "=r"(f[2]), "=r"(f[3]) : "r"(addr));
}
__device__ __forceinline__ void mma16(float* c, const uint32_t* a, const uint32_t* b) {
    asm volatile("mma.sync.aligned.m16n8k16.row.col.f32.bf16.bf16.f32 "
                 "{%0,%1,%2,%3}, {%4,%5,%6,%7}, {%8,%9}, {%0,%1,%2,%3};"
                 : "+f"(c[0]), "+f"(c[1]), "+f"(c[2]), "+f"(c[3])
                 : "r"(a[0]), "r"(a[1]), "r"(a[2]), "r"(a[3]), "r"(b[0]), "r"(b[1]));
}
#define CP_ASYNC_COMMIT() asm volatile("cp.async.commit_group;")
#define CP_ASYNC_WAIT(n)  asm volatile("cp.async.wait_group %0;" :: "n"(n))
#define CP_ASYNC16(dst, src) \
    asm volatile("cp.async.cg.shared.global [%0], [%1], 16;" :: "r"(dst), "l"(src))
#define CP_ASYNC16Z(dst, src, gz) \
    asm volatile("cp.async.cg.shared.global [%0], [%1], 16, %2;" :: "r"(dst), "l"(src), "r"(gz))

__device__ __forceinline__ void bsplit(float v, bf16& h, bf16& l) {
    h = __float2bfloat16(v);
    l = __float2bfloat16(v - __bfloat162float(h));
}
__device__ __forceinline__ uint32_t pack_bf(float lo, float hi) {
    bf162 t; t.x = __float2bfloat16(lo); t.y = __float2bfloat16(hi);
    return *(uint32_t*)&t;
}

// interleaved-line SMEM layout for BK=32 (64B rows): 2 rows per 128B line
__device__ __forceinline__ uint32_t tpos(int r, int ch) {
    return ((uint32_t)(r >> 1) << 7) |
           ((uint32_t)((((r & 1) << 2) | ch) ^ ((r >> 1) & 7)) << 4);
}
// full-line layout for 128B rows (64 bf16): chunk ch in 0..7
__device__ __forceinline__ uint32_t fpos(int r, int ch) {
    return ((uint32_t)r << 7) | ((uint32_t)(ch ^ (r & 7)) << 4);
}

#define STAGES 3

// =====================================================================
// bf16x3 mma.sync GEMM: C[M,N] = A[M,K] @ B[N,K]^T (+extras)
// A/B as (hi, lo) bf16 planes, K-major.  CTA BM x BN, 8 warps (4m x 2n).
// MODE 0: plain fp32 C (+bias if given).
// MODE 1: qkvt producer. col0 = bx*128 over 0..2047; Q region (col0<512)
//         only for rows%2048 < 640.  Epilogue: cg<1024 -> qk planes;
//         cg<1536 -> V planes; else t fp32.
// MODE 5: final out.  C = acc + bias[cg] + O1proj[b*513 + i%513][cg].
// =====================================================================
template<int BM, int BN, int MODE>
__global__ __launch_bounds__(256) void bmma_gemm(
    const bf16* __restrict__ Ah, const bf16* __restrict__ Al, int lda,
    const bf16* __restrict__ Bh, const bf16* __restrict__ Bl, int ldb,
    float* __restrict__ C, int ldc,
    int M, int K, const float* __restrict__ bias)
{
    constexpr int MT     = BM / 64;
    constexpr int NTILES = BN / 16;
    constexpr int APL = BM * 64;
    constexpr int BPL = BN * 64;
    constexpr int STAGE = 2 * (APL + BPL);

    int row0 = blockIdx.y * BM;
    int col0 = blockIdx.x * BN;
    if (MODE == 1) {
        if (col0 < 512 && (row0 & 2047) >= FROWS) return;   // Q region: 640 rows/batch
    }

    extern __shared__ __align__(1024) char smem[];
    uint32_t sbase = smem_u32(smem);
    int tid = threadIdx.x, wid = tid >> 5, lane = tid & 31;

    auto load_stage = [&](int stage, int k0) {
        uint32_t sb = sbase + stage * STAGE;
#pragma unroll
        for (int i = 0; i < BM * 4 / 256; ++i) {
            int id = tid + i * 256;
            int r = id >> 2, ch = id & 3;
            uint32_t pos = tpos(r, ch);
            const bf16* sh = Ah + (size_t)(row0 + r) * lda + k0 + ch * 8;
            const bf16* sl = Al + (size_t)(row0 + r) * lda + k0 + ch * 8;
            uint32_t gz = (row0 + r < M) ? 16u : 0u;
            CP_ASYNC16Z(sb + pos, sh, gz);
            CP_ASYNC16Z(sb + APL + pos, sl, gz);
        }
#pragma unroll
        for (int i = 0; i < BN * 4 / 256; ++i) {
            int id = tid + i * 256;
            int r = id >> 2, ch = id & 3;
            uint32_t pos = tpos(r, ch);
            const bf16* sh = Bh + (size_t)(col0 + r) * ldb + k0 + ch * 8;
            const bf16* sl = Bl + (size_t)(col0 + r) * ldb + k0 + ch * 8;
            CP_ASYNC16(sb + 2 * APL + pos, sh);
            CP_ASYNC16(sb + 2 * APL + BPL + pos, sl);
        }
    };

    int NT = K >> 5;
#pragma unroll
    for (int s = 0; s < STAGES - 1; ++s) {
        if (s < NT) load_stage(s, s * 32);
        CP_ASYNC_COMMIT();
    }

    int wm = wid & 3, wn = wid >> 2;
    int mbase = wm * (BM / 4);
    int nbase = wn * (BN / 2);

    float acc[MT][NTILES][4];
#pragma unroll
    for (int mt = 0; mt < MT; ++mt)
#pragma unroll
        for (int nt = 0; nt < NTILES; ++nt)
#pragma unroll
            for (int j = 0; j < 4; ++j) acc[mt][nt][j] = 0.f;

    for (int t = 0; t < NT; ++t) {
        CP_ASYNC_WAIT(STAGES - 2);
        __syncthreads();
        if (t + STAGES - 1 < NT)
            load_stage((t + STAGES - 1) % STAGES, (t + STAGES - 1) * 32);
        CP_ASYNC_COMMIT();

        uint32_t sb = sbase + (t % STAGES) * STAGE;
#pragma unroll
        for (int kk = 0; kk < 2; ++kk) {
            uint32_t ah[MT][4], al[MT][4];
#pragma unroll
            for (int mt = 0; mt < MT; ++mt) {
                int r = mbase + mt * 16 + (lane & 15);
                int ch = kk * 2 + (lane >> 4);
                uint32_t pos = tpos(r, ch);
                ldsm_x4(ah[mt], sb + pos);
                ldsm_x4(al[mt], sb + APL + pos);
            }
            uint32_t bh[NTILES][2], bl[NTILES][2];
#pragma unroll
            for (int p = 0; p < NTILES / 2; ++p) {
                int r = nbase + p * 16 + ((lane >> 4) << 3) + (lane & 7);
                int ch = kk * 2 + ((lane >> 3) & 1);
                uint32_t pos = tpos(r, ch);
                uint32_t f[4];
                ldsm_x4(f, sb + 2 * APL + pos);
                bh[2 * p][0] = f[0]; bh[2 * p][1] = f[1];
                bh[2 * p + 1][0] = f[2]; bh[2 * p + 1][1] = f[3];
                ldsm_x4(f, sb + 2 * APL + BPL + pos);
                bl[2 * p][0] = f[0]; bl[2 * p][1] = f[1];
                bl[2 * p + 1][0] = f[2]; bl[2 * p + 1][1] = f[3];
            }
#pragma unroll
            for (int mt = 0; mt < MT; ++mt)
#pragma unroll
                for (int nt = 0; nt < NTILES; ++nt) {
                    mma16(acc[mt][nt], ah[mt], bh[nt]);
                    mma16(acc[mt][nt], ah[mt], bl[nt]);
                    mma16(acc[mt][nt], al[mt], bh[nt]);
                }
        }
    }
    CP_ASYNC_WAIT(0);

    int cr = lane >> 2, cc = (lane & 3) * 2;
#pragma unroll
    for (int mt = 0; mt < MT; ++mt) {
        int rgb = row0 + mbase + mt * 16 + cr;
#pragma unroll
        for (int nt = 0; nt < NTILES; ++nt) {
            int cg = col0 + nbase + nt * 8 + cc;
#pragma unroll
            for (int half = 0; half < 2; ++half) {
                int rg = rgb + half * 8;
                if (rg >= M) continue;
                float vx = acc[mt][nt][half * 2];
                float vy = acc[mt][nt][half * 2 + 1];
                if (MODE == 0) {
                    if (bias) {
                        float2 b2 = *(const float2*)(bias + cg);
                        vx += b2.x; vy += b2.y;
                    }
                    *(float2*)(C + (size_t)rg * ldc + cg) = make_float2(vx, vy);
                } else if (MODE == 5) {
                    float2 b2 = *(const float2*)(bias + cg);
                    int b = rg >> 11, i = rg & 2047;
                    int i513 = i % 513;
                    float2 o1 = *(const float2*)&g_O1[(size_t)(b * 513 + i513) * 512 + cg];
                    *(float2*)(C + (size_t)rg * ldc + cg) =
                        make_float2(vx + b2.x + o1.x, vy + b2.y + o1.y);
                } else { // MODE 1
                    if (cg < 1024) {
                        bf16 hx, lx, hy, ly;
                        bsplit(vx, hx, lx); bsplit(vy, hy, ly);
                        bf162 hh; hh.x = hx; hh.y = hy;
                        bf162 ll; ll.x = lx; ll.y = ly;
                        *(bf162*)&g_qkh[(size_t)rg * 1024 + cg] = hh;
                        *(bf162*)&g_qkl[(size_t)rg * 1024 + cg] = ll;
                    } else if (cg < 1536) {
                        bf16 hx, lx, hy, ly;
                        bsplit(vx, hx, lx); bsplit(vy, hy, ly);
                        bf162 hh; hh.x = hx; hh.y = hy;
                        bf162 ll; ll.x = lx; ll.y = ly;
                        *(bf162*)&g_vh[(size_t)rg * 512 + cg - 1024] = hh;
                        *(bf162*)&g_vl[(size_t)rg * 512 + cg - 1024] = ll;
                    } else {
                        *(float2*)&g_t[(size_t)rg * 512 + cg - 1536] = make_float2(vx, vy);
                    }
                }
            }
        }
    }
}

// =====================================================================
// Fused flash attention: S = 0.125 * Q K^T, online softmax, O = P V.
// grid (2 splits, 5 mtiles, 16 g), 8 warps.  V loaded row-major [j][c]
// and B-frags formed with ldmatrix.trans.
// =====================================================================
__global__ __launch_bounds__(256) void flash_kernel()
{
    constexpr int JT = 16;
    extern __shared__ __align__(1024) char smem[];
    uint32_t sb = smem_u32(smem);
    const uint32_t sQh = sb, sQl = sb + 16384;

    int split = blockIdx.x, mtile = blockIdx.y, g = blockIdx.z;
    int b = g >> 3, h = g & 7;
    int row0 = mtile * 128;
    int tid = threadIdx.x, wid = tid >> 5, lane = tid & 31;

    const bf16* Qh = g_qkh + (size_t)b * 2048 * 1024 + h * 64;
    const bf16* Ql = g_qkl + (size_t)b * 2048 * 1024 + h * 64;
    const bf16* Kh = Qh + 512;
    const bf16* Kl = Ql + 512;
    const bf16* Vh = g_vh + (size_t)b * 2048 * 512 + h * 64;
    const bf16* Vl = g_vl + (size_t)b * 2048 * 512 + h * 64;

#pragma unroll
    for (int i = 0; i < 4; ++i) {
        int id = tid + i * 256;
        int r = id >> 3, ch = id & 7;
        uint32_t pos = fpos(r, ch);
        uint32_t gz = (row0 + r < NQ) ? 16u : 0u;
        CP_ASYNC16Z(sQh + pos, Qh + (size_t)(row0 + r) * 1024 + ch * 8, gz);
        CP_ASYNC16Z(sQl + pos, Ql + (size_t)(row0 + r) * 1024 + ch * 8, gz);
    }
    CP_ASYNC_COMMIT();

    int j0 = split * 1024;
    auto load_kv = [&](int stage, int jt) {
        uint32_t kb = sb + 32768 + stage * 32768;
        int jb = j0 + jt * 64;
#pragma unroll
        for (int i = 0; i < 2; ++i) {
            int id = tid + i * 256;
            int r = id >> 3, ch = id & 7;
            uint32_t pos = fpos(r, ch);
            CP_ASYNC16(kb + pos,         Kh + (size_t)(jb + r) * 1024 + ch * 8);
            CP_ASYNC16(kb + 8192 + pos,  Kl + (size_t)(jb + r) * 1024 + ch * 8);
            CP_ASYNC16(kb + 16384 + pos, Vh + (size_t)(jb + r) * 512 + ch * 8);
            CP_ASYNC16(kb + 24576 + pos, Vl + (size_t)(jb + r) * 512 + ch * 8);
        }
    };
    load_kv(0, 0);
    CP_ASYNC_COMMIT();
    CP_ASYNC_WAIT(0);
    __syncthreads();

    uint32_t qh[4][4], ql[4][4];
#pragma unroll
    for (int kk = 0; kk < 4; ++kk) {
        int r = wid * 16 + (lane & 15);
        uint32_t pos = fpos(r, 2 * kk + (lane >> 4));
        ldsm_x4(qh[kk], sQh + pos);
        ldsm_x4(ql[kk], sQl + pos);
    }

    float mr[2] = {-1e30f, -1e30f};
    float lr[2] = {0.f, 0.f};
    float oacc[8][4];
#pragma unroll
    for (int nt = 0; nt < 8; ++nt)
#pragma unroll
        for (int j = 0; j < 4; ++j) oacc[nt][j] = 0.f;

    for (int t = 0; t < JT; ++t) {
        if (t + 1 < JT) load_kv((t + 1) & 1, t + 1);
        CP_ASYNC_COMMIT();

        uint32_t kb = sb + 32768 + (t & 1) * 32768;

        // ---- S = Q K^T (bf16x3) ----
        float sacc[8][4];
#pragma unroll
        for (int nt = 0; nt < 8; ++nt)
#pragma unroll
            for (int j = 0; j < 4; ++j) sacc[nt][j] = 0.f;
#pragma unroll
        for (int kk = 0; kk < 4; ++kk) {
            uint32_t bh[8][2], bl[8][2];
#pragma unroll
            for (int p = 0; p < 4; ++p) {
                int r = p * 16 + ((lane >> 4) << 3) + (lane & 7);
                uint32_t pos = fpos(r, 2 * kk + ((lane >> 3) & 1));
                uint32_t f[4];
                ldsm_x4(f, kb + pos);
                bh[2 * p][0] = f[0]; bh[2 * p][1] = f[1];
                bh[2 * p + 1][0] = f[2]; bh[2 * p + 1][1] = f[3];
                ldsm_x4(f, kb + 8192 + pos);
                bl[2 * p][0] = f[0]; bl[2 * p][1] = f[1];
                bl[2 * p + 1][0] = f[2]; bl[2 * p + 1][1] = f[3];
            }
#pragma unroll
            for (int nt = 0; nt < 8; ++nt) {
                mma16(sacc[nt], qh[kk], bh[nt]);
                mma16(sacc[nt], qh[kk], bl[nt]);
                mma16(sacc[nt], ql[kk], bh[nt]);
            }
        }

        // ---- scale + online softmax ----
#pragma unroll
        for (int nt = 0; nt < 8; ++nt)
#pragma unroll
            for (int j = 0; j < 4; ++j) sacc[nt][j] *= 0.125f;

#pragma unroll
        for (int hr = 0; hr < 2; ++hr) {
            float mx = -1e30f;
#pragma unroll
            for (int nt = 0; nt < 8; ++nt)
                mx = fmaxf(mx, fmaxf(sacc[nt][hr * 2], sacc[nt][hr * 2 + 1]));
            mx = fmaxf(mx, __shfl_xor_sync(0xffffffffu, mx, 1));
            mx = fmaxf(mx, __shfl_xor_sync(0xffffffffu, mx, 2));
            float mnew = fmaxf(mr[hr], mx);
            float alpha = __expf(mr[hr] - mnew);
            mr[hr] = mnew;
            float rs = 0.f;
#pragma unroll
            for (int nt = 0; nt < 8; ++nt) {
                float p0 = __expf(sacc[nt][hr * 2] - mnew);
                float p1 = __expf(sacc[nt][hr * 2 + 1] - mnew);
                sacc[nt][hr * 2] = p0; sacc[nt][hr * 2 + 1] = p1;
                rs += p0 + p1;
            }
            rs += __shfl_xor_sync(0xffffffffu, rs, 1);
            rs += __shfl_xor_sync(0xffffffffu, rs, 2);
            lr[hr] = lr[hr] * alpha + rs;
#pragma unroll
            for (int nt = 0; nt < 8; ++nt) {
                oacc[nt][hr * 2]     *= alpha;
                oacc[nt][hr * 2 + 1] *= alpha;
            }
        }

        // ---- O += P V (bf16x3; V via trans-ldmatrix from [j][c]) ----
#pragma unroll
        for (int kk = 0; kk < 4; ++kk) {
            uint32_t pa_h[4], pa_l[4];
            {
                float x0 = sacc[2 * kk][0],     x1 = sacc[2 * kk][1];
                float x2 = sacc[2 * kk][2],     x3 = sacc[2 * kk][3];
                float y0 = sacc[2 * kk + 1][0], y1 = sacc[2 * kk + 1][1];
                float y2 = sacc[2 * kk + 1][2], y3 = sacc[2 * kk + 1][3];
                pa_h[0] = pack_bf(x0, x1);
                pa_h[1] = pack_bf(x2, x3);
                pa_h[2] = pack_bf(y0, y1);
                pa_h[3] = pack_bf(y2, y3);
                bf162* ph = (bf162*)pa_h;
                pa_l[0] = pack_bf(x0 - __bfloat162float(ph[0].x), x1 - __bfloat162float(ph[0].y));
                pa_l[1] = pack_bf(x2 - __bfloat162float(ph[1].x), x3 - __bfloat162float(ph[1].y));
                pa_l[2] = pack_bf(y0 - __bfloat162float(ph[2].x), y1 - __bfloat162float(ph[2].y));
                pa_l[3] = pack_bf(y2 - __bfloat162float(ph[3].x), y3 - __bfloat162float(ph[3].y));
            }
            uint32_t vh[8][2], vl[8][2];
#pragma unroll
            for (int p = 0; p < 4; ++p) {
                // trans load: j rows = k (within kk*16 tile), c cols = n
                int jl = kk * 16 + ((lane >> 3) & 1) * 8 + (lane & 7);
                int ch = p * 2 + (lane >> 4);
                uint32_t pos = fpos(jl, ch);
                uint32_t f[4];
                ldsm_x4_t(f, kb + 16384 + pos);
                vh[2 * p][0] = f[0]; vh[2 * p][1] = f[1];
                vh[2 * p + 1][0] = f[2]; vh[2 * p + 1][1] = f[3];
                ldsm_x4_t(f, kb + 24576 + pos);
                vl[2 * p][0] = f[0]; vl[2 * p][1] = f[1];
                vl[2 * p + 1][0] = f[2]; vl[2 * p + 1][1] = f[3];
            }
#pragma unroll
            for (int nt = 0; nt < 8; ++nt) {
                mma16(oacc[nt], pa_h, vh[nt]);
                mma16(oacc[nt], pa_h, vl[nt]);
                mma16(oacc[nt], pa_l, vh[nt]);
            }
        }

        CP_ASYNC_WAIT(0);
        __syncthreads();
    }

    int cr = lane >> 2, cc = (lane & 3) * 2;
#pragma unroll
    for (int hr = 0; hr < 2; ++hr) {
        int row = row0 + wid * 16 + cr + hr * 8;
        size_t base = (((size_t)split * G + g) * FROWS + row) * DHH;
#pragma unroll
        for (int nt = 0; nt < 8; ++nt) {
            *(float2*)&g_pO[base + nt * 8 + cc] =
                make_float2(oacc[nt][hr * 2], oacc[nt][hr * 2 + 1]);
        }
        if ((lane & 3) == 0) {
            size_t mi = ((size_t)split * G + g) * FROWS + row;
            g_pM[mi] = mr[hr];
            g_pL[mi] = lr[hr];
        }
    }
}

// =====================================================================
// Combine split-j partials -> o1 planes [b*513+row][h*64+c].
// =====================================================================
__global__ void combine_kernel()
{
    int idx = blockIdx.x * 256 + threadIdx.x;
    if (idx >= G * NQ * 32) return;
    int c = (idx & 31) * 2;
    int rem = idx >> 5;
    int row = rem % NQ, g = rem / NQ;
    int b = g >> 3, h = g & 7;
    size_t m0i = ((size_t)0 * G + g) * FROWS + row;
    size_t m1i = ((size_t)1 * G + g) * FROWS + row;
    float m0 = g_pM[m0i], l0 = g_pL[m0i];
    float m1 = g_pM[m1i], l1 = g_pL[m1i];
    float M = fmaxf(m0, m1);
    float w0 = __expf(m0 - M), w1 = __expf(m1 - M);
    float inv = 1.f / (w0 * l0 + w1 * l1);
    float2 o0 = *(const float2*)&g_pO[m0i * DHH + c];
    float2 o1 = *(const float2*)&g_pO[m1i * DHH + c];
    float vx = (w0 * o0.x + w1 * o1.x) * inv;
    float vy = (w0 * o0.y + w1 * o1.y) * inv;
    bf16 hx, lx, hy, ly;
    bsplit(vx, hx, lx); bsplit(vy, hy, ly);
    bf162 hh; hh.x = hx; hh.y = hy;
    bf162 ll; ll.x = lx; ll.y = ly;
    size_t o = (size_t)(b * 513 + row) * 512 + h * 64 + c;
    *(bf162*)&g_o1h[o] = hh;
    *(bf162*)&g_o1l[o] = ll;
}

// =====================================================================
// x splitter
// =====================================================================
__global__ void split_x_kernel(const float* __restrict__ X)
{
    int i = blockIdx.x * 256 + threadIdx.x;
    float4 v = ((const float4*)X)[i];
    bf16 h0, l0, h1, l1, h2, l2, h3, l3;
    bsplit(v.x, h0, l0); bsplit(v.y, h1, l1);
    bsplit(v.z, h2, l2); bsplit(v.w, h3, l3);
    bf162 a, b;
    a.x = h0; a.y = h1; b.x = h2; b.y = h3;
    ((bf162*)g_xh)[i * 2] = a; ((bf162*)g_xh)[i * 2 + 1] = b;
    a.x = l0; a.y = l1; b.x = l2; b.y = l3;
    ((bf162*)g_xl)[i * 2] = a; ((bf162*)g_xl)[i * 2 + 1] = b;
}

// =====================================================================
// W_qkv transpose + split: D[c][r] = split(S[r][c]), S=[512][2048].
// =====================================================================
__global__ void transpose_split(const float* __restrict__ S,
                                bf16* __restrict__ Dh, bf16* __restrict__ Dl,
                                int R, int C)
{
    __shared__ float t[32][33];
    int bx = blockIdx.x * 32, by = blockIdx.y * 32;
#pragma unroll
    for (int i = 0; i < 32; i += 8)
        t[threadIdx.y + i][threadIdx.x] =
            S[(size_t)(by + threadIdx.y + i) * C + bx + threadIdx.x];
    __syncthreads();
#pragma unroll
    for (int i = 0; i < 32; i += 8) {
        float v = t[threadIdx.x][threadIdx.y + i];
        bf16 h, l; bsplit(v, h, l);
        size_t o = (size_t)(bx + threadIdx.y + i) * R + by + threadIdx.x;
        Dh[o] = h; Dl[o] = l;
    }
}

// =====================================================================
// W_out transpose with out1/out2 row split remap.
// W_out [1024][512]; row r = h*128+cc.  cc<64 -> Wo1t[c][h*64+cc],
// else Wo2t[c][h*64+cc-64].  grid (16, 32), block (32,8).
// =====================================================================
__global__ void trans_wout(const float* __restrict__ W)
{
    __shared__ float t[32][33];
    int bx = blockIdx.x * 32, by = blockIdx.y * 32;
#pragma unroll
    for (int i = 0; i < 32; i += 8)
        t[threadIdx.y + i][threadIdx.x] =
            W[(size_t)(by + threadIdx.y + i) * 512 + bx + threadIdx.x];
    __syncthreads();
#pragma unroll
    for (int i = 0; i < 32; i += 8) {
        int c = bx + threadIdx.y + i;          // out column 0..511
        int r = by + threadIdx.x;              // W_out row
        float v = t[threadIdx.x][threadIdx.y + i];
        int h = r >> 7, cc = r & 127;
        bf16 hh, ll; bsplit(v, hh, ll);
        size_t o = (size_t)c * 512 + h * 64 + (cc & 63);
        if (cc < 64) { g_Wo1th[o] = hh; g_Wo1tl[o] = ll; }
        else         { g_Wo2th[o] = hh; g_Wo2tl[o] = ll; }
    }
}

// =====================================================================
// out2 decay scan (sinv closed-form in smem; backward pass buffered in
// smem, forward pass writes bf16 planes).  grid (16 g, 8 chunks), 64 thr.
// =====================================================================
__global__ __launch_bounds__(64) void scan_kernel()
{
    extern __shared__ float sm[];
    float* buf = sm;                 // [256][64]
    float* sv  = sm + 256 * 64;      // [448]

    int g = blockIdx.x, chunk = blockIdx.y;
    int b = g >> 3, h = g & 7;
    int c = threadIdx.x;
    const float r = RDEC;
    int i0 = chunk * 256;

    for (int q = (int)threadIdx.x; q < 448; q += 64) {
        int j = i0 - 96 + q;
        if (j >= 0 && j < NN) {
            float s = (1.0f - powf(r, (float)(j + 1)) + r - powf(r, (float)(NN - j)))
                      / (1.0f - r);
            sv[q] = 1.0f / s;
        }
    }
    __syncthreads();

    const float* T = g_t + (size_t)b * 2048 * 512 + h * 64 + c;

    int je = i0 + 255 + 96; if (je > NN - 1) je = NN - 1;
    float gg = 0.f;
    for (int j = je; j >= i0; --j) {
        float u = T[(size_t)j * 512] * sv[j - i0 + 96];
        gg = gg * r + u;
        if (j < i0 + 256) buf[(j - i0) * 64 + c] = gg;
    }

    int js = i0 - 96; if (js < 0) js = 0;
    float f = 0.f;
    for (int j = js; j < i0 + 256; ++j) {
        float u = T[(size_t)j * 512] * sv[j - i0 + 96];
        f = f * r + u;
        if (j >= i0) {
            float v = f + buf[(j - i0) * 64 + c] - u;
            bf16 hh, ll; bsplit(v, hh, ll);
            size_t o = (size_t)(b * 2048 + j) * 512 + h * 64 + c;
            g_o2h[o] = hh; g_o2l[o] = ll;
        }
    }
}

// =====================================================================
#define SM_QKV   (STAGES * 2 * (128 * 64 + 128 * 64))   // 98304
#define SM_O1    (STAGES * 2 * (64 * 64 + 64 * 64))     // 49152
#define SM_OUT   (STAGES * 2 * (128 * 64 + 64 * 64))    // 73728
#define SM_FLASH (32768 + 2 * 32768)                    // 98304
#define SM_SCAN  (256 * 64 * 4 + 448 * 4)               // 67328

extern "C" void kernel_launch(void* const* d_in, const int* in_sizes, int n_in,
                              void* d_out, int out_size)
{
    const float* x     = (const float*)d_in[0];   // [2,2048,512]
    const float* W_qkv = (const float*)d_in[1];   // [512,2048]
    const float* W_out = (const float*)d_in[2];   // [1024,512]
    const float* b_out = (const float*)d_in[3];   // [512]
    float* out = (float*)d_out;                   // [2,2048,512]

    bf16 *p_xh, *p_xl, *p_Wqth, *p_Wqtl;
    bf16 *p_Wo1th, *p_Wo1tl, *p_Wo2th, *p_Wo2tl;
    bf16 *p_o1h, *p_o1l, *p_o2h, *p_o2l;
    float *p_O1;
    cudaGetSymbolAddress((void**)&p_xh,    g_xh);
    cudaGetSymbolAddress((void**)&p_xl,    g_xl);
    cudaGetSymbolAddress((void**)&p_Wqth,  g_Wqth);
    cudaGetSymbolAddress((void**)&p_Wqtl,  g_Wqtl);
    cudaGetSymbolAddress((void**)&p_Wo1th, g_Wo1th);
    cudaGetSymbolAddress((void**)&p_Wo1tl, g_Wo1tl);
    cudaGetSymbolAddress((void**)&p_Wo2th, g_Wo2th);
    cudaGetSymbolAddress((void**)&p_Wo2tl, g_Wo2tl);
    cudaGetSymbolAddress((void**)&p_o1h,   g_o1h);
    cudaGetSymbolAddress((void**)&p_o1l,   g_o1l);
    cudaGetSymbolAddress((void**)&p_o2h,   g_o2h);
    cudaGetSymbolAddress((void**)&p_o2l,   g_o2l);
    cudaGetSymbolAddress((void**)&p_O1,    g_O1);

    static bool attr_done = false;
    if (!attr_done) {
        cudaFuncSetAttribute(bmma_gemm<128, 128, 1>,
                             cudaFuncAttributeMaxDynamicSharedMemorySize, SM_QKV);
        cudaFuncSetAttribute(bmma_gemm<64, 64, 0>,
                             cudaFuncAttributeMaxDynamicSharedMemorySize, SM_O1);
        cudaFuncSetAttribute(bmma_gemm<128, 64, 5>,
                             cudaFuncAttributeMaxDynamicSharedMemorySize, SM_OUT);
        cudaFuncSetAttribute(flash_kernel,
                             cudaFuncAttributeMaxDynamicSharedMemorySize, SM_FLASH);
        cudaFuncSetAttribute(scan_kernel,
                             cudaFuncAttributeMaxDynamicSharedMemorySize, SM_SCAN);
        attr_done = true;
    }

    // 0) input/weight plane production
    split_x_kernel<<<(ROWS * DIMM / 4) / 256, 256>>>(x);
    transpose_split<<<dim3(64, 16), dim3(32, 8)>>>(W_qkv, p_Wqth, p_Wqtl, 512, 2048);
    trans_wout<<<dim3(16, 32), dim3(32, 8)>>>(W_out);

    // 1) qkvt: Q (rows<640/batch) + K/V/t, all epilogues fused.
    bmma_gemm<128, 128, 1><<<dim3(16, 32, 1), 256, SM_QKV>>>(
        p_xh, p_xl, DIMM, p_Wqth, p_Wqtl, DIMM, nullptr, 0, ROWS, DIMM, nullptr);

    // 2) fused flash (split-j x2) + combine -> o1 planes
    flash_kernel<<<dim3(2, 5, G), 256, SM_FLASH>>>();
    combine_kernel<<<(G * NQ * 32 + 255) / 256, 256>>>();

    // 3) out2 decay scan -> o2 planes
    scan_kernel<<<dim3(G, 8), 64, SM_SCAN>>>();

    // 4) O1proj = o1 @ Wo1 : M=1026, N=512, K=512
    bmma_gemm<64, 64, 0><<<dim3(8, 17, 1), 256, SM_O1>>>(
        p_o1h, p_o1l, 512, p_Wo1th, p_Wo1tl, 512, p_O1, 512, 1026, 512, nullptr);

    // 5) out = o2 @ Wo2 + gather(O1proj) + b_out : M=4096, N=512, K=512
    bmma_gemm<128, 64, 5><<<dim3(8, 32, 1), 256, SM_OUT>>>(
        p_o2h, p_o2l, 512, p_Wo2th, p_Wo2tl, 512, out, DIMM, ROWS, 512, b_out);
}

// round 12
// speedup vs baseline: 2.6259x; 1.0593x over previous
#include <cuda_runtime.h>
#include <cuda_bf16.h>
#include <cstdint>
#include <cstddef>

// Problem constants
#define BB    2
#define NN    2048
#define DIMM  512
#define HH    8
#define DHH   64
#define NQ    513          // distinct effective query rows per head (q[i] = q[i % 513])
#define G     16           // B*H
#define ROWS  4096         // B*N
#define FROWS 640          // padded NQ for flash partials (5 * 128)
#define NSPLIT 4           // flash split-j factor

// r = exp(-1/e)
#define RDEC 0.69220062755534637f

typedef __nv_bfloat16  bf16;
typedef __nv_bfloat162 bf162;

// ---------------- scratch (static device arrays; no allocation) ----------------
__device__ __align__(256) float g_t[(size_t)ROWS * 512];          // t quarter fp32
__device__ __align__(256) float g_O1[(size_t)1152 * 512];         // O1proj fp32

__device__ __align__(256) bf16 g_xh[(size_t)ROWS * DIMM];         // x planes
__device__ __align__(256) bf16 g_xl[(size_t)ROWS * DIMM];
__device__ __align__(256) bf16 g_Wqth[(size_t)2048 * DIMM];       // W_qkv^T planes
__device__ __align__(256) bf16 g_Wqtl[(size_t)2048 * DIMM];
__device__ __align__(256) bf16 g_Wo1th[(size_t)512 * 512];        // W_out^T (out1 rows) planes
__device__ __align__(256) bf16 g_Wo1tl[(size_t)512 * 512];
__device__ __align__(256) bf16 g_Wo2th[(size_t)512 * 512];        // W_out^T (out2 rows) planes
__device__ __align__(256) bf16 g_Wo2tl[(size_t)512 * 512];
__device__ __align__(256) bf16 g_qkh[(size_t)ROWS * 1024];        // Q/K planes (cols 0..1023)
__device__ __align__(256) bf16 g_qkl[(size_t)ROWS * 1024];
__device__ __align__(256) bf16 g_vh[(size_t)ROWS * 512];          // V planes [row][h*64+c]
__device__ __align__(256) bf16 g_vl[(size_t)ROWS * 512];
__device__ __align__(256) bf16 g_o1h[(size_t)1152 * 512];         // combine out planes
__device__ __align__(256) bf16 g_o1l[(size_t)1152 * 512];
__device__ __align__(256) bf16 g_o2h[(size_t)ROWS * 512];         // scan out planes
__device__ __align__(256) bf16 g_o2l[(size_t)ROWS * 512];

// flash split-j partials
__device__ __align__(256) float g_pO[(size_t)NSPLIT * G * FROWS * DHH];
__device__ __align__(256) float g_pM[NSPLIT * G * FROWS];
__device__ __align__(256) float g_pL[NSPLIT * G * FROWS];

// ======================= portable PTX helpers =======================
__device__ __forceinline__ uint32_t smem_u32(const void* p) {
    uint32_t a;
    asm("{ .reg .u64 t; cvta.to.shared.u64 t, %1; cvt.u32.u64 %0, t; }" : "=r"(a) : "l"(p));
    return a;
}
__device__ __forceinline__ void ldsm_x4(uint32_t* f, uint32_t addr) {
    asm volatile("ldmatrix.sync.aligned.m8n8.x4.shared.b16 {%0,%1,%2,%3}, [%4];"
                 : "=r"(f[0]), "=r"(f[1]), "=r"(f[2]), "=r"(f[3]) : "r"(addr));
}
__device__ __forceinline__ void ldsm_x4_t(uint32_t* f, uint32_t addr) {
    asm volatile("ldmatrix.sync.aligned.m8n8.x4.trans.shared.b16 {%0,%1,%2,%3}, [%4];"
                 : "=r"(f[0]), "=r"(f[1]), "=r"(f[2]), "=r"(f[3]) : "r"(addr));
}
__device__ __forceinline__ void mma16(float* c, const uint32_t* a, const uint32_t* b) {
    asm volatile("mma.sync.aligned.m16n8k16.row.col.f32.bf16.bf16.f32 "
                 "{%0,%1,%2,%3}, {%4,%5,%6,%7}, {%8,%9}, {%0,%1,%2,%3};"
                 : "+f"(c[0]), "+f"(c[1]), "+f"(c[2]), "+f"(c[3])
                 : "r"(a[0]), "r"(a[1]), "r"(a[2]), "r"(a[3]), "r"(b[0]), "r"(b[1]));
}
#define CP_ASYNC_COMMIT() asm volatile("cp.async.commit_group;")
#define CP_ASYNC_WAIT(n)  asm volatile("cp.async.wait_group %0;" :: "n"(n))
#define CP_ASYNC16(dst, src) \
    asm volatile("cp.async.cg.shared.global [%0], [%1], 16;" :: "r"(dst), "l"(src))
#define CP_ASYNC16Z(dst, src, gz) \
    asm volatile("cp.async.cg.shared.global [%0], [%1], 16, %2;" :: "r"(dst), "l"(src), "r"(gz))

__device__ __forceinline__ void bsplit(float v, bf16& h, bf16& l) {
    h = __float2bfloat16(v);
    l = __float2bfloat16(v - __bfloat162float(h));
}
__device__ __forceinline__ uint32_t pack_bf(float lo, float hi) {
    bf162 t; t.x = __float2bfloat16(lo); t.y = __float2bfloat16(hi);
    return *(uint32_t*)&t;
}

// interleaved-line SMEM layout for BK=32 (64B rows): 2 rows per 128B line
__device__ __forceinline__ uint32_t tpos(int r, int ch) {
    return ((uint32_t)(r >> 1) << 7) |
           ((uint32_t)((((r & 1) << 2) | ch) ^ ((r >> 1) & 7)) << 4);
}
// full-line layout for 128B rows (64 bf16): chunk ch in 0..7
__device__ __forceinline__ uint32_t fpos(int r, int ch) {
    return ((uint32_t)r << 7) | ((uint32_t)(ch ^ (r & 7)) << 4);
}

#define STAGES 3

// =====================================================================
// bf16x3 mma.sync GEMM: C[M,N] = A[M,K] @ B[N,K]^T (+extras)
// A/B as (hi, lo) bf16 planes, K-major.  CTA BM x BN, 8 warps (4m x 2n).
// __launch_bounds__(256, 2): cap 128 regs -> 2 CTAs/SM.
// MODE 0: plain fp32 C (+bias if given).
// MODE 1: qkvt producer (Q region only rows%2048<640; fused plane epilogues).
// MODE 5: final out.  C = acc + bias[cg] + O1proj[b*513 + i%513][cg].
// =====================================================================
template<int BM, int BN, int MODE>
__global__ __launch_bounds__(256, 2) void bmma_gemm(
    const bf16* __restrict__ Ah, const bf16* __restrict__ Al, int lda,
    const bf16* __restrict__ Bh, const bf16* __restrict__ Bl, int ldb,
    float* __restrict__ C, int ldc,
    int M, int K, const float* __restrict__ bias)
{
    constexpr int MT     = BM / 64;
    constexpr int NTILES = BN / 16;
    constexpr int APL = BM * 64;
    constexpr int BPL = BN * 64;
    constexpr int STAGE = 2 * (APL + BPL);

    int row0 = blockIdx.y * BM;
    int col0 = blockIdx.x * BN;
    if (MODE == 1) {
        if (col0 < 512 && (row0 & 2047) >= FROWS) return;   // Q region: 640 rows/batch
    }

    extern __shared__ __align__(1024) char smem[];
    uint32_t sbase = smem_u32(smem);
    int tid = threadIdx.x, wid = tid >> 5, lane = tid & 31;

    auto load_stage = [&](int stage, int k0) {
        uint32_t sb = sbase + stage * STAGE;
#pragma unroll
        for (int i = 0; i < BM * 4 / 256; ++i) {
            int id = tid + i * 256;
            int r = id >> 2, ch = id & 3;
            uint32_t pos = tpos(r, ch);
            const bf16* sh = Ah + (size_t)(row0 + r) * lda + k0 + ch * 8;
            const bf16* sl = Al + (size_t)(row0 + r) * lda + k0 + ch * 8;
            uint32_t gz = (row0 + r < M) ? 16u : 0u;
            CP_ASYNC16Z(sb + pos, sh, gz);
            CP_ASYNC16Z(sb + APL + pos, sl, gz);
        }
#pragma unroll
        for (int i = 0; i < BN * 4 / 256; ++i) {
            int id = tid + i * 256;
            int r = id >> 2, ch = id & 3;
            uint32_t pos = tpos(r, ch);
            const bf16* sh = Bh + (size_t)(col0 + r) * ldb + k0 + ch * 8;
            const bf16* sl = Bl + (size_t)(col0 + r) * ldb + k0 + ch * 8;
            CP_ASYNC16(sb + 2 * APL + pos, sh);
            CP_ASYNC16(sb + 2 * APL + BPL + pos, sl);
        }
    };

    int NT = K >> 5;
#pragma unroll
    for (int s = 0; s < STAGES - 1; ++s) {
        if (s < NT) load_stage(s, s * 32);
        CP_ASYNC_COMMIT();
    }

    int wm = wid & 3, wn = wid >> 2;
    int mbase = wm * (BM / 4);
    int nbase = wn * (BN / 2);

    float acc[MT][NTILES][4];
#pragma unroll
    for (int mt = 0; mt < MT; ++mt)
#pragma unroll
        for (int nt = 0; nt < NTILES; ++nt)
#pragma unroll
            for (int j = 0; j < 4; ++j) acc[mt][nt][j] = 0.f;

    for (int t = 0; t < NT; ++t) {
        CP_ASYNC_WAIT(STAGES - 2);
        __syncthreads();
        if (t + STAGES - 1 < NT)
            load_stage((t + STAGES - 1) % STAGES, (t + STAGES - 1) * 32);
        CP_ASYNC_COMMIT();

        uint32_t sb = sbase + (t % STAGES) * STAGE;
#pragma unroll
        for (int kk = 0; kk < 2; ++kk) {
            uint32_t ah[MT][4], al[MT][4];
#pragma unroll
            for (int mt = 0; mt < MT; ++mt) {
                int r = mbase + mt * 16 + (lane & 15);
                int ch = kk * 2 + (lane >> 4);
                uint32_t pos = tpos(r, ch);
                ldsm_x4(ah[mt], sb + pos);
                ldsm_x4(al[mt], sb + APL + pos);
            }
            uint32_t bh[NTILES][2], bl[NTILES][2];
#pragma unroll
            for (int p = 0; p < NTILES / 2; ++p) {
                int r = nbase + p * 16 + ((lane >> 4) << 3) + (lane & 7);
                int ch = kk * 2 + ((lane >> 3) & 1);
                uint32_t pos = tpos(r, ch);
                uint32_t f[4];
                ldsm_x4(f, sb + 2 * APL + pos);
                bh[2 * p][0] = f[0]; bh[2 * p][1] = f[1];
                bh[2 * p + 1][0] = f[2]; bh[2 * p + 1][1] = f[3];
                ldsm_x4(f, sb + 2 * APL + BPL + pos);
                bl[2 * p][0] = f[0]; bl[2 * p][1] = f[1];
                bl[2 * p + 1][0] = f[2]; bl[2 * p + 1][1] = f[3];
            }
#pragma unroll
            for (int mt = 0; mt < MT; ++mt)
#pragma unroll
                for (int nt = 0; nt < NTILES; ++nt) {
                    mma16(acc[mt][nt], ah[mt], bh[nt]);
                    mma16(acc[mt][nt], ah[mt], bl[nt]);
                    mma16(acc[mt][nt], al[mt], bh[nt]);
                }
        }
    }
    CP_ASYNC_WAIT(0);

    int cr = lane >> 2, cc = (lane & 3) * 2;
#pragma unroll
    for (int mt = 0; mt < MT; ++mt) {
        int rgb = row0 + mbase + mt * 16 + cr;
#pragma unroll
        for (int nt = 0; nt < NTILES; ++nt) {
            int cg = col0 + nbase + nt * 8 + cc;
#pragma unroll
            for (int half = 0; half < 2; ++half) {
                int rg = rgb + half * 8;
                if (rg >= M) continue;
                float vx = acc[mt][nt][half * 2];
                float vy = acc[mt][nt][half * 2 + 1];
                if (MODE == 0) {
                    if (bias) {
                        float2 b2 = *(const float2*)(bias + cg);
                        vx += b2.x; vy += b2.y;
                    }
                    *(float2*)(C + (size_t)rg * ldc + cg) = make_float2(vx, vy);
                } else if (MODE == 5) {
                    float2 b2 = *(const float2*)(bias + cg);
                    int b = rg >> 11, i = rg & 2047;
                    int i513 = i % 513;
                    float2 o1 = *(const float2*)&g_O1[(size_t)(b * 513 + i513) * 512 + cg];
                    *(float2*)(C + (size_t)rg * ldc + cg) =
                        make_float2(vx + b2.x + o1.x, vy + b2.y + o1.y);
                } else { // MODE 1
                    if (cg < 1024) {
                        bf16 hx, lx, hy, ly;
                        bsplit(vx, hx, lx); bsplit(vy, hy, ly);
                        bf162 hh; hh.x = hx; hh.y = hy;
                        bf162 ll; ll.x = lx; ll.y = ly;
                        *(bf162*)&g_qkh[(size_t)rg * 1024 + cg] = hh;
                        *(bf162*)&g_qkl[(size_t)rg * 1024 + cg] = ll;
                    } else if (cg < 1536) {
                        bf16 hx, lx, hy, ly;
                        bsplit(vx, hx, lx); bsplit(vy, hy, ly);
                        bf162 hh; hh.x = hx; hh.y = hy;
                        bf162 ll; ll.x = lx; ll.y = ly;
                        *(bf162*)&g_vh[(size_t)rg * 512 + cg - 1024] = hh;
                        *(bf162*)&g_vl[(size_t)rg * 512 + cg - 1024] = ll;
                    } else {
                        *(float2*)&g_t[(size_t)rg * 512 + cg - 1536] = make_float2(vx, vy);
                    }
                }
            }
        }
    }
}

// =====================================================================
// Fused flash attention: S = 0.125 * Q K^T, online softmax, O = P V.
// grid (NSPLIT, 5, 16), 8 warps.  512 j per split, j-tiles of 64.
// =====================================================================
__global__ __launch_bounds__(256) void flash_kernel()
{
    constexpr int JT = 2048 / (NSPLIT * 64);     // j-tiles per split
    extern __shared__ __align__(1024) char smem[];
    uint32_t sb = smem_u32(smem);
    const uint32_t sQh = sb, sQl = sb + 16384;

    int split = blockIdx.x, mtile = blockIdx.y, g = blockIdx.z;
    int b = g >> 3, h = g & 7;
    int row0 = mtile * 128;
    int tid = threadIdx.x, wid = tid >> 5, lane = tid & 31;

    const bf16* Qh = g_qkh + (size_t)b * 2048 * 1024 + h * 64;
    const bf16* Ql = g_qkl + (size_t)b * 2048 * 1024 + h * 64;
    const bf16* Kh = Qh + 512;
    const bf16* Kl = Ql + 512;
    const bf16* Vh = g_vh + (size_t)b * 2048 * 512 + h * 64;
    const bf16* Vl = g_vl + (size_t)b * 2048 * 512 + h * 64;

#pragma unroll
    for (int i = 0; i < 4; ++i) {
        int id = tid + i * 256;
        int r = id >> 3, ch = id & 7;
        uint32_t pos = fpos(r, ch);
        uint32_t gz = (row0 + r < NQ) ? 16u : 0u;
        CP_ASYNC16Z(sQh + pos, Qh + (size_t)(row0 + r) * 1024 + ch * 8, gz);
        CP_ASYNC16Z(sQl + pos, Ql + (size_t)(row0 + r) * 1024 + ch * 8, gz);
    }
    CP_ASYNC_COMMIT();

    int j0 = split * (2048 / NSPLIT);
    auto load_kv = [&](int stage, int jt) {
        uint32_t kb = sb + 32768 + stage * 32768;
        int jb = j0 + jt * 64;
#pragma unroll
        for (int i = 0; i < 2; ++i) {
            int id = tid + i * 256;
            int r = id >> 3, ch = id & 7;
            uint32_t pos = fpos(r, ch);
            CP_ASYNC16(kb + pos,         Kh + (size_t)(jb + r) * 1024 + ch * 8);
            CP_ASYNC16(kb + 8192 + pos,  Kl + (size_t)(jb + r) * 1024 + ch * 8);
            CP_ASYNC16(kb + 16384 + pos, Vh + (size_t)(jb + r) * 512 + ch * 8);
            CP_ASYNC16(kb + 24576 + pos, Vl + (size_t)(jb + r) * 512 + ch * 8);
        }
    };
    load_kv(0, 0);
    CP_ASYNC_COMMIT();
    CP_ASYNC_WAIT(0);
    __syncthreads();

    uint32_t qh[4][4], ql[4][4];
#pragma unroll
    for (int kk = 0; kk < 4; ++kk) {
        int r = wid * 16 + (lane & 15);
        uint32_t pos = fpos(r, 2 * kk + (lane >> 4));
        ldsm_x4(qh[kk], sQh + pos);
        ldsm_x4(ql[kk], sQl + pos);
    }

    float mr[2] = {-1e30f, -1e30f};
    float lr[2] = {0.f, 0.f};
    float oacc[8][4];
#pragma unroll
    for (int nt = 0; nt < 8; ++nt)
#pragma unroll
        for (int j = 0; j < 4; ++j) oacc[nt][j] = 0.f;

    for (int t = 0; t < JT; ++t) {
        if (t + 1 < JT) load_kv((t + 1) & 1, t + 1);
        CP_ASYNC_COMMIT();

        uint32_t kb = sb + 32768 + (t & 1) * 32768;

        // ---- S = Q K^T (bf16x3) ----
        float sacc[8][4];
#pragma unroll
        for (int nt = 0; nt < 8; ++nt)
#pragma unroll
            for (int j = 0; j < 4; ++j) sacc[nt][j] = 0.f;
#pragma unroll
        for (int kk = 0; kk < 4; ++kk) {
            uint32_t bh[8][2], bl[8][2];
#pragma unroll
            for (int p = 0; p < 4; ++p) {
                int r = p * 16 + ((lane >> 4) << 3) + (lane & 7);
                uint32_t pos = fpos(r, 2 * kk + ((lane >> 3) & 1));
                uint32_t f[4];
                ldsm_x4(f, kb + pos);
                bh[2 * p][0] = f[0]; bh[2 * p][1] = f[1];
                bh[2 * p + 1][0] = f[2]; bh[2 * p + 1][1] = f[3];
                ldsm_x4(f, kb + 8192 + pos);
                bl[2 * p][0] = f[0]; bl[2 * p][1] = f[1];
                bl[2 * p + 1][0] = f[2]; bl[2 * p + 1][1] = f[3];
            }
#pragma unroll
            for (int nt = 0; nt < 8; ++nt) {
                mma16(sacc[nt], qh[kk], bh[nt]);
                mma16(sacc[nt], qh[kk], bl[nt]);
                mma16(sacc[nt], ql[kk], bh[nt]);
            }
        }

        // ---- scale + online softmax ----
#pragma unroll
        for (int nt = 0; nt < 8; ++nt)
#pragma unroll
            for (int j = 0; j < 4; ++j) sacc[nt][j] *= 0.125f;

#pragma unroll
        for (int hr = 0; hr < 2; ++hr) {
            float mx = -1e30f;
#pragma unroll
            for (int nt = 0; nt < 8; ++nt)
                mx = fmaxf(mx, fmaxf(sacc[nt][hr * 2], sacc[nt][hr * 2 + 1]));
            mx = fmaxf(mx, __shfl_xor_sync(0xffffffffu, mx, 1));
            mx = fmaxf(mx, __shfl_xor_sync(0xffffffffu, mx, 2));
            float mnew = fmaxf(mr[hr], mx);
            float alpha = __expf(mr[hr] - mnew);
            mr[hr] = mnew;
            float rs = 0.f;
#pragma unroll
            for (int nt = 0; nt < 8; ++nt) {
                float p0 = __expf(sacc[nt][hr * 2] - mnew);
                float p1 = __expf(sacc[nt][hr * 2 + 1] - mnew);
                sacc[nt][hr * 2] = p0; sacc[nt][hr * 2 + 1] = p1;
                rs += p0 + p1;
            }
            rs += __shfl_xor_sync(0xffffffffu, rs, 1);
            rs += __shfl_xor_sync(0xffffffffu, rs, 2);
            lr[hr] = lr[hr] * alpha + rs;
#pragma unroll
            for (int nt = 0; nt < 8; ++nt) {
                oacc[nt][hr * 2]     *= alpha;
                oacc[nt][hr * 2 + 1] *= alpha;
            }
        }

        // ---- O += P V (bf16x3; V via trans-ldmatrix from [j][c]) ----
#pragma unroll
        for (int kk = 0; kk < 4; ++kk) {
            uint32_t pa_h[4], pa_l[4];
            {
                float x0 = sacc[2 * kk][0],     x1 = sacc[2 * kk][1];
                float x2 = sacc[2 * kk][2],     x3 = sacc[2 * kk][3];
                float y0 = sacc[2 * kk + 1][0], y1 = sacc[2 * kk + 1][1];
                float y2 = sacc[2 * kk + 1][2], y3 = sacc[2 * kk + 1][3];
                pa_h[0] = pack_bf(x0, x1);
                pa_h[1] = pack_bf(x2, x3);
                pa_h[2] = pack_bf(y0, y1);
                pa_h[3] = pack_bf(y2, y3);
                bf162* ph = (bf162*)pa_h;
                pa_l[0] = pack_bf(x0 - __bfloat162float(ph[0].x), x1 - __bfloat162float(ph[0].y));
                pa_l[1] = pack_bf(x2 - __bfloat162float(ph[1].x), x3 - __bfloat162float(ph[1].y));
                pa_l[2] = pack_bf(y0 - __bfloat162float(ph[2].x), y1 - __bfloat162float(ph[2].y));
                pa_l[3] = pack_bf(y2 - __bfloat162float(ph[3].x), y3 - __bfloat162float(ph[3].y));
            }
            uint32_t vh[8][2], vl[8][2];
#pragma unroll
            for (int p = 0; p < 4; ++p) {
                int jl = kk * 16 + ((lane >> 3) & 1) * 8 + (lane & 7);
                int ch = p * 2 + (lane >> 4);
                uint32_t pos = fpos(jl, ch);
                uint32_t f[4];
                ldsm_x4_t(f, kb + 16384 + pos);
                vh[2 * p][0] = f[0]; vh[2 * p][1] = f[1];
                vh[2 * p + 1][0] = f[2]; vh[2 * p + 1][1] = f[3];
                ldsm_x4_t(f, kb + 24576 + pos);
                vl[2 * p][0] = f[0]; vl[2 * p][1] = f[1];
                vl[2 * p + 1][0] = f[2]; vl[2 * p + 1][1] = f[3];
            }
#pragma unroll
            for (int nt = 0; nt < 8; ++nt) {
                mma16(oacc[nt], pa_h, vh[nt]);
                mma16(oacc[nt], pa_h, vl[nt]);
                mma16(oacc[nt], pa_l, vh[nt]);
            }
        }

        CP_ASYNC_WAIT(0);
        __syncthreads();
    }

    int cr = lane >> 2, cc = (lane & 3) * 2;
#pragma unroll
    for (int hr = 0; hr < 2; ++hr) {
        int row = row0 + wid * 16 + cr + hr * 8;
        size_t base = (((size_t)split * G + g) * FROWS + row) * DHH;
#pragma unroll
        for (int nt = 0; nt < 8; ++nt) {
            *(float2*)&g_pO[base + nt * 8 + cc] =
                make_float2(oacc[nt][hr * 2], oacc[nt][hr * 2 + 1]);
        }
        if ((lane & 3) == 0) {
            size_t mi = ((size_t)split * G + g) * FROWS + row;
            g_pM[mi] = mr[hr];
            g_pL[mi] = lr[hr];
        }
    }
}

// =====================================================================
// Combine split-j partials -> o1 planes [b*513+row][h*64+c].
// =====================================================================
__global__ void combine_kernel()
{
    int idx = blockIdx.x * 256 + threadIdx.x;
    if (idx >= G * NQ * 32) return;
    int c = (idx & 31) * 2;
    int rem = idx >> 5;
    int row = rem % NQ, g = rem / NQ;
    int b = g >> 3, h = g & 7;

    float m[NSPLIT], l[NSPLIT];
    float M = -1e30f;
#pragma unroll
    for (int s = 0; s < NSPLIT; ++s) {
        size_t mi = ((size_t)s * G + g) * FROWS + row;
        m[s] = g_pM[mi]; l[s] = g_pL[mi];
        M = fmaxf(M, m[s]);
    }
    float den = 0.f;
    float w[NSPLIT];
#pragma unroll
    for (int s = 0; s < NSPLIT; ++s) {
        w[s] = __expf(m[s] - M);
        den += w[s] * l[s];
    }
    float inv = 1.f / den;
    float vx = 0.f, vy = 0.f;
#pragma unroll
    for (int s = 0; s < NSPLIT; ++s) {
        size_t mi = ((size_t)s * G + g) * FROWS + row;
        float2 o = *(const float2*)&g_pO[mi * DHH + c];
        vx += w[s] * o.x; vy += w[s] * o.y;
    }
    vx *= inv; vy *= inv;

    bf16 hx, lx, hy, ly;
    bsplit(vx, hx, lx); bsplit(vy, hy, ly);
    bf162 hh; hh.x = hx; hh.y = hy;
    bf162 ll; ll.x = lx; ll.y = ly;
    size_t o = (size_t)(b * 513 + row) * 512 + h * 64 + c;
    *(bf162*)&g_o1h[o] = hh;
    *(bf162*)&g_o1l[o] = ll;
}

// =====================================================================
// x splitter
// =====================================================================
__global__ void split_x_kernel(const float* __restrict__ X)
{
    int i = blockIdx.x * 256 + threadIdx.x;
    float4 v = ((const float4*)X)[i];
    bf16 h0, l0, h1, l1, h2, l2, h3, l3;
    bsplit(v.x, h0, l0); bsplit(v.y, h1, l1);
    bsplit(v.z, h2, l2); bsplit(v.w, h3, l3);
    bf162 a, b;
    a.x = h0; a.y = h1; b.x = h2; b.y = h3;
    ((bf162*)g_xh)[i * 2] = a; ((bf162*)g_xh)[i * 2 + 1] = b;
    a.x = l0; a.y = l1; b.x = l2; b.y = l3;
    ((bf162*)g_xl)[i * 2] = a; ((bf162*)g_xl)[i * 2 + 1] = b;
}

// =====================================================================
// W_qkv transpose + split: D[c][r] = split(S[r][c]), S=[512][2048].
// =====================================================================
__global__ void transpose_split(const float* __restrict__ S,
                                bf16* __restrict__ Dh, bf16* __restrict__ Dl,
                                int R, int C)
{
    __shared__ float t[32][33];
    int bx = blockIdx.x * 32, by = blockIdx.y * 32;
#pragma unroll
    for (int i = 0; i < 32; i += 8)
        t[threadIdx.y + i][threadIdx.x] =
            S[(size_t)(by + threadIdx.y + i) * C + bx + threadIdx.x];
    __syncthreads();
#pragma unroll
    for (int i = 0; i < 32; i += 8) {
        float v = t[threadIdx.x][threadIdx.y + i];
        bf16 h, l; bsplit(v, h, l);
        size_t o = (size_t)(bx + threadIdx.y + i) * R + by + threadIdx.x;
        Dh[o] = h; Dl[o] = l;
    }
}

// =====================================================================
// W_out transpose with out1/out2 row split remap.
// =====================================================================
__global__ void trans_wout(const float* __restrict__ W)
{
    __shared__ float t[32][33];
    int bx = blockIdx.x * 32, by = blockIdx.y * 32;
#pragma unroll
    for (int i = 0; i < 32; i += 8)
        t[threadIdx.y + i][threadIdx.x] =
            W[(size_t)(by + threadIdx.y + i) * 512 + bx + threadIdx.x];
    __syncthreads();
#pragma unroll
    for (int i = 0; i < 32; i += 8) {
        int c = bx + threadIdx.y + i;
        int r = by + threadIdx.x;
        float v = t[threadIdx.x][threadIdx.y + i];
        int h = r >> 7, cc = r & 127;
        bf16 hh, ll; bsplit(v, hh, ll);
        size_t o = (size_t)c * 512 + h * 64 + (cc & 63);
        if (cc < 64) { g_Wo1th[o] = hh; g_Wo1tl[o] = ll; }
        else         { g_Wo2th[o] = hh; g_Wo2tl[o] = ll; }
    }
}

// =====================================================================
// out2 decay scan.  grid (16 g, 8 chunks), 64 threads.
// =====================================================================
__global__ __launch_bounds__(64) void scan_kernel()
{
    extern __shared__ float sm[];
    float* buf = sm;
    float* sv  = sm + 256 * 64;

    int g = blockIdx.x, chunk = blockIdx.y;
    int b = g >> 3, h = g & 7;
    int c = threadIdx.x;
    const float r = RDEC;
    int i0 = chunk * 256;

    for (int q = (int)threadIdx.x; q < 448; q += 64) {
        int j = i0 - 96 + q;
        if (j >= 0 && j < NN) {
            float s = (1.0f - powf(r, (float)(j + 1)) + r - powf(r, (float)(NN - j)))
                      / (1.0f - r);
            sv[q] = 1.0f / s;
        }
    }
    __syncthreads();

    const float* T = g_t + (size_t)b * 2048 * 512 + h * 64 + c;

    int je = i0 + 255 + 96; if (je > NN - 1) je = NN - 1;
    float gg = 0.f;
    for (int j = je; j >= i0; --j) {
        float u = T[(size_t)j * 512] * sv[j - i0 + 96];
        gg = gg * r + u;
        if (j < i0 + 256) buf[(j - i0) * 64 + c] = gg;
    }

    int js = i0 - 96; if (js < 0) js = 0;
    float f = 0.f;
    for (int j = js; j < i0 + 256; ++j) {
        float u = T[(size_t)j * 512] * sv[j - i0 + 96];
        f = f * r + u;
        if (j >= i0) {
            float v = f + buf[(j - i0) * 64 + c] - u;
            bf16 hh, ll; bsplit(v, hh, ll);
            size_t o = (size_t)(b * 2048 + j) * 512 + h * 64 + c;
            g_o2h[o] = hh; g_o2l[o] = ll;
        }
    }
}

// =====================================================================
#define SM_QKV   (STAGES * 2 * (128 * 64 + 128 * 64))   // 98304
#define SM_O1    (STAGES * 2 * (64 * 64 + 64 * 64))     // 49152
#define SM_OUT   (STAGES * 2 * (128 * 64 + 64 * 64))    // 73728
#define SM_FLASH (32768 + 2 * 32768)                    // 98304
#define SM_SCAN  (256 * 64 * 4 + 448 * 4)               // 67328

extern "C" void kernel_launch(void* const* d_in, const int* in_sizes, int n_in,
                              void* d_out, int out_size)
{
    const float* x     = (const float*)d_in[0];   // [2,2048,512]
    const float* W_qkv = (const float*)d_in[1];   // [512,2048]
    const float* W_out = (const float*)d_in[2];   // [1024,512]
    const float* b_out = (const float*)d_in[3];   // [512]
    float* out = (float*)d_out;                   // [2,2048,512]

    bf16 *p_xh, *p_xl, *p_Wqth, *p_Wqtl;
    bf16 *p_Wo1th, *p_Wo1tl, *p_Wo2th, *p_Wo2tl;
    bf16 *p_o1h, *p_o1l, *p_o2h, *p_o2l;
    float *p_O1;
    cudaGetSymbolAddress((void**)&p_xh,    g_xh);
    cudaGetSymbolAddress((void**)&p_xl,    g_xl);
    cudaGetSymbolAddress((void**)&p_Wqth,  g_Wqth);
    cudaGetSymbolAddress((void**)&p_Wqtl,  g_Wqtl);
    cudaGetSymbolAddress((void**)&p_Wo1th, g_Wo1th);
    cudaGetSymbolAddress((void**)&p_Wo1tl, g_Wo1tl);
    cudaGetSymbolAddress((void**)&p_Wo2th, g_Wo2th);
    cudaGetSymbolAddress((void**)&p_Wo2tl, g_Wo2tl);
    cudaGetSymbolAddress((void**)&p_o1h,   g_o1h);
    cudaGetSymbolAddress((void**)&p_o1l,   g_o1l);
    cudaGetSymbolAddress((void**)&p_o2h,   g_o2h);
    cudaGetSymbolAddress((void**)&p_o2l,   g_o2l);
    cudaGetSymbolAddress((void**)&p_O1,    g_O1);

    static bool attr_done = false;
    if (!attr_done) {
        cudaFuncSetAttribute(bmma_gemm<128, 128, 1>,
                             cudaFuncAttributeMaxDynamicSharedMemorySize, SM_QKV);
        cudaFuncSetAttribute(bmma_gemm<64, 64, 0>,
                             cudaFuncAttributeMaxDynamicSharedMemorySize, SM_O1);
        cudaFuncSetAttribute(bmma_gemm<128, 64, 5>,
                             cudaFuncAttributeMaxDynamicSharedMemorySize, SM_OUT);
        cudaFuncSetAttribute(flash_kernel,
                             cudaFuncAttributeMaxDynamicSharedMemorySize, SM_FLASH);
        cudaFuncSetAttribute(scan_kernel,
                             cudaFuncAttributeMaxDynamicSharedMemorySize, SM_SCAN);
        attr_done = true;
    }

    // 0) input/weight plane production
    split_x_kernel<<<(ROWS * DIMM / 4) / 256, 256>>>(x);
    transpose_split<<<dim3(64, 16), dim3(32, 8)>>>(W_qkv, p_Wqth, p_Wqtl, 512, 2048);
    trans_wout<<<dim3(16, 32), dim3(32, 8)>>>(W_out);

    // 1) qkvt: Q (rows<640/batch) + K/V/t, fused plane epilogues.
    bmma_gemm<128, 128, 1><<<dim3(16, 32, 1), 256, SM_QKV>>>(
        p_xh, p_xl, DIMM, p_Wqth, p_Wqtl, DIMM, nullptr, 0, ROWS, DIMM, nullptr);

    // 2) fused flash (split-j x4) + combine -> o1 planes
    flash_kernel<<<dim3(NSPLIT, 5, G), 256, SM_FLASH>>>();
    combine_kernel<<<(G * NQ * 32 + 255) / 256, 256>>>();

    // 3) out2 decay scan -> o2 planes
    scan_kernel<<<dim3(G, 8), 64, SM_SCAN>>>();

    // 4) O1proj = o1 @ Wo1 : M=1026, N=512, K=512
    bmma_gemm<64, 64, 0><<<dim3(8, 17, 1), 256, SM_O1>>>(
        p_o1h, p_o1l, 512, p_Wo1th, p_Wo1tl, 512, p_O1, 512, 1026, 512, nullptr);

    // 5) out = o2 @ Wo2 + gather(O1proj) + b_out : M=4096, N=512, K=512
    bmma_gemm<128, 64, 5><<<dim3(8, 32, 1), 256, SM_OUT>>>(
        p_o2h, p_o2l, 512, p_Wo2th, p_Wo2tl, 512, out, DIMM, ROWS, 512, b_out);
}

// round 13
// speedup vs baseline: 2.7205x; 1.0360x over previous
#include <cuda_runtime.h>
#include <cuda_bf16.h>
#include <cstdint>
#include <cstddef>

// Problem constants
#define BB    2
#define NN    2048
#define DIMM  512
#define HH    8
#define DHH   64
#define NQ    513          // distinct effective query rows per head (q[i] = q[i % 513])
#define G     16           // B*H
#define ROWS  4096         // B*N
#define FROWS 640          // padded NQ for flash partials (5 * 128)
#define NSPLIT 4           // flash split-j factor

// r = exp(-1/e)
#define RDEC 0.69220062755534637f

typedef __nv_bfloat16  bf16;
typedef __nv_bfloat162 bf162;

// ---------------- scratch (static device arrays; no allocation) ----------------
__device__ __align__(256) float g_t[(size_t)ROWS * 512];          // t quarter fp32
__device__ __align__(256) float g_O1[(size_t)1152 * 512];         // O1proj fp32

__device__ __align__(256) bf16 g_xh[(size_t)ROWS * DIMM];         // x planes
__device__ __align__(256) bf16 g_xl[(size_t)ROWS * DIMM];
__device__ __align__(256) bf16 g_Wqth[(size_t)2048 * DIMM];       // W_qkv^T planes
__device__ __align__(256) bf16 g_Wqtl[(size_t)2048 * DIMM];
__device__ __align__(256) bf16 g_Wo1th[(size_t)512 * 512];        // W_out^T (out1 rows) planes
__device__ __align__(256) bf16 g_Wo1tl[(size_t)512 * 512];
__device__ __align__(256) bf16 g_Wo2th[(size_t)512 * 512];        // W_out^T (out2 rows) planes
__device__ __align__(256) bf16 g_Wo2tl[(size_t)512 * 512];
__device__ __align__(256) bf16 g_qkh[(size_t)ROWS * 1024];        // Q/K planes (cols 0..1023)
__device__ __align__(256) bf16 g_qkl[(size_t)ROWS * 1024];
__device__ __align__(256) bf16 g_vh[(size_t)ROWS * 512];          // V planes [row][h*64+c]
__device__ __align__(256) bf16 g_vl[(size_t)ROWS * 512];
__device__ __align__(256) bf16 g_o1h[(size_t)1152 * 512];         // combine out planes
__device__ __align__(256) bf16 g_o1l[(size_t)1152 * 512];
__device__ __align__(256) bf16 g_o2h[(size_t)ROWS * 512];         // scan out planes
__device__ __align__(256) bf16 g_o2l[(size_t)ROWS * 512];

// flash split-j partials
__device__ __align__(256) float g_pO[(size_t)NSPLIT * G * FROWS * DHH];
__device__ __align__(256) float g_pM[NSPLIT * G * FROWS];
__device__ __align__(256) float g_pL[NSPLIT * G * FROWS];

// ======================= portable PTX helpers =======================
__device__ __forceinline__ uint32_t smem_u32(const void* p) {
    uint32_t a;
    asm("{ .reg .u64 t; cvta.to.shared.u64 t, %1; cvt.u32.u64 %0, t; }" : "=r"(a) : "l"(p));
    return a;
}
__device__ __forceinline__ void ldsm_x4(uint32_t* f, uint32_t addr) {
    asm volatile("ldmatrix.sync.aligned.m8n8.x4.shared.b16 {%0,%1,%2,%3}, [%4];"
                 : "=r"(f[0]), "=r"(f[1]), "=r"(f[2]), "=r"(f[3]) : "r"(addr));
}
__device__ __forceinline__ void ldsm_x4_t(uint32_t* f, uint32_t addr) {
    asm volatile("ldmatrix.sync.aligned.m8n8.x4.trans.shared.b16 {%0,%1,%2,%3}, [%4];"
                 : "=r"(f[0]), "=r"(f[1]), "=r"(f[2]), "=r"(f[3]) : "r"(addr));
}
__device__ __forceinline__ void mma16(float* c, const uint32_t* a, const uint32_t* b) {
    asm volatile("mma.sync.aligned.m16n8k16.row.col.f32.bf16.bf16.f32 "
                 "{%0,%1,%2,%3}, {%4,%5,%6,%7}, {%8,%9}, {%0,%1,%2,%3};"
                 : "+f"(c[0]), "+f"(c[1]), "+f"(c[2]), "+f"(c[3])
                 : "r"(a[0]), "r"(a[1]), "r"(a[2]), "r"(a[3]), "r"(b[0]), "r"(b[1]));
}
#define CP_ASYNC_COMMIT() asm volatile("cp.async.commit_group;")
#define CP_ASYNC_WAIT(n)  asm volatile("cp.async.wait_group %0;" :: "n"(n))
#define CP_ASYNC16(dst, src) \
    asm volatile("cp.async.cg.shared.global [%0], [%1], 16;" :: "r"(dst), "l"(src))
#define CP_ASYNC16Z(dst, src, gz) \
    asm volatile("cp.async.cg.shared.global [%0], [%1], 16, %2;" :: "r"(dst), "l"(src), "r"(gz))

__device__ __forceinline__ void bsplit(float v, bf16& h, bf16& l) {
    h = __float2bfloat16(v);
    l = __float2bfloat16(v - __bfloat162float(h));
}
__device__ __forceinline__ uint32_t pack_bf(float lo, float hi) {
    bf162 t; t.x = __float2bfloat16(lo); t.y = __float2bfloat16(hi);
    return *(uint32_t*)&t;
}

// interleaved-line SMEM layout for BK=32 (64B rows): 2 rows per 128B line
__device__ __forceinline__ uint32_t tpos(int r, int ch) {
    return ((uint32_t)(r >> 1) << 7) |
           ((uint32_t)((((r & 1) << 2) | ch) ^ ((r >> 1) & 7)) << 4);
}
// full-line layout for 128B rows (64 bf16): chunk ch in 0..7
__device__ __forceinline__ uint32_t fpos(int r, int ch) {
    return ((uint32_t)r << 7) | ((uint32_t)(ch ^ (r & 7)) << 4);
}

#define STAGES 3

// =====================================================================
// bf16x3 mma.sync GEMM: C[M,N] = A[M,K] @ B[N,K]^T (+extras)
// A/B as (hi, lo) bf16 planes, K-major.  CTA BM x BN, 8 warps (4m x 2n).
// __launch_bounds__(256, 2): cap 128 regs -> 2 CTAs/SM.
// MODE 0: plain fp32 C (+bias if given).
// MODE 1: qkvt producer (Q region only rows%2048<640; fused plane epilogues).
// MODE 5: final out.  C = acc + bias[cg] + O1proj[b*513 + i%513][cg].
// =====================================================================
template<int BM, int BN, int MODE>
__global__ __launch_bounds__(256, 2) void bmma_gemm(
    const bf16* __restrict__ Ah, const bf16* __restrict__ Al, int lda,
    const bf16* __restrict__ Bh, const bf16* __restrict__ Bl, int ldb,
    float* __restrict__ C, int ldc,
    int M, int K, const float* __restrict__ bias)
{
    constexpr int MT     = BM / 64;
    constexpr int NTILES = BN / 16;
    constexpr int APL = BM * 64;
    constexpr int BPL = BN * 64;
    constexpr int STAGE = 2 * (APL + BPL);

    int row0 = blockIdx.y * BM;
    int col0 = blockIdx.x * BN;
    if (MODE == 1) {
        if (col0 < 512 && (row0 & 2047) >= FROWS) return;   // Q region: 640 rows/batch
    }

    extern __shared__ __align__(1024) char smem[];
    uint32_t sbase = smem_u32(smem);
    int tid = threadIdx.x, wid = tid >> 5, lane = tid & 31;

    auto load_stage = [&](int stage, int k0) {
        uint32_t sb = sbase + stage * STAGE;
#pragma unroll
        for (int i = 0; i < BM * 4 / 256; ++i) {
            int id = tid + i * 256;
            int r = id >> 2, ch = id & 3;
            uint32_t pos = tpos(r, ch);
            const bf16* sh = Ah + (size_t)(row0 + r) * lda + k0 + ch * 8;
            const bf16* sl = Al + (size_t)(row0 + r) * lda + k0 + ch * 8;
            uint32_t gz = (row0 + r < M) ? 16u : 0u;
            CP_ASYNC16Z(sb + pos, sh, gz);
            CP_ASYNC16Z(sb + APL + pos, sl, gz);
        }
#pragma unroll
        for (int i = 0; i < BN * 4 / 256; ++i) {
            int id = tid + i * 256;
            int r = id >> 2, ch = id & 3;
            uint32_t pos = tpos(r, ch);
            const bf16* sh = Bh + (size_t)(col0 + r) * ldb + k0 + ch * 8;
            const bf16* sl = Bl + (size_t)(col0 + r) * ldb + k0 + ch * 8;
            CP_ASYNC16(sb + 2 * APL + pos, sh);
            CP_ASYNC16(sb + 2 * APL + BPL + pos, sl);
        }
    };

    int NT = K >> 5;
#pragma unroll
    for (int s = 0; s < STAGES - 1; ++s) {
        if (s < NT) load_stage(s, s * 32);
        CP_ASYNC_COMMIT();
    }

    int wm = wid & 3, wn = wid >> 2;
    int mbase = wm * (BM / 4);
    int nbase = wn * (BN / 2);

    float acc[MT][NTILES][4];
#pragma unroll
    for (int mt = 0; mt < MT; ++mt)
#pragma unroll
        for (int nt = 0; nt < NTILES; ++nt)
#pragma unroll
            for (int j = 0; j < 4; ++j) acc[mt][nt][j] = 0.f;

    for (int t = 0; t < NT; ++t) {
        CP_ASYNC_WAIT(STAGES - 2);
        __syncthreads();
        if (t + STAGES - 1 < NT)
            load_stage((t + STAGES - 1) % STAGES, (t + STAGES - 1) * 32);
        CP_ASYNC_COMMIT();

        uint32_t sb = sbase + (t % STAGES) * STAGE;
#pragma unroll
        for (int kk = 0; kk < 2; ++kk) {
            uint32_t ah[MT][4], al[MT][4];
#pragma unroll
            for (int mt = 0; mt < MT; ++mt) {
                int r = mbase + mt * 16 + (lane & 15);
                int ch = kk * 2 + (lane >> 4);
                uint32_t pos = tpos(r, ch);
                ldsm_x4(ah[mt], sb + pos);
                ldsm_x4(al[mt], sb + APL + pos);
            }
            uint32_t bh[NTILES][2], bl[NTILES][2];
#pragma unroll
            for (int p = 0; p < NTILES / 2; ++p) {
                int r = nbase + p * 16 + ((lane >> 4) << 3) + (lane & 7);
                int ch = kk * 2 + ((lane >> 3) & 1);
                uint32_t pos = tpos(r, ch);
                uint32_t f[4];
                ldsm_x4(f, sb + 2 * APL + pos);
                bh[2 * p][0] = f[0]; bh[2 * p][1] = f[1];
                bh[2 * p + 1][0] = f[2]; bh[2 * p + 1][1] = f[3];
                ldsm_x4(f, sb + 2 * APL + BPL + pos);
                bl[2 * p][0] = f[0]; bl[2 * p][1] = f[1];
                bl[2 * p + 1][0] = f[2]; bl[2 * p + 1][1] = f[3];
            }
#pragma unroll
            for (int mt = 0; mt < MT; ++mt)
#pragma unroll
                for (int nt = 0; nt < NTILES; ++nt) {
                    mma16(acc[mt][nt], ah[mt], bh[nt]);
                    mma16(acc[mt][nt], ah[mt], bl[nt]);
                    mma16(acc[mt][nt], al[mt], bh[nt]);
                }
        }
    }
    CP_ASYNC_WAIT(0);

    int cr = lane >> 2, cc = (lane & 3) * 2;
#pragma unroll
    for (int mt = 0; mt < MT; ++mt) {
        int rgb = row0 + mbase + mt * 16 + cr;
#pragma unroll
        for (int nt = 0; nt < NTILES; ++nt) {
            int cg = col0 + nbase + nt * 8 + cc;
#pragma unroll
            for (int half = 0; half < 2; ++half) {
                int rg = rgb + half * 8;
                if (rg >= M) continue;
                float vx = acc[mt][nt][half * 2];
                float vy = acc[mt][nt][half * 2 + 1];
                if (MODE == 0) {
                    if (bias) {
                        float2 b2 = *(const float2*)(bias + cg);
                        vx += b2.x; vy += b2.y;
                    }
                    *(float2*)(C + (size_t)rg * ldc + cg) = make_float2(vx, vy);
                } else if (MODE == 5) {
                    float2 b2 = *(const float2*)(bias + cg);
                    int b = rg >> 11, i = rg & 2047;
                    int i513 = i % 513;
                    float2 o1 = *(const float2*)&g_O1[(size_t)(b * 513 + i513) * 512 + cg];
                    *(float2*)(C + (size_t)rg * ldc + cg) =
                        make_float2(vx + b2.x + o1.x, vy + b2.y + o1.y);
                } else { // MODE 1
                    if (cg < 1024) {
                        bf16 hx, lx, hy, ly;
                        bsplit(vx, hx, lx); bsplit(vy, hy, ly);
                        bf162 hh; hh.x = hx; hh.y = hy;
                        bf162 ll; ll.x = lx; ll.y = ly;
                        *(bf162*)&g_qkh[(size_t)rg * 1024 + cg] = hh;
                        *(bf162*)&g_qkl[(size_t)rg * 1024 + cg] = ll;
                    } else if (cg < 1536) {
                        bf16 hx, lx, hy, ly;
                        bsplit(vx, hx, lx); bsplit(vy, hy, ly);
                        bf162 hh; hh.x = hx; hh.y = hy;
                        bf162 ll; ll.x = lx; ll.y = ly;
                        *(bf162*)&g_vh[(size_t)rg * 512 + cg - 1024] = hh;
                        *(bf162*)&g_vl[(size_t)rg * 512 + cg - 1024] = ll;
                    } else {
                        *(float2*)&g_t[(size_t)rg * 512 + cg - 1536] = make_float2(vx, vy);
                    }
                }
            }
        }
    }
}

// =====================================================================
// Fused flash attention: S = 0.125 * Q K^T, online softmax, O = P V.
// grid (NSPLIT, 5, 16), 8 warps.  Q smem region reused by KV stages
// (64 KB total) + reg cap -> 2 CTAs/SM.  Fragments loaded per tile-pair
// to keep register pressure under the 128-reg cap.
// =====================================================================
__global__ __launch_bounds__(256, 2) void flash_kernel()
{
    constexpr int JT = 2048 / (NSPLIT * 64);     // j-tiles per split
    extern __shared__ __align__(1024) char smem[];
    uint32_t sb = smem_u32(smem);

    int split = blockIdx.x, mtile = blockIdx.y, g = blockIdx.z;
    int b = g >> 3, h = g & 7;
    int row0 = mtile * 128;
    int tid = threadIdx.x, wid = tid >> 5, lane = tid & 31;

    const bf16* Qh = g_qkh + (size_t)b * 2048 * 1024 + h * 64;
    const bf16* Ql = g_qkl + (size_t)b * 2048 * 1024 + h * 64;
    const bf16* Kh = Qh + 512;
    const bf16* Kl = Ql + 512;
    const bf16* Vh = g_vh + (size_t)b * 2048 * 512 + h * 64;
    const bf16* Vl = g_vl + (size_t)b * 2048 * 512 + h * 64;

    // ---- Q tile load into stage-0 region (reused by KV afterwards) ----
    const uint32_t sQh = sb, sQl = sb + 16384;
#pragma unroll
    for (int i = 0; i < 4; ++i) {
        int id = tid + i * 256;
        int r = id >> 3, ch = id & 7;
        uint32_t pos = fpos(r, ch);
        uint32_t gz = (row0 + r < NQ) ? 16u : 0u;
        CP_ASYNC16Z(sQh + pos, Qh + (size_t)(row0 + r) * 1024 + ch * 8, gz);
        CP_ASYNC16Z(sQl + pos, Ql + (size_t)(row0 + r) * 1024 + ch * 8, gz);
    }
    CP_ASYNC_COMMIT();
    CP_ASYNC_WAIT(0);
    __syncthreads();

    // ---- Q fragments (held for whole loop) ----
    uint32_t qh[4][4], ql[4][4];
#pragma unroll
    for (int kk = 0; kk < 4; ++kk) {
        int r = wid * 16 + (lane & 15);
        uint32_t pos = fpos(r, 2 * kk + (lane >> 4));
        ldsm_x4(qh[kk], sQh + pos);
        ldsm_x4(ql[kk], sQl + pos);
    }
    __syncthreads();   // all warps done reading Q before KV overwrites

    int j0 = split * (2048 / NSPLIT);
    auto load_kv = [&](int stage, int jt) {
        uint32_t kb = sb + stage * 32768;
        int jb = j0 + jt * 64;
#pragma unroll
        for (int i = 0; i < 2; ++i) {
            int id = tid + i * 256;
            int r = id >> 3, ch = id & 7;
            uint32_t pos = fpos(r, ch);
            CP_ASYNC16(kb + pos,         Kh + (size_t)(jb + r) * 1024 + ch * 8);
            CP_ASYNC16(kb + 8192 + pos,  Kl + (size_t)(jb + r) * 1024 + ch * 8);
            CP_ASYNC16(kb + 16384 + pos, Vh + (size_t)(jb + r) * 512 + ch * 8);
            CP_ASYNC16(kb + 24576 + pos, Vl + (size_t)(jb + r) * 512 + ch * 8);
        }
    };
    load_kv(0, 0);
    CP_ASYNC_COMMIT();
    CP_ASYNC_WAIT(0);
    __syncthreads();

    float mr[2] = {-1e30f, -1e30f};
    float lr[2] = {0.f, 0.f};
    float oacc[8][4];
#pragma unroll
    for (int nt = 0; nt < 8; ++nt)
#pragma unroll
        for (int j = 0; j < 4; ++j) oacc[nt][j] = 0.f;

    for (int t = 0; t < JT; ++t) {
        if (t + 1 < JT) load_kv((t + 1) & 1, t + 1);
        CP_ASYNC_COMMIT();

        uint32_t kb = sb + (t & 1) * 32768;

        // ---- S = Q K^T (bf16x3), fragments per tile-pair ----
        float sacc[8][4];
#pragma unroll
        for (int nt = 0; nt < 8; ++nt)
#pragma unroll
            for (int j = 0; j < 4; ++j) sacc[nt][j] = 0.f;
#pragma unroll
        for (int kk = 0; kk < 4; ++kk) {
#pragma unroll
            for (int p = 0; p < 4; ++p) {
                int r = p * 16 + ((lane >> 4) << 3) + (lane & 7);
                uint32_t pos = fpos(r, 2 * kk + ((lane >> 3) & 1));
                uint32_t fh[4], fl[4];
                ldsm_x4(fh, kb + pos);
                ldsm_x4(fl, kb + 8192 + pos);
                uint32_t b0h[2] = {fh[0], fh[1]}, b1h[2] = {fh[2], fh[3]};
                uint32_t b0l[2] = {fl[0], fl[1]}, b1l[2] = {fl[2], fl[3]};
                mma16(sacc[2 * p],     qh[kk], b0h);
                mma16(sacc[2 * p],     qh[kk], b0l);
                mma16(sacc[2 * p],     ql[kk], b0h);
                mma16(sacc[2 * p + 1], qh[kk], b1h);
                mma16(sacc[2 * p + 1], qh[kk], b1l);
                mma16(sacc[2 * p + 1], ql[kk], b1h);
            }
        }

        // ---- scale + online softmax ----
#pragma unroll
        for (int nt = 0; nt < 8; ++nt)
#pragma unroll
            for (int j = 0; j < 4; ++j) sacc[nt][j] *= 0.125f;

#pragma unroll
        for (int hr = 0; hr < 2; ++hr) {
            float mx = -1e30f;
#pragma unroll
            for (int nt = 0; nt < 8; ++nt)
                mx = fmaxf(mx, fmaxf(sacc[nt][hr * 2], sacc[nt][hr * 2 + 1]));
            mx = fmaxf(mx, __shfl_xor_sync(0xffffffffu, mx, 1));
            mx = fmaxf(mx, __shfl_xor_sync(0xffffffffu, mx, 2));
            float mnew = fmaxf(mr[hr], mx);
            float alpha = __expf(mr[hr] - mnew);
            mr[hr] = mnew;
            float rs = 0.f;
#pragma unroll
            for (int nt = 0; nt < 8; ++nt) {
                float p0 = __expf(sacc[nt][hr * 2] - mnew);
                float p1 = __expf(sacc[nt][hr * 2 + 1] - mnew);
                sacc[nt][hr * 2] = p0; sacc[nt][hr * 2 + 1] = p1;
                rs += p0 + p1;
            }
            rs += __shfl_xor_sync(0xffffffffu, rs, 1);
            rs += __shfl_xor_sync(0xffffffffu, rs, 2);
            lr[hr] = lr[hr] * alpha + rs;
#pragma unroll
            for (int nt = 0; nt < 8; ++nt) {
                oacc[nt][hr * 2]     *= alpha;
                oacc[nt][hr * 2 + 1] *= alpha;
            }
        }

        // ---- O += P V (bf16x3; V frags per tile-pair via trans-ldmatrix) ----
#pragma unroll
        for (int kk = 0; kk < 4; ++kk) {
            uint32_t pa_h[4], pa_l[4];
            {
                float x0 = sacc[2 * kk][0],     x1 = sacc[2 * kk][1];
                float x2 = sacc[2 * kk][2],     x3 = sacc[2 * kk][3];
                float y0 = sacc[2 * kk + 1][0], y1 = sacc[2 * kk + 1][1];
                float y2 = sacc[2 * kk + 1][2], y3 = sacc[2 * kk + 1][3];
                pa_h[0] = pack_bf(x0, x1);
                pa_h[1] = pack_bf(x2, x3);
                pa_h[2] = pack_bf(y0, y1);
                pa_h[3] = pack_bf(y2, y3);
                bf162* ph = (bf162*)pa_h;
                pa_l[0] = pack_bf(x0 - __bfloat162float(ph[0].x), x1 - __bfloat162float(ph[0].y));
                pa_l[1] = pack_bf(x2 - __bfloat162float(ph[1].x), x3 - __bfloat162float(ph[1].y));
                pa_l[2] = pack_bf(y0 - __bfloat162float(ph[2].x), y1 - __bfloat162float(ph[2].y));
                pa_l[3] = pack_bf(y2 - __bfloat162float(ph[3].x), y3 - __bfloat162float(ph[3].y));
            }
#pragma unroll
            for (int p = 0; p < 4; ++p) {
                int jl = kk * 16 + ((lane >> 3) & 1) * 8 + (lane & 7);
                int ch = p * 2 + (lane >> 4);
                uint32_t pos = fpos(jl, ch);
                uint32_t fh[4], fl[4];
                ldsm_x4_t(fh, kb + 16384 + pos);
                ldsm_x4_t(fl, kb + 24576 + pos);
                uint32_t v0h[2] = {fh[0], fh[1]}, v1h[2] = {fh[2], fh[3]};
                uint32_t v0l[2] = {fl[0], fl[1]}, v1l[2] = {fl[2], fl[3]};
                mma16(oacc[2 * p],     pa_h, v0h);
                mma16(oacc[2 * p],     pa_h, v0l);
                mma16(oacc[2 * p],     pa_l, v0h);
                mma16(oacc[2 * p + 1], pa_h, v1h);
                mma16(oacc[2 * p + 1], pa_h, v1l);
                mma16(oacc[2 * p + 1], pa_l, v1h);
            }
        }

        CP_ASYNC_WAIT(0);
        __syncthreads();
    }

    int cr = lane >> 2, cc = (lane & 3) * 2;
#pragma unroll
    for (int hr = 0; hr < 2; ++hr) {
        int row = row0 + wid * 16 + cr + hr * 8;
        size_t base = (((size_t)split * G + g) * FROWS + row) * DHH;
#pragma unroll
        for (int nt = 0; nt < 8; ++nt) {
            *(float2*)&g_pO[base + nt * 8 + cc] =
                make_float2(oacc[nt][hr * 2], oacc[nt][hr * 2 + 1]);
        }
        if ((lane & 3) == 0) {
            size_t mi = ((size_t)split * G + g) * FROWS + row;
            g_pM[mi] = mr[hr];
            g_pL[mi] = lr[hr];
        }
    }
}

// =====================================================================
// Combine split-j partials -> o1 planes [b*513+row][h*64+c].
// =====================================================================
__global__ void combine_kernel()
{
    int idx = blockIdx.x * 256 + threadIdx.x;
    if (idx >= G * NQ * 32) return;
    int c = (idx & 31) * 2;
    int rem = idx >> 5;
    int row = rem % NQ, g = rem / NQ;
    int b = g >> 3, h = g & 7;

    float m[NSPLIT], l[NSPLIT];
    float M = -1e30f;
#pragma unroll
    for (int s = 0; s < NSPLIT; ++s) {
        size_t mi = ((size_t)s * G + g) * FROWS + row;
        m[s] = g_pM[mi]; l[s] = g_pL[mi];
        M = fmaxf(M, m[s]);
    }
    float den = 0.f;
    float w[NSPLIT];
#pragma unroll
    for (int s = 0; s < NSPLIT; ++s) {
        w[s] = __expf(m[s] - M);
        den += w[s] * l[s];
    }
    float inv = 1.f / den;
    float vx = 0.f, vy = 0.f;
#pragma unroll
    for (int s = 0; s < NSPLIT; ++s) {
        size_t mi = ((size_t)s * G + g) * FROWS + row;
        float2 o = *(const float2*)&g_pO[mi * DHH + c];
        vx += w[s] * o.x; vy += w[s] * o.y;
    }
    vx *= inv; vy *= inv;

    bf16 hx, lx, hy, ly;
    bsplit(vx, hx, lx); bsplit(vy, hy, ly);
    bf162 hh; hh.x = hx; hh.y = hy;
    bf162 ll; ll.x = lx; ll.y = ly;
    size_t o = (size_t)(b * 513 + row) * 512 + h * 64 + c;
    *(bf162*)&g_o1h[o] = hh;
    *(bf162*)&g_o1l[o] = ll;
}

// =====================================================================
// x splitter
// =====================================================================
__global__ void split_x_kernel(const float* __restrict__ X)
{
    int i = blockIdx.x * 256 + threadIdx.x;
    float4 v = ((const float4*)X)[i];
    bf16 h0, l0, h1, l1, h2, l2, h3, l3;
    bsplit(v.x, h0, l0); bsplit(v.y, h1, l1);
    bsplit(v.z, h2, l2); bsplit(v.w, h3, l3);
    bf162 a, b;
    a.x = h0; a.y = h1; b.x = h2; b.y = h3;
    ((bf162*)g_xh)[i * 2] = a; ((bf162*)g_xh)[i * 2 + 1] = b;
    a.x = l0; a.y = l1; b.x = l2; b.y = l3;
    ((bf162*)g_xl)[i * 2] = a; ((bf162*)g_xl)[i * 2 + 1] = b;
}

// =====================================================================
// W_qkv transpose + split: D[c][r] = split(S[r][c]), S=[512][2048].
// =====================================================================
__global__ void transpose_split(const float* __restrict__ S,
                                bf16* __restrict__ Dh, bf16* __restrict__ Dl,
                                int R, int C)
{
    __shared__ float t[32][33];
    int bx = blockIdx.x * 32, by = blockIdx.y * 32;
#pragma unroll
    for (int i = 0; i < 32; i += 8)
        t[threadIdx.y + i][threadIdx.x] =
            S[(size_t)(by + threadIdx.y + i) * C + bx + threadIdx.x];
    __syncthreads();
#pragma unroll
    for (int i = 0; i < 32; i += 8) {
        float v = t[threadIdx.x][threadIdx.y + i];
        bf16 h, l; bsplit(v, h, l);
        size_t o = (size_t)(bx + threadIdx.y + i) * R + by + threadIdx.x;
        Dh[o] = h; Dl[o] = l;
    }
}

// =====================================================================
// W_out transpose with out1/out2 row split remap.
// =====================================================================
__global__ void trans_wout(const float* __restrict__ W)
{
    __shared__ float t[32][33];
    int bx = blockIdx.x * 32, by = blockIdx.y * 32;
#pragma unroll
    for (int i = 0; i < 32; i += 8)
        t[threadIdx.y + i][threadIdx.x] =
            W[(size_t)(by + threadIdx.y + i) * 512 + bx + threadIdx.x];
    __syncthreads();
#pragma unroll
    for (int i = 0; i < 32; i += 8) {
        int c = bx + threadIdx.y + i;
        int r = by + threadIdx.x;
        float v = t[threadIdx.x][threadIdx.y + i];
        int h = r >> 7, cc = r & 127;
        bf16 hh, ll; bsplit(v, hh, ll);
        size_t o = (size_t)c * 512 + h * 64 + (cc & 63);
        if (cc < 64) { g_Wo1th[o] = hh; g_Wo1tl[o] = ll; }
        else         { g_Wo2th[o] = hh; g_Wo2tl[o] = ll; }
    }
}

// =====================================================================
// out2 decay scan.  grid (16 g, 8 chunks), 64 threads.
// =====================================================================
__global__ __launch_bounds__(64) void scan_kernel()
{
    extern __shared__ float sm[];
    float* buf = sm;
    float* sv  = sm + 256 * 64;

    int g = blockIdx.x, chunk = blockIdx.y;
    int b = g >> 3, h = g & 7;
    int c = threadIdx.x;
    const float r = RDEC;
    int i0 = chunk * 256;

    for (int q = (int)threadIdx.x; q < 448; q += 64) {
        int j = i0 - 96 + q;
        if (j >= 0 && j < NN) {
            float s = (1.0f - powf(r, (float)(j + 1)) + r - powf(r, (float)(NN - j)))
                      / (1.0f - r);
            sv[q] = 1.0f / s;
        }
    }
    __syncthreads();

    const float* T = g_t + (size_t)b * 2048 * 512 + h * 64 + c;

    int je = i0 + 255 + 96; if (je > NN - 1) je = NN - 1;
    float gg = 0.f;
    for (int j = je; j >= i0; --j) {
        float u = T[(size_t)j * 512] * sv[j - i0 + 96];
        gg = gg * r + u;
        if (j < i0 + 256) buf[(j - i0) * 64 + c] = gg;
    }

    int js = i0 - 96; if (js < 0) js = 0;
    float f = 0.f;
    for (int j = js; j < i0 + 256; ++j) {
        float u = T[(size_t)j * 512] * sv[j - i0 + 96];
        f = f * r + u;
        if (j >= i0) {
            float v = f + buf[(j - i0) * 64 + c] - u;
            bf16 hh, ll; bsplit(v, hh, ll);
            size_t o = (size_t)(b * 2048 + j) * 512 + h * 64 + c;
            g_o2h[o] = hh; g_o2l[o] = ll;
        }
    }
}

// =====================================================================
#define SM_QKV   (STAGES * 2 * (128 * 64 + 128 * 64))   // 98304
#define SM_O1    (STAGES * 2 * (64 * 64 + 64 * 64))     // 49152
#define SM_OUT   (STAGES * 2 * (128 * 64 + 64 * 64))    // 73728
#define SM_FLASH (2 * 32768)                            // 65536 (Q reuses stage 0)
#define SM_SCAN  (256 * 64 * 4 + 448 * 4)               // 67328

extern "C" void kernel_launch(void* const* d_in, const int* in_sizes, int n_in,
                              void* d_out, int out_size)
{
    const float* x     = (const float*)d_in[0];   // [2,2048,512]
    const float* W_qkv = (const float*)d_in[1];   // [512,2048]
    const float* W_out = (const float*)d_in[2];   // [1024,512]
    const float* b_out = (const float*)d_in[3];   // [512]
    float* out = (float*)d_out;                   // [2,2048,512]

    bf16 *p_xh, *p_xl, *p_Wqth, *p_Wqtl;
    bf16 *p_Wo1th, *p_Wo1tl, *p_Wo2th, *p_Wo2tl;
    bf16 *p_o1h, *p_o1l, *p_o2h, *p_o2l;
    float *p_O1;
    cudaGetSymbolAddress((void**)&p_xh,    g_xh);
    cudaGetSymbolAddress((void**)&p_xl,    g_xl);
    cudaGetSymbolAddress((void**)&p_Wqth,  g_Wqth);
    cudaGetSymbolAddress((void**)&p_Wqtl,  g_Wqtl);
    cudaGetSymbolAddress((void**)&p_Wo1th, g_Wo1th);
    cudaGetSymbolAddress((void**)&p_Wo1tl, g_Wo1tl);
    cudaGetSymbolAddress((void**)&p_Wo2th, g_Wo2th);
    cudaGetSymbolAddress((void**)&p_Wo2tl, g_Wo2tl);
    cudaGetSymbolAddress((void**)&p_o1h,   g_o1h);
    cudaGetSymbolAddress((void**)&p_o1l,   g_o1l);
    cudaGetSymbolAddress((void**)&p_o2h,   g_o2h);
    cudaGetSymbolAddress((void**)&p_o2l,   g_o2l);
    cudaGetSymbolAddress((void**)&p_O1,    g_O1);

    static bool attr_done = false;
    if (!attr_done) {
        cudaFuncSetAttribute(bmma_gemm<128, 128, 1>,
                             cudaFuncAttributeMaxDynamicSharedMemorySize, SM_QKV);
        cudaFuncSetAttribute(bmma_gemm<64, 64, 0>,
                             cudaFuncAttributeMaxDynamicSharedMemorySize, SM_O1);
        cudaFuncSetAttribute(bmma_gemm<128, 64, 5>,
                             cudaFuncAttributeMaxDynamicSharedMemorySize, SM_OUT);
        cudaFuncSetAttribute(flash_kernel,
                             cudaFuncAttributeMaxDynamicSharedMemorySize, SM_FLASH);
        cudaFuncSetAttribute(scan_kernel,
                             cudaFuncAttributeMaxDynamicSharedMemorySize, SM_SCAN);
        attr_done = true;
    }

    // 0) input/weight plane production
    split_x_kernel<<<(ROWS * DIMM / 4) / 256, 256>>>(x);
    transpose_split<<<dim3(64, 16), dim3(32, 8)>>>(W_qkv, p_Wqth, p_Wqtl, 512, 2048);
    trans_wout<<<dim3(16, 32), dim3(32, 8)>>>(W_out);

    // 1) qkvt: Q (rows<640/batch) + K/V/t, fused plane epilogues.
    bmma_gemm<128, 128, 1><<<dim3(16, 32, 1), 256, SM_QKV>>>(
        p_xh, p_xl, DIMM, p_Wqth, p_Wqtl, DIMM, nullptr, 0, ROWS, DIMM, nullptr);

    // 2) fused flash (split-j x4, 2 CTA/SM) + combine -> o1 planes
    flash_kernel<<<dim3(NSPLIT, 5, G), 256, SM_FLASH>>>();
    combine_kernel<<<(G * NQ * 32 + 255) / 256, 256>>>();

    // 3) out2 decay scan -> o2 planes
    scan_kernel<<<dim3(G, 8), 64, SM_SCAN>>>();

    // 4) O1proj = o1 @ Wo1 : M=1026, N=512, K=512
    bmma_gemm<64, 64, 0><<<dim3(8, 17, 1), 256, SM_O1>>>(
        p_o1h, p_o1l, 512, p_Wo1th, p_Wo1tl, 512, p_O1, 512, 1026, 512, nullptr);

    // 5) out = o2 @ Wo2 + gather(O1proj) + b_out : M=4096, N=512, K=512
    bmma_gemm<128, 64, 5><<<dim3(8, 32, 1), 256, SM_OUT>>>(
        p_o2h, p_o2l, 512, p_Wo2th, p_Wo2tl, 512, out, DIMM, ROWS, 512, b_out);
}